// round 4
// baseline (speedup 1.0000x reference)
#include <cuda_runtime.h>
#include <math.h>

#define QLEN 900
#define DM   256
#define NH   8
#define HD   32
#define NPTS 4
#define FFD  1024

// ---------------- scratch (__device__ globals; allocation-free) ----------------
__device__ float g_qkv[5529600];      // [B*Q, 768]
__device__ float g_scores[51840000];  // [B*H, 900, 900]
__device__ float g_attn[1843200];     // [B*Q, 256] self-attn output
__device__ float g_t1[1843200];       // after norm1
__device__ float g_val[20480000];     // [B*HW, 256] projected memory
__device__ float g_dsm[1843200];      // deform-attn sampled output
__device__ float g_proj[1843200];     // generic GEMM output pre-LN
__device__ float g_t2[1843200];       // after norm2
__device__ float g_ffn[7372800];      // [B*Q, 1024]

// ---------------------------------------------------------------------------
// Generic SGEMM: C[M,N] = act(A[M,K] @ W[N,K]^T + bias[N])
// 128x128 tile, BK=8, 256 threads, 8x8 micro-tile in split 2x(4x4) layout.
// ---------------------------------------------------------------------------
__global__ __launch_bounds__(256) void sgemm_nt(
    const float* __restrict__ A, const float* __restrict__ W,
    const float* __restrict__ bias, float* __restrict__ C,
    int M, int N, int K, int relu)
{
    __shared__ float As[8][128];
    __shared__ float Bs[8][128];
    const int tid = threadIdx.x;
    const int tx = tid & 15;     // col group
    const int ty = tid >> 4;     // row group
    const int row0 = blockIdx.y * 128;
    const int col0 = blockIdx.x * 128;

    const int lr = tid >> 1;           // 0..127
    const int lc = (tid & 1) << 2;     // 0 or 4

    float acc[8][8];
#pragma unroll
    for (int i = 0; i < 8; i++)
#pragma unroll
        for (int j = 0; j < 8; j++) acc[i][j] = 0.f;

    for (int k0 = 0; k0 < K; k0 += 8) {
        float4 av = make_float4(0.f, 0.f, 0.f, 0.f);
        float4 bv = make_float4(0.f, 0.f, 0.f, 0.f);
        if (row0 + lr < M)
            av = *(const float4*)(A + (size_t)(row0 + lr) * K + k0 + lc);
        if (col0 + lr < N)
            bv = *(const float4*)(W + (size_t)(col0 + lr) * K + k0 + lc);
        As[lc + 0][lr] = av.x; As[lc + 1][lr] = av.y;
        As[lc + 2][lr] = av.z; As[lc + 3][lr] = av.w;
        Bs[lc + 0][lr] = bv.x; Bs[lc + 1][lr] = bv.y;
        Bs[lc + 2][lr] = bv.z; Bs[lc + 3][lr] = bv.w;
        __syncthreads();
#pragma unroll
        for (int kk = 0; kk < 8; kk++) {
            float4 a0 = *(const float4*)&As[kk][ty * 4];
            float4 a1 = *(const float4*)&As[kk][64 + ty * 4];
            float4 b0 = *(const float4*)&Bs[kk][tx * 4];
            float4 b1 = *(const float4*)&Bs[kk][64 + tx * 4];
            float ar[8] = {a0.x, a0.y, a0.z, a0.w, a1.x, a1.y, a1.z, a1.w};
            float br[8] = {b0.x, b0.y, b0.z, b0.w, b1.x, b1.y, b1.z, b1.w};
#pragma unroll
            for (int i = 0; i < 8; i++)
#pragma unroll
                for (int j = 0; j < 8; j++)
                    acc[i][j] += ar[i] * br[j];
        }
        __syncthreads();
    }

#pragma unroll
    for (int i = 0; i < 8; i++) {
        int row = row0 + ((i < 4) ? (ty * 4 + i) : (64 + ty * 4 + i - 4));
        if (row >= M) continue;
#pragma unroll
        for (int jb = 0; jb < 2; jb++) {
            int colb = col0 + jb * 64 + tx * 4;
            float v[4];
#pragma unroll
            for (int j = 0; j < 4; j++) {
                v[j] = acc[i][jb * 4 + j];
                int col = colb + j;
                if (col < N) v[j] += bias[col];
                if (relu) v[j] = fmaxf(v[j], 0.f);
            }
            if (colb + 3 < N) {
                *(float4*)(C + (size_t)row * N + colb) =
                    make_float4(v[0], v[1], v[2], v[3]);
            } else {
#pragma unroll
                for (int j = 0; j < 4; j++)
                    if (colb + j < N) C[(size_t)row * N + colb + j] = v[j];
            }
        }
    }
}

// ---------------------------------------------------------------------------
// Self-attention scores: S[bh][m][n] = scale * dot(Qh[m], Kh[n]), K=32.
// grid (15, 15, B*H), 64x64 tile, 4x4 micro-tile.
// ---------------------------------------------------------------------------
__global__ __launch_bounds__(256) void attn_scores(
    const float* __restrict__ qkv, float* __restrict__ S)
{
    const int bh = blockIdx.z;
    const int b = bh >> 3, h = bh & 7;
    const int m0 = blockIdx.y * 64, n0 = blockIdx.x * 64;
    __shared__ float Qs[32][64];
    __shared__ float Ks[32][64];
    const int tid = threadIdx.x;

    {
        int r = tid >> 2;            // 0..63
        int c = (tid & 3) * 8;       // 0,8,16,24
        const float* qbase = qkv + (size_t)b * QLEN * 768 + h * 32;
        float4 v0 = make_float4(0.f,0.f,0.f,0.f), v1 = v0, w0 = v0, w1 = v0;
        if (m0 + r < QLEN) {
            const float* p = qbase + (size_t)(m0 + r) * 768 + c;
            v0 = *(const float4*)p; v1 = *(const float4*)(p + 4);
        }
        if (n0 + r < QLEN) {
            const float* p = qbase + 256 + (size_t)(n0 + r) * 768 + c;
            w0 = *(const float4*)p; w1 = *(const float4*)(p + 4);
        }
        Qs[c+0][r]=v0.x; Qs[c+1][r]=v0.y; Qs[c+2][r]=v0.z; Qs[c+3][r]=v0.w;
        Qs[c+4][r]=v1.x; Qs[c+5][r]=v1.y; Qs[c+6][r]=v1.z; Qs[c+7][r]=v1.w;
        Ks[c+0][r]=w0.x; Ks[c+1][r]=w0.y; Ks[c+2][r]=w0.z; Ks[c+3][r]=w0.w;
        Ks[c+4][r]=w1.x; Ks[c+5][r]=w1.y; Ks[c+6][r]=w1.z; Ks[c+7][r]=w1.w;
    }
    __syncthreads();

    const int tx = tid & 15, ty = tid >> 4;
    float acc[4][4];
#pragma unroll
    for (int i = 0; i < 4; i++)
#pragma unroll
        for (int j = 0; j < 4; j++) acc[i][j] = 0.f;

#pragma unroll
    for (int kk = 0; kk < 32; kk++) {
        float4 a = *(const float4*)&Qs[kk][ty * 4];
        float4 bb = *(const float4*)&Ks[kk][tx * 4];
        float ar[4] = {a.x, a.y, a.z, a.w};
        float br[4] = {bb.x, bb.y, bb.z, bb.w};
#pragma unroll
        for (int i = 0; i < 4; i++)
#pragma unroll
            for (int j = 0; j < 4; j++)
                acc[i][j] += ar[i] * br[j];
    }

    const float scale = 0.17677669529663687f;  // 1/sqrt(32)
    float* Sb = S + (size_t)bh * QLEN * QLEN;
#pragma unroll
    for (int i = 0; i < 4; i++) {
        int m = m0 + ty * 4 + i;
        if (m >= QLEN) continue;
        int n = n0 + tx * 4;
        if (n + 3 < QLEN) {
            *(float4*)(Sb + (size_t)m * QLEN + n) = make_float4(
                acc[i][0]*scale, acc[i][1]*scale, acc[i][2]*scale, acc[i][3]*scale);
        } else {
#pragma unroll
            for (int j = 0; j < 4; j++)
                if (n + j < QLEN) Sb[(size_t)m * QLEN + n + j] = acc[i][j] * scale;
        }
    }
}

// ---------------------------------------------------------------------------
// Row softmax over 900 elements. grid (900, B*H), 256 threads.
// ---------------------------------------------------------------------------
__global__ __launch_bounds__(256) void softmax900(float* __restrict__ S)
{
    __shared__ float red[8];
    __shared__ float s_val;
    float* row = S + ((size_t)blockIdx.y * QLEN + blockIdx.x) * QLEN;
    const int tid = threadIdx.x;
    const int lane = tid & 31, w = tid >> 5;

    float x[4];
    float m = -3.4e38f;
#pragma unroll
    for (int it = 0; it < 4; it++) {
        int i = tid + it * 256;
        x[it] = (i < QLEN) ? row[i] : -3.4e38f;
        m = fmaxf(m, x[it]);
    }
#pragma unroll
    for (int o = 16; o; o >>= 1) m = fmaxf(m, __shfl_xor_sync(0xffffffffu, m, o));
    if (lane == 0) red[w] = m;
    __syncthreads();
    if (tid == 0) {
        float t = red[0];
        for (int i = 1; i < 8; i++) t = fmaxf(t, red[i]);
        s_val = t;
    }
    __syncthreads();
    m = s_val;
    __syncthreads();

    float sum = 0.f;
#pragma unroll
    for (int it = 0; it < 4; it++) {
        int i = tid + it * 256;
        if (i < QLEN) { x[it] = __expf(x[it] - m); sum += x[it]; }
    }
#pragma unroll
    for (int o = 16; o; o >>= 1) sum += __shfl_xor_sync(0xffffffffu, sum, o);
    if (lane == 0) red[w] = sum;
    __syncthreads();
    if (tid == 0) {
        float t = 0.f;
        for (int i = 0; i < 8; i++) t += red[i];
        s_val = t;
    }
    __syncthreads();
    float inv = 1.f / s_val;
#pragma unroll
    for (int it = 0; it < 4; it++) {
        int i = tid + it * 256;
        if (i < QLEN) row[i] = x[it] * inv;
    }
}

// ---------------------------------------------------------------------------
// O = P @ V per (b,h). BM=256 rows, N=32, BK=32. 256 threads, 8m x 4n each.
// Output written to [b*Q+m, h*32+n] layout of g_attn.
// ---------------------------------------------------------------------------
__global__ __launch_bounds__(256) void attn_av(
    const float* __restrict__ S, const float* __restrict__ qkv,
    float* __restrict__ O)
{
    const int bh = blockIdx.y;
    const int b = bh >> 3, h = bh & 7;
    const int m0 = blockIdx.x * 256;
    __shared__ float PsT[32][256];
    __shared__ float Vs[32][32];
    const int tid = threadIdx.x;
    const int n4 = (tid & 7) * 4;
    const int mg = tid >> 3;   // 0..31 -> rows mg*8 .. mg*8+7

    float acc[8][4];
#pragma unroll
    for (int i = 0; i < 8; i++)
#pragma unroll
        for (int j = 0; j < 4; j++) acc[i][j] = 0.f;

    const float* Sb = S + (size_t)bh * QLEN * QLEN;
    const float* Vb = qkv + (size_t)b * QLEN * 768 + 512 + h * 32;

    for (int k0 = 0; k0 < QLEN; k0 += 32) {
        // load P tile 256x32, transposed
#pragma unroll
        for (int it = 0; it < 8; it++) {
            int s = tid + it * 256;        // float4 slot
            int r = s >> 3;
            int c = (s & 7) * 4;
            float4 v = make_float4(0.f, 0.f, 0.f, 0.f);
            int gm = m0 + r;
            if (gm < QLEN) {
                const float* p = Sb + (size_t)gm * QLEN + k0 + c;
                if (k0 + c + 3 < QLEN) v = *(const float4*)p;
                else {
                    if (k0 + c + 0 < QLEN) v.x = p[0];
                    if (k0 + c + 1 < QLEN) v.y = p[1];
                    if (k0 + c + 2 < QLEN) v.z = p[2];
                    if (k0 + c + 3 < QLEN) v.w = p[3];
                }
            }
            PsT[c + 0][r] = v.x; PsT[c + 1][r] = v.y;
            PsT[c + 2][r] = v.z; PsT[c + 3][r] = v.w;
        }
        {
            int r = tid >> 3, c = (tid & 7) * 4;
            float4 v = make_float4(0.f, 0.f, 0.f, 0.f);
            if (k0 + r < QLEN)
                v = *(const float4*)(Vb + (size_t)(k0 + r) * 768 + c);
            Vs[r][c + 0] = v.x; Vs[r][c + 1] = v.y;
            Vs[r][c + 2] = v.z; Vs[r][c + 3] = v.w;
        }
        __syncthreads();
#pragma unroll
        for (int kk = 0; kk < 32; kk++) {
            float4 p0 = *(const float4*)&PsT[kk][mg * 8];
            float4 p1 = *(const float4*)&PsT[kk][mg * 8 + 4];
            float4 vv = *(const float4*)&Vs[kk][n4];
            float pr[8] = {p0.x, p0.y, p0.z, p0.w, p1.x, p1.y, p1.z, p1.w};
            float vr[4] = {vv.x, vv.y, vv.z, vv.w};
#pragma unroll
            for (int i = 0; i < 8; i++)
#pragma unroll
                for (int j = 0; j < 4; j++)
                    acc[i][j] += pr[i] * vr[j];
        }
        __syncthreads();
    }

#pragma unroll
    for (int i = 0; i < 8; i++) {
        int gm = m0 + mg * 8 + i;
        if (gm >= QLEN) continue;
        *(float4*)(O + ((size_t)(b * QLEN + gm)) * 256 + h * 32 + n4) =
            make_float4(acc[i][0], acc[i][1], acc[i][2], acc[i][3]);
    }
}

// ---------------------------------------------------------------------------
// out = LayerNorm(a + b) over D=256. One block (256 thr) per row.
// ---------------------------------------------------------------------------
__global__ __launch_bounds__(256) void add_ln(
    const float* __restrict__ a, const float* __restrict__ b,
    const float* __restrict__ gam, const float* __restrict__ bet,
    float* __restrict__ out)
{
    __shared__ float red[8];
    __shared__ float s_mu, s_rstd;
    const int tid = threadIdx.x;
    const int lane = tid & 31, w = tid >> 5;
    size_t idx = (size_t)blockIdx.x * 256 + tid;
    float v = a[idx] + b[idx];

    float s = v;
#pragma unroll
    for (int o = 16; o; o >>= 1) s += __shfl_xor_sync(0xffffffffu, s, o);
    if (lane == 0) red[w] = s;
    __syncthreads();
    if (tid == 0) {
        float t = 0.f;
        for (int i = 0; i < 8; i++) t += red[i];
        s_mu = t * (1.f / 256.f);
    }
    __syncthreads();
    float d = v - s_mu;
    float sq = d * d;
    __syncthreads();
#pragma unroll
    for (int o = 16; o; o >>= 1) sq += __shfl_xor_sync(0xffffffffu, sq, o);
    if (lane == 0) red[w] = sq;
    __syncthreads();
    if (tid == 0) {
        float t = 0.f;
        for (int i = 0; i < 8; i++) t += red[i];
        s_rstd = rsqrtf(t * (1.f / 256.f) + 1e-5f);
    }
    __syncthreads();
    out[idx] = d * s_rstd * gam[tid] + bet[tid];
}

// ---------------------------------------------------------------------------
// Fused deformable attention sampling. One block per (b,q).
// Computes ref/offs/attw projections, per-head softmax, bilinear gather.
// ---------------------------------------------------------------------------
__global__ __launch_bounds__(256) void deform_attn(
    const float* __restrict__ t, const float* __restrict__ val,
    const float* __restrict__ offs_w, const float* __restrict__ offs_b,
    const float* __restrict__ attw_w, const float* __restrict__ attw_b,
    const float* __restrict__ ref_w, const float* __restrict__ ref_b,
    const int* __restrict__ pH, const int* __restrict__ pW,
    float* __restrict__ out)
{
    __shared__ float trow[256];
    __shared__ float sref[2];
    __shared__ float soffs[64];
    __shared__ float sattw[32];
    const int bq = blockIdx.x;
    const int b = bq / QLEN;
    const int tid = threadIdx.x;
    const int warp = tid >> 5, lane = tid & 31;

    trow[tid] = t[(size_t)bq * 256 + tid];
    __syncthreads();

    // 98 dot products: 0..1 ref(sigmoid), 2..65 offs, 66..97 attw
    for (int o = warp; o < 98; o += 8) {
        const float* wr;
        float bia;
        if (o < 2)       { wr = ref_w  + o * 256;        bia = ref_b[o]; }
        else if (o < 66) { wr = offs_w + (o - 2) * 256;  bia = offs_b[o - 2]; }
        else             { wr = attw_w + (o - 66) * 256; bia = attw_b[o - 66]; }
        float p = 0.f;
#pragma unroll
        for (int i = 0; i < 8; i++)
            p += trow[lane + i * 32] * wr[lane + i * 32];
#pragma unroll
        for (int oo = 16; oo; oo >>= 1) p += __shfl_xor_sync(0xffffffffu, p, oo);
        if (lane == 0) {
            float r = p + bia;
            if (o < 2)       sref[o] = 1.f / (1.f + __expf(-r));
            else if (o < 66) soffs[o - 2] = r;
            else             sattw[o - 66] = r;
        }
    }
    __syncthreads();

    if (tid < 8) {
        float m = -3.4e38f;
#pragma unroll
        for (int p = 0; p < 4; p++) m = fmaxf(m, sattw[tid * 4 + p]);
        float e[4], s = 0.f;
#pragma unroll
        for (int p = 0; p < 4; p++) { e[p] = __expf(sattw[tid * 4 + p] - m); s += e[p]; }
        float inv = 1.f / s;
#pragma unroll
        for (int p = 0; p < 4; p++) sattw[tid * 4 + p] = e[p] * inv;
    }
    __syncthreads();

    const int H = *pH, W = *pW;
    const float fH = (float)H, fW = (float)W;
    const int h = tid >> 5, d = tid & 31;
    const float refx = sref[0], refy = sref[1];
    const float* vbase = val + (size_t)b * H * W * 256 + h * 32 + d;
    float acc = 0.f;
#pragma unroll
    for (int p = 0; p < NPTS; p++) {
        float locx = refx + soffs[h * 8 + 2 * p]     / fW;
        float locy = refy + soffs[h * 8 + 2 * p + 1] / fH;
        float xx = locx * fW - 0.5f;
        float yy = locy * fH - 0.5f;
        float x0f = floorf(xx), y0f = floorf(yy);
        int x0 = (int)x0f, y0 = (int)y0f;
        float lx = xx - x0f, ly = yy - y0f;
        float w00 = (1.f - lx) * (1.f - ly);
        float w10 = lx * (1.f - ly);
        float w01 = (1.f - lx) * ly;
        float w11 = lx * ly;
        float s = 0.f;
        bool vx0 = (x0 >= 0) & (x0 < W);
        bool vx1 = (x0 + 1 >= 0) & (x0 + 1 < W);
        bool vy0 = (y0 >= 0) & (y0 < H);
        bool vy1 = (y0 + 1 >= 0) & (y0 + 1 < H);
        if (vx0 & vy0) s += w00 * vbase[((size_t)y0 * W + x0) * 256];
        if (vx1 & vy0) s += w10 * vbase[((size_t)y0 * W + x0 + 1) * 256];
        if (vx0 & vy1) s += w01 * vbase[((size_t)(y0 + 1) * W + x0) * 256];
        if (vx1 & vy1) s += w11 * vbase[((size_t)(y0 + 1) * W + x0 + 1) * 256];
        acc += sattw[h * 4 + p] * s;
    }
    out[(size_t)bq * 256 + tid] = acc;
}

// ---------------------------------------------------------------------------
extern "C" void kernel_launch(void* const* d_in, const int* in_sizes, int n_in,
                              void* d_out, int out_size)
{
    const float* tgt  = (const float*)d_in[0];
    const float* mem  = (const float*)d_in[1];
    const int*   pH   = (const int*)d_in[2];
    const int*   pW   = (const int*)d_in[3];
    const float* inw  = (const float*)d_in[4];
    const float* inb  = (const float*)d_in[5];
    const float* outw = (const float*)d_in[6];
    const float* outb = (const float*)d_in[7];
    const float* n1s  = (const float*)d_in[8];
    const float* n1b  = (const float*)d_in[9];
    const float* n2s  = (const float*)d_in[10];
    const float* n2b  = (const float*)d_in[11];
    const float* n3s  = (const float*)d_in[12];
    const float* n3b  = (const float*)d_in[13];
    const float* vpw  = (const float*)d_in[14];
    const float* vpb  = (const float*)d_in[15];
    const float* ofw  = (const float*)d_in[16];
    const float* ofb  = (const float*)d_in[17];
    const float* aww  = (const float*)d_in[18];
    const float* awb  = (const float*)d_in[19];
    const float* rfw  = (const float*)d_in[20];
    const float* rfb  = (const float*)d_in[21];
    const float* cow  = (const float*)d_in[22];
    const float* cob  = (const float*)d_in[23];
    const float* f1w  = (const float*)d_in[24];
    const float* f1b  = (const float*)d_in[25];
    const float* f2w  = (const float*)d_in[26];
    const float* f2b  = (const float*)d_in[27];
    float* outp = (float*)d_out;

    const int M  = in_sizes[0] / DM;          // B*Q = 7200
    const int Mm = in_sizes[1] / DM;          // B*HW = 80000
    const int B  = M / QLEN;                  // 8
    const int BHgrid = B * NH;                // 64

    float *qkv, *scores, *attn, *t1, *val, *dsm, *proj, *t2, *ffn;
    cudaGetSymbolAddress((void**)&qkv,    g_qkv);
    cudaGetSymbolAddress((void**)&scores, g_scores);
    cudaGetSymbolAddress((void**)&attn,   g_attn);
    cudaGetSymbolAddress((void**)&t1,     g_t1);
    cudaGetSymbolAddress((void**)&val,    g_val);
    cudaGetSymbolAddress((void**)&dsm,    g_dsm);
    cudaGetSymbolAddress((void**)&proj,   g_proj);
    cudaGetSymbolAddress((void**)&t2,     g_t2);
    cudaGetSymbolAddress((void**)&ffn,    g_ffn);

    const int mb = (M + 127) / 128;           // 57
    const int mmb = (Mm + 127) / 128;         // 625

    // memory value projection (independent — launch first)
    sgemm_nt<<<dim3(2, mmb), 256>>>(mem, vpw, vpb, val, Mm, 256, 256, 0);

    // self-attention
    sgemm_nt<<<dim3(6, mb), 256>>>(tgt, inw, inb, qkv, M, 768, 256, 0);
    attn_scores<<<dim3((QLEN + 63) / 64, (QLEN + 63) / 64, BHgrid), 256>>>(qkv, scores);
    softmax900<<<dim3(QLEN, BHgrid), 256>>>(scores);
    attn_av<<<dim3((QLEN + 255) / 256, BHgrid), 256>>>(scores, qkv, attn);
    sgemm_nt<<<dim3(2, mb), 256>>>(attn, outw, outb, proj, M, 256, 256, 0);
    add_ln<<<M, 256>>>(proj, tgt, n1s, n1b, t1);

    // deformable cross-attention
    deform_attn<<<M, 256>>>(t1, val, ofw, ofb, aww, awb, rfw, rfb, pH, pW, dsm);
    sgemm_nt<<<dim3(2, mb), 256>>>(dsm, cow, cob, proj, M, 256, 256, 0);
    add_ln<<<M, 256>>>(proj, t1, n2s, n2b, t2);

    // FFN
    sgemm_nt<<<dim3(8, mb), 256>>>(t2, f1w, f1b, ffn, M, FFD, 256, 1);
    sgemm_nt<<<dim3(2, mb), 256>>>(ffn, f2w, f2b, proj, M, 256, FFD, 0);
    add_ln<<<M, 256>>>(proj, t2, n3s, n3b, outp);
}

// round 5
// speedup vs baseline: 1.1484x; 1.1484x over previous
#include <cuda_runtime.h>
#include <math.h>

#define QLEN 900
#define DM   256
#define NH   8
#define HD   32
#define NPTS 4
#define FFD  1024

// ---------------- scratch (__device__ globals; allocation-free) ----------------
__device__ float g_qkv[5529600];      // [B*Q, 768]
__device__ float g_attn[1843200];     // [B*Q, 256] self-attn output
__device__ float g_t1[1843200];       // after norm1
__device__ float g_val[20480000];     // [B*HW, 256] projected memory
__device__ float g_dsm[1843200];      // deform-attn sampled output
__device__ float g_proj[1843200];     // generic GEMM output pre-LN
__device__ float g_t2[1843200];       // after norm2
__device__ float g_ffn[7372800];      // [B*Q, 1024]

// ---------------------------------------------------------------------------
// Generic SGEMM: C[M,N] = act(A[M,K] @ W[N,K]^T + bias[N])
// 128x128 tile, BK=8, 256 threads, 8x8 micro-tile in split 2x(4x4) layout.
// ---------------------------------------------------------------------------
__global__ __launch_bounds__(256) void sgemm_nt(
    const float* __restrict__ A, const float* __restrict__ W,
    const float* __restrict__ bias, float* __restrict__ C,
    int M, int N, int K, int relu)
{
    __shared__ float As[8][128];
    __shared__ float Bs[8][128];
    const int tid = threadIdx.x;
    const int tx = tid & 15;     // col group
    const int ty = tid >> 4;     // row group
    const int row0 = blockIdx.y * 128;
    const int col0 = blockIdx.x * 128;

    const int lr = tid >> 1;           // 0..127
    const int lc = (tid & 1) << 2;     // 0 or 4

    float acc[8][8];
#pragma unroll
    for (int i = 0; i < 8; i++)
#pragma unroll
        for (int j = 0; j < 8; j++) acc[i][j] = 0.f;

    for (int k0 = 0; k0 < K; k0 += 8) {
        float4 av = make_float4(0.f, 0.f, 0.f, 0.f);
        float4 bv = make_float4(0.f, 0.f, 0.f, 0.f);
        if (row0 + lr < M)
            av = *(const float4*)(A + (size_t)(row0 + lr) * K + k0 + lc);
        if (col0 + lr < N)
            bv = *(const float4*)(W + (size_t)(col0 + lr) * K + k0 + lc);
        As[lc + 0][lr] = av.x; As[lc + 1][lr] = av.y;
        As[lc + 2][lr] = av.z; As[lc + 3][lr] = av.w;
        Bs[lc + 0][lr] = bv.x; Bs[lc + 1][lr] = bv.y;
        Bs[lc + 2][lr] = bv.z; Bs[lc + 3][lr] = bv.w;
        __syncthreads();
#pragma unroll
        for (int kk = 0; kk < 8; kk++) {
            float4 a0 = *(const float4*)&As[kk][ty * 4];
            float4 a1 = *(const float4*)&As[kk][64 + ty * 4];
            float4 b0 = *(const float4*)&Bs[kk][tx * 4];
            float4 b1 = *(const float4*)&Bs[kk][64 + tx * 4];
            float ar[8] = {a0.x, a0.y, a0.z, a0.w, a1.x, a1.y, a1.z, a1.w};
            float br[8] = {b0.x, b0.y, b0.z, b0.w, b1.x, b1.y, b1.z, b1.w};
#pragma unroll
            for (int i = 0; i < 8; i++)
#pragma unroll
                for (int j = 0; j < 8; j++)
                    acc[i][j] += ar[i] * br[j];
        }
        __syncthreads();
    }

#pragma unroll
    for (int i = 0; i < 8; i++) {
        int row = row0 + ((i < 4) ? (ty * 4 + i) : (64 + ty * 4 + i - 4));
        if (row >= M) continue;
#pragma unroll
        for (int jb = 0; jb < 2; jb++) {
            int colb = col0 + jb * 64 + tx * 4;
            float v[4];
#pragma unroll
            for (int j = 0; j < 4; j++) {
                v[j] = acc[i][jb * 4 + j];
                int col = colb + j;
                if (col < N) v[j] += bias[col];
                if (relu) v[j] = fmaxf(v[j], 0.f);
            }
            if (colb + 3 < N) {
                *(float4*)(C + (size_t)row * N + colb) =
                    make_float4(v[0], v[1], v[2], v[3]);
            } else {
#pragma unroll
                for (int j = 0; j < 4; j++)
                    if (colb + j < N) C[(size_t)row * N + colb + j] = v[j];
            }
        }
    }
}

// ---------------------------------------------------------------------------
// Fused flash self-attention: per (b,h), 64-query block; online softmax.
// grid (15, B*H), 256 threads. Q scale folded at load.
//   tx = tid&15 : S col-group (4 cols) / O col-group (2 cols)
//   ty = tid>>4 : row-group (4 rows) for both S and O
// ---------------------------------------------------------------------------
__global__ __launch_bounds__(256) void flash_attn(
    const float* __restrict__ qkv, float* __restrict__ O)
{
    const int bh = blockIdx.y;
    const int b = bh >> 3, h = bh & 7;
    const int m0 = blockIdx.x * 64;

    __shared__ float Qs[32][64];     // [k][row]
    __shared__ float Ks[32][64];     // [k][col]
    __shared__ float Vs[64][32];     // [kpos][d]
    __shared__ float Ps[64][68];     // [row][kpos], padded stride 68

    const int tid = threadIdx.x;
    const int tx = tid & 15;
    const int ty = tid >> 4;
    const float scale = 0.17677669529663687f;  // 1/sqrt(32)

    const float* base = qkv + (size_t)b * QLEN * 768 + h * 32;

    // ---- load Q tile (transposed, pre-scaled) ----
    {
        int r = tid >> 2;            // 0..63
        int c = (tid & 3) * 8;       // 0,8,16,24
        float4 v0 = make_float4(0.f,0.f,0.f,0.f), v1 = v0;
        if (m0 + r < QLEN) {
            const float* p = base + (size_t)(m0 + r) * 768 + c;
            v0 = *(const float4*)p; v1 = *(const float4*)(p + 4);
        }
        Qs[c+0][r]=v0.x*scale; Qs[c+1][r]=v0.y*scale;
        Qs[c+2][r]=v0.z*scale; Qs[c+3][r]=v0.w*scale;
        Qs[c+4][r]=v1.x*scale; Qs[c+5][r]=v1.y*scale;
        Qs[c+6][r]=v1.z*scale; Qs[c+7][r]=v1.w*scale;
    }

    float m_i[4], l_i[4];
    float acc_o[4][2];
#pragma unroll
    for (int i = 0; i < 4; i++) {
        m_i[i] = -1e30f; l_i[i] = 0.f;
        acc_o[i][0] = 0.f; acc_o[i][1] = 0.f;
    }

    for (int k0 = 0; k0 < QLEN; k0 += 64) {
        __syncthreads();   // protect Ks/Vs/Ps from previous iteration readers
        // ---- load K tile (transposed) ----
        {
            int r = tid >> 2;
            int c = (tid & 3) * 8;
            float4 w0 = make_float4(0.f,0.f,0.f,0.f), w1 = w0;
            if (k0 + r < QLEN) {
                const float* p = base + 256 + (size_t)(k0 + r) * 768 + c;
                w0 = *(const float4*)p; w1 = *(const float4*)(p + 4);
            }
            Ks[c+0][r]=w0.x; Ks[c+1][r]=w0.y; Ks[c+2][r]=w0.z; Ks[c+3][r]=w0.w;
            Ks[c+4][r]=w1.x; Ks[c+5][r]=w1.y; Ks[c+6][r]=w1.z; Ks[c+7][r]=w1.w;
        }
        // ---- load V tile (natural) ----
        {
            int cv = (tid & 7) * 4;
#pragma unroll
            for (int it = 0; it < 2; it++) {
                int rv = (tid >> 3) + it * 32;
                float4 v = make_float4(0.f, 0.f, 0.f, 0.f);
                if (k0 + rv < QLEN)
                    v = *(const float4*)(base + 512 + (size_t)(k0 + rv) * 768 + cv);
                *(float4*)&Vs[rv][cv] = v;
            }
        }
        __syncthreads();

        // ---- S = Q K^T (64x64), 4x4 per thread ----
        float s[4][4];
#pragma unroll
        for (int i = 0; i < 4; i++)
#pragma unroll
            for (int j = 0; j < 4; j++) s[i][j] = 0.f;
#pragma unroll
        for (int kk = 0; kk < 32; kk++) {
            float4 a = *(const float4*)&Qs[kk][ty * 4];
            float4 bb = *(const float4*)&Ks[kk][tx * 4];
            float ar[4] = {a.x, a.y, a.z, a.w};
            float br[4] = {bb.x, bb.y, bb.z, bb.w};
#pragma unroll
            for (int i = 0; i < 4; i++)
#pragma unroll
                for (int j = 0; j < 4; j++)
                    s[i][j] += ar[i] * br[j];
        }
        // mask invalid key columns
#pragma unroll
        for (int j = 0; j < 4; j++) {
            if (k0 + tx * 4 + j >= QLEN) {
#pragma unroll
                for (int i = 0; i < 4; i++) s[i][j] = -1e30f;
            }
        }

        // ---- online softmax (per row, reduce across 16 tx lanes) ----
        float p[4][4];
#pragma unroll
        for (int i = 0; i < 4; i++) {
            float rm = fmaxf(fmaxf(s[i][0], s[i][1]), fmaxf(s[i][2], s[i][3]));
#pragma unroll
            for (int o = 8; o; o >>= 1)
                rm = fmaxf(rm, __shfl_xor_sync(0xffffffffu, rm, o));
            float mn = fmaxf(m_i[i], rm);
            float corr = __expf(m_i[i] - mn);
            m_i[i] = mn;
            float rs = 0.f;
#pragma unroll
            for (int j = 0; j < 4; j++) {
                p[i][j] = __expf(s[i][j] - mn);
                rs += p[i][j];
            }
#pragma unroll
            for (int o = 8; o; o >>= 1)
                rs += __shfl_xor_sync(0xffffffffu, rs, o);
            l_i[i] = l_i[i] * corr + rs;
            acc_o[i][0] *= corr;
            acc_o[i][1] *= corr;
        }

        // ---- store P tile: Ps[row][kpos], STS.128 per row ----
#pragma unroll
        for (int i = 0; i < 4; i++)
            *(float4*)&Ps[ty * 4 + i][tx * 4] =
                make_float4(p[i][0], p[i][1], p[i][2], p[i][3]);
        __syncthreads();

        // ---- O += P @ V : rows ty*4+i, cols tx*2+{0,1} ----
#pragma unroll
        for (int kk = 0; kk < 64; kk += 4) {
            float4 pr[4];
#pragma unroll
            for (int i = 0; i < 4; i++)
                pr[i] = *(const float4*)&Ps[ty * 4 + i][kk];
            float2 v0 = *(const float2*)&Vs[kk + 0][tx * 2];
            float2 v1 = *(const float2*)&Vs[kk + 1][tx * 2];
            float2 v2 = *(const float2*)&Vs[kk + 2][tx * 2];
            float2 v3 = *(const float2*)&Vs[kk + 3][tx * 2];
#pragma unroll
            for (int i = 0; i < 4; i++) {
                acc_o[i][0] += pr[i].x * v0.x + pr[i].y * v1.x
                             + pr[i].z * v2.x + pr[i].w * v3.x;
                acc_o[i][1] += pr[i].x * v0.y + pr[i].y * v1.y
                             + pr[i].z * v2.y + pr[i].w * v3.y;
            }
        }
    }

    // ---- finalize: O /= l, store ----
#pragma unroll
    for (int i = 0; i < 4; i++) {
        int row = m0 + ty * 4 + i;
        if (row >= QLEN) continue;
        float inv = 1.f / l_i[i];
        float2 out = make_float2(acc_o[i][0] * inv, acc_o[i][1] * inv);
        *(float2*)(O + ((size_t)(b * QLEN + row)) * 256 + h * 32 + tx * 2) = out;
    }
}

// ---------------------------------------------------------------------------
// out = LayerNorm(a + b) over D=256. One block (256 thr) per row.
// ---------------------------------------------------------------------------
__global__ __launch_bounds__(256) void add_ln(
    const float* __restrict__ a, const float* __restrict__ b,
    const float* __restrict__ gam, const float* __restrict__ bet,
    float* __restrict__ out)
{
    __shared__ float red[8];
    __shared__ float s_mu, s_rstd;
    const int tid = threadIdx.x;
    const int lane = tid & 31, w = tid >> 5;
    size_t idx = (size_t)blockIdx.x * 256 + tid;
    float v = a[idx] + b[idx];

    float s = v;
#pragma unroll
    for (int o = 16; o; o >>= 1) s += __shfl_xor_sync(0xffffffffu, s, o);
    if (lane == 0) red[w] = s;
    __syncthreads();
    if (tid == 0) {
        float t = 0.f;
        for (int i = 0; i < 8; i++) t += red[i];
        s_mu = t * (1.f / 256.f);
    }
    __syncthreads();
    float d = v - s_mu;
    float sq = d * d;
    __syncthreads();
#pragma unroll
    for (int o = 16; o; o >>= 1) sq += __shfl_xor_sync(0xffffffffu, sq, o);
    if (lane == 0) red[w] = sq;
    __syncthreads();
    if (tid == 0) {
        float t = 0.f;
        for (int i = 0; i < 8; i++) t += red[i];
        s_rstd = rsqrtf(t * (1.f / 256.f) + 1e-5f);
    }
    __syncthreads();
    out[idx] = d * s_rstd * gam[tid] + bet[tid];
}

// ---------------------------------------------------------------------------
// Fused deformable attention sampling. One block per (b,q).
// ---------------------------------------------------------------------------
__global__ __launch_bounds__(256) void deform_attn(
    const float* __restrict__ t, const float* __restrict__ val,
    const float* __restrict__ offs_w, const float* __restrict__ offs_b,
    const float* __restrict__ attw_w, const float* __restrict__ attw_b,
    const float* __restrict__ ref_w, const float* __restrict__ ref_b,
    const int* __restrict__ pH, const int* __restrict__ pW,
    float* __restrict__ out)
{
    __shared__ float trow[256];
    __shared__ float sref[2];
    __shared__ float soffs[64];
    __shared__ float sattw[32];
    const int bq = blockIdx.x;
    const int b = bq / QLEN;
    const int tid = threadIdx.x;
    const int warp = tid >> 5, lane = tid & 31;

    trow[tid] = t[(size_t)bq * 256 + tid];
    __syncthreads();

    for (int o = warp; o < 98; o += 8) {
        const float* wr;
        float bia;
        if (o < 2)       { wr = ref_w  + o * 256;        bia = ref_b[o]; }
        else if (o < 66) { wr = offs_w + (o - 2) * 256;  bia = offs_b[o - 2]; }
        else             { wr = attw_w + (o - 66) * 256; bia = attw_b[o - 66]; }
        float p = 0.f;
#pragma unroll
        for (int i = 0; i < 8; i++)
            p += trow[lane + i * 32] * wr[lane + i * 32];
#pragma unroll
        for (int oo = 16; oo; oo >>= 1) p += __shfl_xor_sync(0xffffffffu, p, oo);
        if (lane == 0) {
            float r = p + bia;
            if (o < 2)       sref[o] = 1.f / (1.f + __expf(-r));
            else if (o < 66) soffs[o - 2] = r;
            else             sattw[o - 66] = r;
        }
    }
    __syncthreads();

    if (tid < 8) {
        float m = -3.4e38f;
#pragma unroll
        for (int p = 0; p < 4; p++) m = fmaxf(m, sattw[tid * 4 + p]);
        float e[4], s = 0.f;
#pragma unroll
        for (int p = 0; p < 4; p++) { e[p] = __expf(sattw[tid * 4 + p] - m); s += e[p]; }
        float inv = 1.f / s;
#pragma unroll
        for (int p = 0; p < 4; p++) sattw[tid * 4 + p] = e[p] * inv;
    }
    __syncthreads();

    const int H = *pH, W = *pW;
    const float fH = (float)H, fW = (float)W;
    const int h = tid >> 5, d = tid & 31;
    const float refx = sref[0], refy = sref[1];
    const float* vbase = val + (size_t)b * H * W * 256 + h * 32 + d;
    float acc = 0.f;
#pragma unroll
    for (int p = 0; p < NPTS; p++) {
        float locx = refx + soffs[h * 8 + 2 * p]     / fW;
        float locy = refy + soffs[h * 8 + 2 * p + 1] / fH;
        float xx = locx * fW - 0.5f;
        float yy = locy * fH - 0.5f;
        float x0f = floorf(xx), y0f = floorf(yy);
        int x0 = (int)x0f, y0 = (int)y0f;
        float lx = xx - x0f, ly = yy - y0f;
        float w00 = (1.f - lx) * (1.f - ly);
        float w10 = lx * (1.f - ly);
        float w01 = (1.f - lx) * ly;
        float w11 = lx * ly;
        float s = 0.f;
        bool vx0 = (x0 >= 0) & (x0 < W);
        bool vx1 = (x0 + 1 >= 0) & (x0 + 1 < W);
        bool vy0 = (y0 >= 0) & (y0 < H);
        bool vy1 = (y0 + 1 >= 0) & (y0 + 1 < H);
        if (vx0 & vy0) s += w00 * vbase[((size_t)y0 * W + x0) * 256];
        if (vx1 & vy0) s += w10 * vbase[((size_t)y0 * W + x0 + 1) * 256];
        if (vx0 & vy1) s += w01 * vbase[((size_t)(y0 + 1) * W + x0) * 256];
        if (vx1 & vy1) s += w11 * vbase[((size_t)(y0 + 1) * W + x0 + 1) * 256];
        acc += sattw[h * 4 + p] * s;
    }
    out[(size_t)bq * 256 + tid] = acc;
}

// ---------------------------------------------------------------------------
extern "C" void kernel_launch(void* const* d_in, const int* in_sizes, int n_in,
                              void* d_out, int out_size)
{
    const float* tgt  = (const float*)d_in[0];
    const float* mem  = (const float*)d_in[1];
    const int*   pH   = (const int*)d_in[2];
    const int*   pW   = (const int*)d_in[3];
    const float* inw  = (const float*)d_in[4];
    const float* inb  = (const float*)d_in[5];
    const float* outw = (const float*)d_in[6];
    const float* outb = (const float*)d_in[7];
    const float* n1s  = (const float*)d_in[8];
    const float* n1b  = (const float*)d_in[9];
    const float* n2s  = (const float*)d_in[10];
    const float* n2b  = (const float*)d_in[11];
    const float* n3s  = (const float*)d_in[12];
    const float* n3b  = (const float*)d_in[13];
    const float* vpw  = (const float*)d_in[14];
    const float* vpb  = (const float*)d_in[15];
    const float* ofw  = (const float*)d_in[16];
    const float* ofb  = (const float*)d_in[17];
    const float* aww  = (const float*)d_in[18];
    const float* awb  = (const float*)d_in[19];
    const float* rfw  = (const float*)d_in[20];
    const float* rfb  = (const float*)d_in[21];
    const float* cow  = (const float*)d_in[22];
    const float* cob  = (const float*)d_in[23];
    const float* f1w  = (const float*)d_in[24];
    const float* f1b  = (const float*)d_in[25];
    const float* f2w  = (const float*)d_in[26];
    const float* f2b  = (const float*)d_in[27];
    float* outp = (float*)d_out;

    const int M  = in_sizes[0] / DM;          // B*Q = 7200
    const int Mm = in_sizes[1] / DM;          // B*HW = 80000
    const int B  = M / QLEN;                  // 8
    const int BHgrid = B * NH;                // 64

    float *qkv, *attn, *t1, *val, *dsm, *proj, *t2, *ffn;
    cudaGetSymbolAddress((void**)&qkv,  g_qkv);
    cudaGetSymbolAddress((void**)&attn, g_attn);
    cudaGetSymbolAddress((void**)&t1,   g_t1);
    cudaGetSymbolAddress((void**)&val,  g_val);
    cudaGetSymbolAddress((void**)&dsm,  g_dsm);
    cudaGetSymbolAddress((void**)&proj, g_proj);
    cudaGetSymbolAddress((void**)&t2,   g_t2);
    cudaGetSymbolAddress((void**)&ffn,  g_ffn);

    const int mb = (M + 127) / 128;           // 57
    const int mmb = (Mm + 127) / 128;         // 625

    // memory value projection (independent — launch first)
    sgemm_nt<<<dim3(2, mmb), 256>>>(mem, vpw, vpb, val, Mm, 256, 256, 0);

    // self-attention (fused flash)
    sgemm_nt<<<dim3(6, mb), 256>>>(tgt, inw, inb, qkv, M, 768, 256, 0);
    flash_attn<<<dim3((QLEN + 63) / 64, BHgrid), 256>>>(qkv, attn);
    sgemm_nt<<<dim3(2, mb), 256>>>(attn, outw, outb, proj, M, 256, 256, 0);
    add_ln<<<M, 256>>>(proj, tgt, n1s, n1b, t1);

    // deformable cross-attention
    deform_attn<<<M, 256>>>(t1, val, ofw, ofb, aww, awb, rfw, rfb, pH, pW, dsm);
    sgemm_nt<<<dim3(2, mb), 256>>>(dsm, cow, cob, proj, M, 256, 256, 0);
    add_ln<<<M, 256>>>(proj, t1, n2s, n2b, t2);

    // FFN
    sgemm_nt<<<dim3(8, mb), 256>>>(t2, f1w, f1b, ffn, M, FFD, 256, 1);
    sgemm_nt<<<dim3(2, mb), 256>>>(ffn, f2w, f2b, proj, M, 256, FFD, 0);
    add_ln<<<M, 256>>>(proj, t2, n3s, n3b, outp);
}

// round 7
// speedup vs baseline: 1.7551x; 1.5283x over previous
#include <cuda_runtime.h>
#include <cuda_bf16.h>
#include <math.h>
#include <stdint.h>

#define QLEN 900
#define DM   256
#define NH   8
#define HD   32
#define NPTS 4
#define FFD  1024

// ---------------- scratch (__device__ globals; allocation-free) ----------------
__device__ float g_qkv[5529600];      // [B*Q, 768]
__device__ float g_attn[1843200];     // [B*Q, 256]
__device__ float g_t1[1843200];
__device__ float g_val[20480000];     // [B*HW, 256]
__device__ float g_dsm[1843200];
__device__ float g_proj[1843200];
__device__ float g_t2[1843200];
__device__ float g_ffn[7372800];      // [B*Q, 1024]
// bf16 hi/lo split buffers
__device__ __nv_bfloat16 g_ah[20480000];
__device__ __nv_bfloat16 g_al[20480000];
__device__ __nv_bfloat16 g_wh[262144];
__device__ __nv_bfloat16 g_wl[262144];

// ============================================================================
// helpers
// ============================================================================
__device__ __forceinline__ uint32_t smem_u32(const void* p) {
    uint32_t a;
    asm("{ .reg .u64 t; cvta.to.shared.u64 t, %1; cvt.u32.u64 %0, t; }"
        : "=r"(a) : "l"(p));
    return a;
}
__device__ __forceinline__ uint32_t sw128(uint32_t off) {
    return off ^ ((off >> 3) & 0x70);
}
__device__ __forceinline__ void cvt_split(float f, uint16_t& h, uint16_t& l) {
    __nv_bfloat16 hb = __float2bfloat16_rn(f);
    float r = f - __bfloat162float(hb);
    __nv_bfloat16 lb = __float2bfloat16_rn(r);
    h = *reinterpret_cast<uint16_t*>(&hb);
    l = *reinterpret_cast<uint16_t*>(&lb);
}
__device__ __forceinline__ void ldmx4(uint32_t* r, uint32_t addr) {
    asm volatile("ldmatrix.sync.aligned.m8n8.x4.shared.b16 {%0,%1,%2,%3}, [%4];"
        : "=r"(r[0]), "=r"(r[1]), "=r"(r[2]), "=r"(r[3]) : "r"(addr));
}
__device__ __forceinline__ void mma16816(float* d, const uint32_t* a,
                                         uint32_t b0, uint32_t b1) {
    asm volatile(
        "mma.sync.aligned.m16n8k16.row.col.f32.bf16.bf16.f32 "
        "{%0,%1,%2,%3}, {%4,%5,%6,%7}, {%8,%9}, {%0,%1,%2,%3};"
        : "+f"(d[0]), "+f"(d[1]), "+f"(d[2]), "+f"(d[3])
        : "r"(a[0]), "r"(a[1]), "r"(a[2]), "r"(a[3]), "r"(b0), "r"(b1));
}

// ============================================================================
// split_bf16: fp32 -> (hi, lo) bf16, vectorized by 4.
// ============================================================================
__global__ __launch_bounds__(256) void split_bf16(
    const float* __restrict__ x, __nv_bfloat16* __restrict__ hi,
    __nv_bfloat16* __restrict__ lo, int n4)
{
    int i = blockIdx.x * 256 + threadIdx.x;
    if (i >= n4) return;
    float4 v = ((const float4*)x)[i];
    uint16_t h0,h1,h2,h3,l0,l1,l2,l3;
    cvt_split(v.x,h0,l0); cvt_split(v.y,h1,l1);
    cvt_split(v.z,h2,l2); cvt_split(v.w,h3,l3);
    ((uint2*)hi)[i] = make_uint2((uint32_t)h0 | ((uint32_t)h1 << 16),
                                 (uint32_t)h2 | ((uint32_t)h3 << 16));
    ((uint2*)lo)[i] = make_uint2((uint32_t)l0 | ((uint32_t)l1 << 16),
                                 (uint32_t)l2 | ((uint32_t)l3 << 16));
}

// ============================================================================
// hgemm: C[M,N] = act(A[M,K] @ W[N,K]^T + bias) with bf16x3 (Ah,Al)x(Wh,Wl).
// 128x128 tile, BK=64, 8 warps (64x32 each), mma.sync m16n8k16 bf16.
// Requires N%128==0, K%64==0. M guarded.
// smem: 4 x 16KB regions (Ah, Al, Bh, Bl), SW128 swizzle, single buffer.
// ============================================================================
#define HG_SMEM 65536

__global__ __launch_bounds__(256) void hgemm(
    const __nv_bfloat16* __restrict__ Ah, const __nv_bfloat16* __restrict__ Al,
    const __nv_bfloat16* __restrict__ Wh, const __nv_bfloat16* __restrict__ Wl,
    const float* __restrict__ bias, float* __restrict__ C,
    int M, int N, int K, int relu)
{
    extern __shared__ char sm[];
    const uint32_t sb = smem_u32(sm);
    const int tid = threadIdx.x;
    const int wid = tid >> 5, lane = tid & 31;
    const int row0 = blockIdx.y * 128, col0 = blockIdx.x * 128;
    const int wm = (wid & 1) * 64;      // warp m offset
    const int wn = (wid >> 1) * 32;     // warp n offset

    float acc[4][4][4];
#pragma unroll
    for (int mt = 0; mt < 4; mt++)
#pragma unroll
        for (int nt = 0; nt < 4; nt++)
#pragma unroll
            for (int j = 0; j < 4; j++) acc[mt][nt][j] = 0.f;

    // ldmatrix per-lane address components (byte offsets inside a region)
    const uint32_t a_row = wm + (lane & 15);
    const uint32_t a_cb  = (lane >> 4) * 16;              // k-half select (bytes)
    const uint32_t b_row = wn + (lane & 7) + ((lane >> 4) << 3);
    const uint32_t b_cb  = ((lane >> 3) & 1) * 16;

    for (int k0 = 0; k0 < K; k0 += 64) {
        __syncthreads();
        // ---- load 128x64 bf16 tiles for Ah/Al/Bh/Bl ----
#pragma unroll
        for (int it = 0; it < 4; it++) {
            int idx = it * 256 + tid;
            int r = idx >> 3;
            int c8 = (idx & 7) * 8;
            uint32_t so = sw128((uint32_t)(r * 128 + c8 * 2));
            uint4 z = make_uint4(0u, 0u, 0u, 0u);
            uint4 vah = z, valo = z;
            if (row0 + r < M) {
                vah  = *(const uint4*)(Ah + (size_t)(row0 + r) * K + k0 + c8);
                valo = *(const uint4*)(Al + (size_t)(row0 + r) * K + k0 + c8);
            }
            *(uint4*)(sm + so)         = vah;
            *(uint4*)(sm + 16384 + so) = valo;
            uint4 vbh = *(const uint4*)(Wh + (size_t)(col0 + r) * K + k0 + c8);
            uint4 vbl = *(const uint4*)(Wl + (size_t)(col0 + r) * K + k0 + c8);
            *(uint4*)(sm + 32768 + so) = vbh;
            *(uint4*)(sm + 49152 + so) = vbl;
        }
        __syncthreads();

        // ---- compute: 4 k-steps of 16 ----
#pragma unroll
        for (int ks = 0; ks < 64; ks += 16) {
            uint32_t ah[4][4], alr[4][4], bh[2][4], bl[2][4];
#pragma unroll
            for (int mt = 0; mt < 4; mt++) {
                uint32_t off = sw128((a_row + mt * 16) * 128 + ks * 2 + a_cb);
                ldmx4(ah[mt],  sb + off);
                ldmx4(alr[mt], sb + 16384 + off);
            }
#pragma unroll
            for (int bt = 0; bt < 2; bt++) {
                uint32_t off = sw128((b_row + bt * 16) * 128 + ks * 2 + b_cb);
                ldmx4(bh[bt], sb + 32768 + off);
                ldmx4(bl[bt], sb + 49152 + off);
            }
#pragma unroll
            for (int mt = 0; mt < 4; mt++) {
#pragma unroll
                for (int nt = 0; nt < 4; nt++) {
                    int bt = nt >> 1, bi = (nt & 1) * 2;
                    mma16816(acc[mt][nt], ah[mt],  bh[bt][bi], bh[bt][bi+1]);
                    mma16816(acc[mt][nt], ah[mt],  bl[bt][bi], bl[bt][bi+1]);
                    mma16816(acc[mt][nt], alr[mt], bh[bt][bi], bh[bt][bi+1]);
                }
            }
        }
    }

    // ---- epilogue: bias + relu + store ----
#pragma unroll
    for (int mt = 0; mt < 4; mt++) {
        int r0e = row0 + wm + mt * 16 + (lane >> 2);
#pragma unroll
        for (int nt = 0; nt < 4; nt++) {
            int c = col0 + wn + nt * 8 + (lane & 3) * 2;
            float b0 = bias[c], b1 = bias[c + 1];
            float2 v0 = make_float2(acc[mt][nt][0] + b0, acc[mt][nt][1] + b1);
            float2 v1 = make_float2(acc[mt][nt][2] + b0, acc[mt][nt][3] + b1);
            if (relu) {
                v0.x = fmaxf(v0.x, 0.f); v0.y = fmaxf(v0.y, 0.f);
                v1.x = fmaxf(v1.x, 0.f); v1.y = fmaxf(v1.y, 0.f);
            }
            if (r0e < M)     *(float2*)(C + (size_t)r0e * N + c) = v0;
            if (r0e + 8 < M) *(float2*)(C + (size_t)(r0e + 8) * N + c) = v1;
        }
    }
}

// ---------------------------------------------------------------------------
// Fused flash self-attention: per (b,h), 64-query block; online softmax.
// ---------------------------------------------------------------------------
__global__ __launch_bounds__(256) void flash_attn(
    const float* __restrict__ qkv, float* __restrict__ O)
{
    const int bh = blockIdx.y;
    const int b = bh >> 3, h = bh & 7;
    const int m0 = blockIdx.x * 64;

    __shared__ float Qs[32][64];
    __shared__ float Ks[32][64];
    __shared__ float Vs[64][32];
    __shared__ float Ps[64][68];

    const int tid = threadIdx.x;
    const int tx = tid & 15;
    const int ty = tid >> 4;
    const float scale = 0.17677669529663687f;

    const float* base = qkv + (size_t)b * QLEN * 768 + h * 32;

    {
        int r = tid >> 2;
        int c = (tid & 3) * 8;
        float4 v0 = make_float4(0.f,0.f,0.f,0.f), v1 = v0;
        if (m0 + r < QLEN) {
            const float* p = base + (size_t)(m0 + r) * 768 + c;
            v0 = *(const float4*)p; v1 = *(const float4*)(p + 4);
        }
        Qs[c+0][r]=v0.x*scale; Qs[c+1][r]=v0.y*scale;
        Qs[c+2][r]=v0.z*scale; Qs[c+3][r]=v0.w*scale;
        Qs[c+4][r]=v1.x*scale; Qs[c+5][r]=v1.y*scale;
        Qs[c+6][r]=v1.z*scale; Qs[c+7][r]=v1.w*scale;
    }

    float m_i[4], l_i[4];
    float acc_o[4][2];
#pragma unroll
    for (int i = 0; i < 4; i++) {
        m_i[i] = -1e30f; l_i[i] = 0.f;
        acc_o[i][0] = 0.f; acc_o[i][1] = 0.f;
    }

    for (int k0 = 0; k0 < QLEN; k0 += 64) {
        __syncthreads();
        {
            int r = tid >> 2;
            int c = (tid & 3) * 8;
            float4 w0 = make_float4(0.f,0.f,0.f,0.f), w1 = w0;
            if (k0 + r < QLEN) {
                const float* p = base + 256 + (size_t)(k0 + r) * 768 + c;
                w0 = *(const float4*)p; w1 = *(const float4*)(p + 4);
            }
            Ks[c+0][r]=w0.x; Ks[c+1][r]=w0.y; Ks[c+2][r]=w0.z; Ks[c+3][r]=w0.w;
            Ks[c+4][r]=w1.x; Ks[c+5][r]=w1.y; Ks[c+6][r]=w1.z; Ks[c+7][r]=w1.w;
        }
        {
            int cv = (tid & 7) * 4;
#pragma unroll
            for (int it = 0; it < 2; it++) {
                int rv = (tid >> 3) + it * 32;
                float4 v = make_float4(0.f, 0.f, 0.f, 0.f);
                if (k0 + rv < QLEN)
                    v = *(const float4*)(base + 512 + (size_t)(k0 + rv) * 768 + cv);
                *(float4*)&Vs[rv][cv] = v;
            }
        }
        __syncthreads();

        float s[4][4];
#pragma unroll
        for (int i = 0; i < 4; i++)
#pragma unroll
            for (int j = 0; j < 4; j++) s[i][j] = 0.f;
#pragma unroll
        for (int kk = 0; kk < 32; kk++) {
            float4 a = *(const float4*)&Qs[kk][ty * 4];
            float4 bb = *(const float4*)&Ks[kk][tx * 4];
            float ar[4] = {a.x, a.y, a.z, a.w};
            float br[4] = {bb.x, bb.y, bb.z, bb.w};
#pragma unroll
            for (int i = 0; i < 4; i++)
#pragma unroll
                for (int j = 0; j < 4; j++)
                    s[i][j] += ar[i] * br[j];
        }
#pragma unroll
        for (int j = 0; j < 4; j++) {
            if (k0 + tx * 4 + j >= QLEN) {
#pragma unroll
                for (int i = 0; i < 4; i++) s[i][j] = -1e30f;
            }
        }

        float p[4][4];
#pragma unroll
        for (int i = 0; i < 4; i++) {
            float rm = fmaxf(fmaxf(s[i][0], s[i][1]), fmaxf(s[i][2], s[i][3]));
#pragma unroll
            for (int o = 8; o; o >>= 1)
                rm = fmaxf(rm, __shfl_xor_sync(0xffffffffu, rm, o));
            float mn = fmaxf(m_i[i], rm);
            float corr = __expf(m_i[i] - mn);
            m_i[i] = mn;
            float rs = 0.f;
#pragma unroll
            for (int j = 0; j < 4; j++) {
                p[i][j] = __expf(s[i][j] - mn);
                rs += p[i][j];
            }
#pragma unroll
            for (int o = 8; o; o >>= 1)
                rs += __shfl_xor_sync(0xffffffffu, rs, o);
            l_i[i] = l_i[i] * corr + rs;
            acc_o[i][0] *= corr;
            acc_o[i][1] *= corr;
        }

#pragma unroll
        for (int i = 0; i < 4; i++)
            *(float4*)&Ps[ty * 4 + i][tx * 4] =
                make_float4(p[i][0], p[i][1], p[i][2], p[i][3]);
        __syncthreads();

#pragma unroll
        for (int kk = 0; kk < 64; kk += 4) {
            float4 pr[4];
#pragma unroll
            for (int i = 0; i < 4; i++)
                pr[i] = *(const float4*)&Ps[ty * 4 + i][kk];
            float2 v0 = *(const float2*)&Vs[kk + 0][tx * 2];
            float2 v1 = *(const float2*)&Vs[kk + 1][tx * 2];
            float2 v2 = *(const float2*)&Vs[kk + 2][tx * 2];
            float2 v3 = *(const float2*)&Vs[kk + 3][tx * 2];
#pragma unroll
            for (int i = 0; i < 4; i++) {
                acc_o[i][0] += pr[i].x * v0.x + pr[i].y * v1.x
                             + pr[i].z * v2.x + pr[i].w * v3.x;
                acc_o[i][1] += pr[i].x * v0.y + pr[i].y * v1.y
                             + pr[i].z * v2.y + pr[i].w * v3.y;
            }
        }
    }

#pragma unroll
    for (int i = 0; i < 4; i++) {
        int row = m0 + ty * 4 + i;
        if (row >= QLEN) continue;
        float inv = 1.f / l_i[i];
        float2 out = make_float2(acc_o[i][0] * inv, acc_o[i][1] * inv);
        *(float2*)(O + ((size_t)(b * QLEN + row)) * 256 + h * 32 + tx * 2) = out;
    }
}

// ---------------------------------------------------------------------------
// out = LayerNorm(a + b) over D=256. One block (256 thr) per row.
// ---------------------------------------------------------------------------
__global__ __launch_bounds__(256) void add_ln(
    const float* __restrict__ a, const float* __restrict__ b,
    const float* __restrict__ gam, const float* __restrict__ bet,
    float* __restrict__ out)
{
    __shared__ float red[8];
    __shared__ float s_mu, s_rstd;
    const int tid = threadIdx.x;
    const int lane = tid & 31, w = tid >> 5;
    size_t idx = (size_t)blockIdx.x * 256 + tid;
    float v = a[idx] + b[idx];

    float s = v;
#pragma unroll
    for (int o = 16; o; o >>= 1) s += __shfl_xor_sync(0xffffffffu, s, o);
    if (lane == 0) red[w] = s;
    __syncthreads();
    if (tid == 0) {
        float t = 0.f;
        for (int i = 0; i < 8; i++) t += red[i];
        s_mu = t * (1.f / 256.f);
    }
    __syncthreads();
    float d = v - s_mu;
    float sq = d * d;
    __syncthreads();
#pragma unroll
    for (int o = 16; o; o >>= 1) sq += __shfl_xor_sync(0xffffffffu, sq, o);
    if (lane == 0) red[w] = sq;
    __syncthreads();
    if (tid == 0) {
        float t = 0.f;
        for (int i = 0; i < 8; i++) t += red[i];
        s_rstd = rsqrtf(t * (1.f / 256.f) + 1e-5f);
    }
    __syncthreads();
    out[idx] = d * s_rstd * gam[tid] + bet[tid];
}

// ---------------------------------------------------------------------------
// Fused deformable attention sampling. One block per (b,q).
// ---------------------------------------------------------------------------
__global__ __launch_bounds__(256) void deform_attn(
    const float* __restrict__ t, const float* __restrict__ val,
    const float* __restrict__ offs_w, const float* __restrict__ offs_b,
    const float* __restrict__ attw_w, const float* __restrict__ attw_b,
    const float* __restrict__ ref_w, const float* __restrict__ ref_b,
    const int* __restrict__ pH, const int* __restrict__ pW,
    float* __restrict__ out)
{
    __shared__ float trow[256];
    __shared__ float sref[2];
    __shared__ float soffs[64];
    __shared__ float sattw[32];
    const int bq = blockIdx.x;
    const int b = bq / QLEN;
    const int tid = threadIdx.x;
    const int warp = tid >> 5, lane = tid & 31;

    trow[tid] = t[(size_t)bq * 256 + tid];
    __syncthreads();

    for (int o = warp; o < 98; o += 8) {
        const float* wr;
        float bia;
        if (o < 2)       { wr = ref_w  + o * 256;        bia = ref_b[o]; }
        else if (o < 66) { wr = offs_w + (o - 2) * 256;  bia = offs_b[o - 2]; }
        else             { wr = attw_w + (o - 66) * 256; bia = attw_b[o - 66]; }
        float p = 0.f;
#pragma unroll
        for (int i = 0; i < 8; i++)
            p += trow[lane + i * 32] * wr[lane + i * 32];
#pragma unroll
        for (int oo = 16; oo; oo >>= 1) p += __shfl_xor_sync(0xffffffffu, p, oo);
        if (lane == 0) {
            float r = p + bia;
            if (o < 2)       sref[o] = 1.f / (1.f + __expf(-r));
            else if (o < 66) soffs[o - 2] = r;
            else             sattw[o - 66] = r;
        }
    }
    __syncthreads();

    if (tid < 8) {
        float m = -3.4e38f;
#pragma unroll
        for (int p = 0; p < 4; p++) m = fmaxf(m, sattw[tid * 4 + p]);
        float e[4], s = 0.f;
#pragma unroll
        for (int p = 0; p < 4; p++) { e[p] = __expf(sattw[tid * 4 + p] - m); s += e[p]; }
        float inv = 1.f / s;
#pragma unroll
        for (int p = 0; p < 4; p++) sattw[tid * 4 + p] = e[p] * inv;
    }
    __syncthreads();

    const int H = *pH, W = *pW;
    const float fH = (float)H, fW = (float)W;
    const int h = tid >> 5, d = tid & 31;
    const float refx = sref[0], refy = sref[1];
    const float* vbase = val + (size_t)b * H * W * 256 + h * 32 + d;
    float acc = 0.f;
#pragma unroll
    for (int p = 0; p < NPTS; p++) {
        float locx = refx + soffs[h * 8 + 2 * p]     / fW;
        float locy = refy + soffs[h * 8 + 2 * p + 1] / fH;
        float xx = locx * fW - 0.5f;
        float yy = locy * fH - 0.5f;
        float x0f = floorf(xx), y0f = floorf(yy);
        int x0 = (int)x0f, y0 = (int)y0f;
        float lx = xx - x0f, ly = yy - y0f;
        float w00 = (1.f - lx) * (1.f - ly);
        float w10 = lx * (1.f - ly);
        float w01 = (1.f - lx) * ly;
        float w11 = lx * ly;
        float s = 0.f;
        bool vx0 = (x0 >= 0) & (x0 < W);
        bool vx1 = (x0 + 1 >= 0) & (x0 + 1 < W);
        bool vy0 = (y0 >= 0) & (y0 < H);
        bool vy1 = (y0 + 1 >= 0) & (y0 + 1 < H);
        if (vx0 & vy0) s += w00 * vbase[((size_t)y0 * W + x0) * 256];
        if (vx1 & vy0) s += w10 * vbase[((size_t)y0 * W + x0 + 1) * 256];
        if (vx0 & vy1) s += w01 * vbase[((size_t)(y0 + 1) * W + x0) * 256];
        if (vx1 & vy1) s += w11 * vbase[((size_t)(y0 + 1) * W + x0 + 1) * 256];
        acc += sattw[h * 4 + p] * s;
    }
    out[(size_t)bq * 256 + tid] = acc;
}

// ---------------------------------------------------------------------------
extern "C" void kernel_launch(void* const* d_in, const int* in_sizes, int n_in,
                              void* d_out, int out_size)
{
    const float* tgt  = (const float*)d_in[0];
    const float* mem  = (const float*)d_in[1];
    const int*   pH   = (const int*)d_in[2];
    const int*   pW   = (const int*)d_in[3];
    const float* inw  = (const float*)d_in[4];
    const float* inb  = (const float*)d_in[5];
    const float* outw = (const float*)d_in[6];
    const float* outb = (const float*)d_in[7];
    const float* n1s  = (const float*)d_in[8];
    const float* n1b  = (const float*)d_in[9];
    const float* n2s  = (const float*)d_in[10];
    const float* n2b  = (const float*)d_in[11];
    const float* n3s  = (const float*)d_in[12];
    const float* n3b  = (const float*)d_in[13];
    const float* vpw  = (const float*)d_in[14];
    const float* vpb  = (const float*)d_in[15];
    const float* ofw  = (const float*)d_in[16];
    const float* ofb  = (const float*)d_in[17];
    const float* aww  = (const float*)d_in[18];
    const float* awb  = (const float*)d_in[19];
    const float* rfw  = (const float*)d_in[20];
    const float* rfb  = (const float*)d_in[21];
    const float* cow  = (const float*)d_in[22];
    const float* cob  = (const float*)d_in[23];
    const float* f1w  = (const float*)d_in[24];
    const float* f1b  = (const float*)d_in[25];
    const float* f2w  = (const float*)d_in[26];
    const float* f2b  = (const float*)d_in[27];
    float* outp = (float*)d_out;

    const int M  = in_sizes[0] / DM;          // B*Q = 7200
    const int Mm = in_sizes[1] / DM;          // B*HW = 80000
    const int B  = M / QLEN;                  // 8
    const int BHgrid = B * NH;                // 64

    float *qkv, *attn, *t1, *val, *dsm, *proj, *t2, *ffn;
    __nv_bfloat16 *ah, *al, *wh, *wl;
    cudaGetSymbolAddress((void**)&qkv,  g_qkv);
    cudaGetSymbolAddress((void**)&attn, g_attn);
    cudaGetSymbolAddress((void**)&t1,   g_t1);
    cudaGetSymbolAddress((void**)&val,  g_val);
    cudaGetSymbolAddress((void**)&dsm,  g_dsm);
    cudaGetSymbolAddress((void**)&proj, g_proj);
    cudaGetSymbolAddress((void**)&t2,   g_t2);
    cudaGetSymbolAddress((void**)&ffn,  g_ffn);
    cudaGetSymbolAddress((void**)&ah,   g_ah);
    cudaGetSymbolAddress((void**)&al,   g_al);
    cudaGetSymbolAddress((void**)&wh,   g_wh);
    cudaGetSymbolAddress((void**)&wl,   g_wl);

    cudaFuncSetAttribute(hgemm, cudaFuncAttributeMaxDynamicSharedMemorySize, HG_SMEM);

    const int mb  = (M + 127) / 128;          // 57
    const int mmb = (Mm + 127) / 128;         // 625

    auto splitN = [](const float* x, __nv_bfloat16* h, __nv_bfloat16* l, int n) {
        int n4 = n / 4;
        split_bf16<<<(n4 + 255) / 256, 256>>>(x, h, l, n4);
    };

    // ---- memory value projection ----
    splitN(mem, ah, al, Mm * 256);
    splitN(vpw, wh, wl, 256 * 256);
    hgemm<<<dim3(2, mmb), 256, HG_SMEM>>>(ah, al, wh, wl, vpb, val, Mm, 256, 256, 0);

    // ---- self-attention ----
    splitN(tgt, ah, al, M * 256);
    splitN(inw, wh, wl, 768 * 256);
    hgemm<<<dim3(6, mb), 256, HG_SMEM>>>(ah, al, wh, wl, inb, qkv, M, 768, 256, 0);
    flash_attn<<<dim3((QLEN + 63) / 64, BHgrid), 256>>>(qkv, attn);
    splitN(attn, ah, al, M * 256);
    splitN(outw, wh, wl, 256 * 256);
    hgemm<<<dim3(2, mb), 256, HG_SMEM>>>(ah, al, wh, wl, outb, proj, M, 256, 256, 0);
    add_ln<<<M, 256>>>(proj, tgt, n1s, n1b, t1);

    // ---- deformable cross-attention ----
    deform_attn<<<M, 256>>>(t1, val, ofw, ofb, aww, awb, rfw, rfb, pH, pW, dsm);
    splitN(dsm, ah, al, M * 256);
    splitN(cow, wh, wl, 256 * 256);
    hgemm<<<dim3(2, mb), 256, HG_SMEM>>>(ah, al, wh, wl, cob, proj, M, 256, 256, 0);
    add_ln<<<M, 256>>>(proj, t1, n2s, n2b, t2);

    // ---- FFN ----
    splitN(t2, ah, al, M * 256);
    splitN(f1w, wh, wl, FFD * 256);
    hgemm<<<dim3(8, mb), 256, HG_SMEM>>>(ah, al, wh, wl, f1b, ffn, M, FFD, 256, 1);
    splitN(ffn, ah, al, M * FFD);
    splitN(f2w, wh, wl, 256 * FFD);
    hgemm<<<dim3(2, mb), 256, HG_SMEM>>>(ah, al, wh, wl, f2b, proj, M, 256, FFD, 0);
    add_ln<<<M, 256>>>(proj, t2, n3s, n3b, outp);
}

// round 8
// speedup vs baseline: 2.2207x; 1.2653x over previous
#include <cuda_runtime.h>
#include <cuda_bf16.h>
#include <math.h>
#include <stdint.h>

#define QLEN 900
#define DM   256
#define NH   8
#define HD   32
#define NPTS 4
#define FFD  1024

// ---------------- scratch (__device__ globals; allocation-free) ----------------
__device__ float g_qkv[5529600];      // [B*Q, 768]
__device__ float g_attn[1843200];     // [B*Q, 256]
__device__ float g_t1[1843200];
__device__ float g_val[20480000];     // [B*HW, 256]
__device__ float g_dsm[1843200];
__device__ float g_proj[1843200];
__device__ float g_t2[1843200];
__device__ float g_ffn[7372800];      // [B*Q, 1024]
// bf16 hi/lo split buffers
__device__ __nv_bfloat16 g_ah[20480000];
__device__ __nv_bfloat16 g_al[20480000];
__device__ __nv_bfloat16 g_wh[262144];
__device__ __nv_bfloat16 g_wl[262144];

// ============================================================================
// helpers
// ============================================================================
__device__ __forceinline__ uint32_t smem_u32(const void* p) {
    uint32_t a;
    asm("{ .reg .u64 t; cvta.to.shared.u64 t, %1; cvt.u32.u64 %0, t; }"
        : "=r"(a) : "l"(p));
    return a;
}
__device__ __forceinline__ uint32_t sw128(uint32_t off) {
    return off ^ ((off >> 3) & 0x70);
}
__device__ __forceinline__ uint32_t sw64(uint32_t off) {
    return off ^ ((off >> 3) & 0x30);
}
__device__ __forceinline__ void cvt_split(float f, uint16_t& h, uint16_t& l) {
    __nv_bfloat16 hb = __float2bfloat16_rn(f);
    float r = f - __bfloat162float(hb);
    __nv_bfloat16 lb = __float2bfloat16_rn(r);
    h = *reinterpret_cast<uint16_t*>(&hb);
    l = *reinterpret_cast<uint16_t*>(&lb);
}
__device__ __forceinline__ void ldmx4(uint32_t* r, uint32_t addr) {
    asm volatile("ldmatrix.sync.aligned.m8n8.x4.shared.b16 {%0,%1,%2,%3}, [%4];"
        : "=r"(r[0]), "=r"(r[1]), "=r"(r[2]), "=r"(r[3]) : "r"(addr));
}
__device__ __forceinline__ void mma16816(float* d, const uint32_t* a,
                                         uint32_t b0, uint32_t b1) {
    asm volatile(
        "mma.sync.aligned.m16n8k16.row.col.f32.bf16.bf16.f32 "
        "{%0,%1,%2,%3}, {%4,%5,%6,%7}, {%8,%9}, {%0,%1,%2,%3};"
        : "+f"(d[0]), "+f"(d[1]), "+f"(d[2]), "+f"(d[3])
        : "r"(a[0]), "r"(a[1]), "r"(a[2]), "r"(a[3]), "r"(b0), "r"(b1));
}

// ============================================================================
// split_bf16: fp32 -> (hi, lo) bf16, vectorized by 4.
// ============================================================================
__global__ __launch_bounds__(256) void split_bf16(
    const float* __restrict__ x, __nv_bfloat16* __restrict__ hi,
    __nv_bfloat16* __restrict__ lo, int n4)
{
    int i = blockIdx.x * 256 + threadIdx.x;
    if (i >= n4) return;
    float4 v = ((const float4*)x)[i];
    uint16_t h0,h1,h2,h3,l0,l1,l2,l3;
    cvt_split(v.x,h0,l0); cvt_split(v.y,h1,l1);
    cvt_split(v.z,h2,l2); cvt_split(v.w,h3,l3);
    ((uint2*)hi)[i] = make_uint2((uint32_t)h0 | ((uint32_t)h1 << 16),
                                 (uint32_t)h2 | ((uint32_t)h3 << 16));
    ((uint2*)lo)[i] = make_uint2((uint32_t)l0 | ((uint32_t)l1 << 16),
                                 (uint32_t)l2 | ((uint32_t)l3 << 16));
}

// ============================================================================
// hgemm: C[M,N] = act(A[M,K] @ W[N,K]^T + bias) with bf16x3 (Ah,Al)x(Wh,Wl).
// 128x128 tile, BK=64, 8 warps (64x32 each), mma.sync m16n8k16 bf16.
// ============================================================================
#define HG_SMEM 65536

__global__ __launch_bounds__(256) void hgemm(
    const __nv_bfloat16* __restrict__ Ah, const __nv_bfloat16* __restrict__ Al,
    const __nv_bfloat16* __restrict__ Wh, const __nv_bfloat16* __restrict__ Wl,
    const float* __restrict__ bias, float* __restrict__ C,
    int M, int N, int K, int relu)
{
    extern __shared__ char sm[];
    const uint32_t sb = smem_u32(sm);
    const int tid = threadIdx.x;
    const int wid = tid >> 5, lane = tid & 31;
    const int row0 = blockIdx.y * 128, col0 = blockIdx.x * 128;
    const int wm = (wid & 1) * 64;
    const int wn = (wid >> 1) * 32;

    float acc[4][4][4];
#pragma unroll
    for (int mt = 0; mt < 4; mt++)
#pragma unroll
        for (int nt = 0; nt < 4; nt++)
#pragma unroll
            for (int j = 0; j < 4; j++) acc[mt][nt][j] = 0.f;

    const uint32_t a_row = wm + (lane & 15);
    const uint32_t a_cb  = (lane >> 4) * 16;
    const uint32_t b_row = wn + (lane & 7) + ((lane >> 4) << 3);
    const uint32_t b_cb  = ((lane >> 3) & 1) * 16;

    for (int k0 = 0; k0 < K; k0 += 64) {
        __syncthreads();
#pragma unroll
        for (int it = 0; it < 4; it++) {
            int idx = it * 256 + tid;
            int r = idx >> 3;
            int c8 = (idx & 7) * 8;
            uint32_t so = sw128((uint32_t)(r * 128 + c8 * 2));
            uint4 z = make_uint4(0u, 0u, 0u, 0u);
            uint4 vah = z, valo = z;
            if (row0 + r < M) {
                vah  = *(const uint4*)(Ah + (size_t)(row0 + r) * K + k0 + c8);
                valo = *(const uint4*)(Al + (size_t)(row0 + r) * K + k0 + c8);
            }
            *(uint4*)(sm + so)         = vah;
            *(uint4*)(sm + 16384 + so) = valo;
            uint4 vbh = *(const uint4*)(Wh + (size_t)(col0 + r) * K + k0 + c8);
            uint4 vbl = *(const uint4*)(Wl + (size_t)(col0 + r) * K + k0 + c8);
            *(uint4*)(sm + 32768 + so) = vbh;
            *(uint4*)(sm + 49152 + so) = vbl;
        }
        __syncthreads();

#pragma unroll
        for (int ks = 0; ks < 64; ks += 16) {
            uint32_t ah[4][4], alr[4][4], bh[2][4], bl[2][4];
#pragma unroll
            for (int mt = 0; mt < 4; mt++) {
                uint32_t off = sw128((a_row + mt * 16) * 128 + ks * 2 + a_cb);
                ldmx4(ah[mt],  sb + off);
                ldmx4(alr[mt], sb + 16384 + off);
            }
#pragma unroll
            for (int bt = 0; bt < 2; bt++) {
                uint32_t off = sw128((b_row + bt * 16) * 128 + ks * 2 + b_cb);
                ldmx4(bh[bt], sb + 32768 + off);
                ldmx4(bl[bt], sb + 49152 + off);
            }
#pragma unroll
            for (int mt = 0; mt < 4; mt++) {
#pragma unroll
                for (int nt = 0; nt < 4; nt++) {
                    int bt = nt >> 1, bi = (nt & 1) * 2;
                    mma16816(acc[mt][nt], ah[mt],  bh[bt][bi], bh[bt][bi+1]);
                    mma16816(acc[mt][nt], ah[mt],  bl[bt][bi], bl[bt][bi+1]);
                    mma16816(acc[mt][nt], alr[mt], bh[bt][bi], bh[bt][bi+1]);
                }
            }
        }
    }

#pragma unroll
    for (int mt = 0; mt < 4; mt++) {
        int r0e = row0 + wm + mt * 16 + (lane >> 2);
#pragma unroll
        for (int nt = 0; nt < 4; nt++) {
            int c = col0 + wn + nt * 8 + (lane & 3) * 2;
            float b0 = bias[c], b1 = bias[c + 1];
            float2 v0 = make_float2(acc[mt][nt][0] + b0, acc[mt][nt][1] + b1);
            float2 v1 = make_float2(acc[mt][nt][2] + b0, acc[mt][nt][3] + b1);
            if (relu) {
                v0.x = fmaxf(v0.x, 0.f); v0.y = fmaxf(v0.y, 0.f);
                v1.x = fmaxf(v1.x, 0.f); v1.y = fmaxf(v1.y, 0.f);
            }
            if (r0e < M)     *(float2*)(C + (size_t)r0e * N + c) = v0;
            if (r0e + 8 < M) *(float2*)(C + (size_t)(r0e + 8) * N + c) = v1;
        }
    }
}

// ============================================================================
// flash_mma: fused flash self-attention via mma.sync bf16x3.
// Per (b,h): 64-query blocks (grid.x=15), 64-key tiles, 4 warps x 16 rows.
// Q/K in SW64 smem (64B rows), V transposed into SW128 smem (128B rows).
// ============================================================================
__global__ __launch_bounds__(128) void flash_mma(
    const float* __restrict__ qkv, float* __restrict__ O)
{
    __shared__ __align__(16) char sQh[4096], sQl[4096];
    __shared__ __align__(16) char sKh[4096], sKl[4096];
    __shared__ __align__(16) char sVh[4096], sVl[4096];

    const int bh = blockIdx.y;
    const int b = bh >> 3, h = bh & 7;
    const int q0 = blockIdx.x * 64;
    const int tid = threadIdx.x;
    const int w = tid >> 5, lane = tid & 31;
    const float scale = 0.17677669529663687f;  // 1/sqrt(32)
    const float* base = qkv + (size_t)b * QLEN * 768 + h * 32;

    const uint32_t uQh = smem_u32(sQh), uQl = smem_u32(sQl);
    const uint32_t uKh = smem_u32(sKh), uKl = smem_u32(sKl);
    const uint32_t uVh = smem_u32(sVh), uVl = smem_u32(sVl);

    // ---- load Q (64x32), fold scale, split, SW64 store ----
    {
        int r = tid >> 1, c0 = (tid & 1) * 16;
        bool v = (q0 + r) < QLEN;
        const float* p = base + (size_t)(q0 + r) * 768 + c0;
#pragma unroll
        for (int i = 0; i < 4; i++) {
            float4 x = v ? *(const float4*)(p + i * 4) : make_float4(0,0,0,0);
            x.x *= scale; x.y *= scale; x.z *= scale; x.w *= scale;
            uint16_t h0,h1,h2,h3,l0,l1,l2,l3;
            cvt_split(x.x,h0,l0); cvt_split(x.y,h1,l1);
            cvt_split(x.z,h2,l2); cvt_split(x.w,h3,l3);
            uint32_t off = sw64((uint32_t)(r * 64 + c0 * 2 + i * 8));
            *(uint2*)(sQh + off) = make_uint2((uint32_t)h0 | ((uint32_t)h1<<16),
                                              (uint32_t)h2 | ((uint32_t)h3<<16));
            *(uint2*)(sQl + off) = make_uint2((uint32_t)l0 | ((uint32_t)l1<<16),
                                              (uint32_t)l2 | ((uint32_t)l3<<16));
        }
    }
    __syncthreads();

    // ---- Q A-fragments (fixed for all key tiles) ----
    uint32_t qa[2][2][4];   // [hi/lo][kstep][frag]
#pragma unroll
    for (int ks = 0; ks < 2; ks++) {
        uint32_t off = sw64((uint32_t)((w*16 + (lane & 15)) * 64
                            + ks * 32 + (lane >> 4) * 16));
        ldmx4(qa[0][ks], uQh + off);
        ldmx4(qa[1][ks], uQl + off);
    }

    float m0 = -1e30f, m1 = -1e30f, l0s = 0.f, l1s = 0.f;
    float o[4][4];
#pragma unroll
    for (int i = 0; i < 4; i++)
#pragma unroll
        for (int j = 0; j < 4; j++) o[i][j] = 0.f;

    for (int kt = 0; kt < 15; kt++) {
        const int k0 = kt * 64;
        __syncthreads();   // previous-iteration smem reads done
        // ---- K tile (64x32), split, SW64 ----
        {
            int r = tid >> 1, c0 = (tid & 1) * 16;
            bool v = (k0 + r) < QLEN;
            const float* p = base + 256 + (size_t)(k0 + r) * 768 + c0;
#pragma unroll
            for (int i = 0; i < 4; i++) {
                float4 x = v ? *(const float4*)(p + i * 4) : make_float4(0,0,0,0);
                uint16_t h0,h1,h2,h3,l0,l1,l2,l3;
                cvt_split(x.x,h0,l0); cvt_split(x.y,h1,l1);
                cvt_split(x.z,h2,l2); cvt_split(x.w,h3,l3);
                uint32_t off = sw64((uint32_t)(r * 64 + c0 * 2 + i * 8));
                *(uint2*)(sKh + off) = make_uint2((uint32_t)h0 | ((uint32_t)h1<<16),
                                                  (uint32_t)h2 | ((uint32_t)h3<<16));
                *(uint2*)(sKl + off) = make_uint2((uint32_t)l0 | ((uint32_t)l1<<16),
                                                  (uint32_t)l2 | ((uint32_t)l3<<16));
            }
        }
        // ---- V tile transposed (Vt[32][64]), split, SW128 ----
        {
            int col = tid >> 1, d0 = (tid & 1) * 16;
            bool v = (k0 + col) < QLEN;
            const float* p = base + 512 + (size_t)(k0 + col) * 768 + d0;
#pragma unroll
            for (int i = 0; i < 4; i++) {
                float4 x = v ? *(const float4*)(p + i * 4) : make_float4(0,0,0,0);
                float xv[4] = {x.x, x.y, x.z, x.w};
#pragma unroll
                for (int e = 0; e < 4; e++) {
                    int d = d0 + i * 4 + e;
                    uint16_t hb, lb;
                    cvt_split(xv[e], hb, lb);
                    uint32_t off = sw128((uint32_t)(d * 128 + col * 2));
                    *(uint16_t*)(sVh + off) = hb;
                    *(uint16_t*)(sVl + off) = lb;
                }
            }
        }
        __syncthreads();

        // ---- S = Q K^T (16 rows x 64 keys per warp), bf16x3 ----
        float s[8][4];
#pragma unroll
        for (int i = 0; i < 8; i++)
#pragma unroll
            for (int j = 0; j < 4; j++) s[i][j] = 0.f;
#pragma unroll
        for (int ks = 0; ks < 2; ks++) {
#pragma unroll
            for (int jj = 0; jj < 4; jj++) {
                uint32_t off = sw64((uint32_t)((jj*16 + (lane & 7)
                               + ((lane >> 4) << 3)) * 64
                               + ((lane >> 3) & 1) * 16 + ks * 32));
                uint32_t bhh[4], bll[4];
                ldmx4(bhh, uKh + off);
                ldmx4(bll, uKl + off);
                mma16816(s[2*jj],   qa[0][ks], bhh[0], bhh[1]);
                mma16816(s[2*jj],   qa[0][ks], bll[0], bll[1]);
                mma16816(s[2*jj],   qa[1][ks], bhh[0], bhh[1]);
                mma16816(s[2*jj+1], qa[0][ks], bhh[2], bhh[3]);
                mma16816(s[2*jj+1], qa[0][ks], bll[2], bll[3]);
                mma16816(s[2*jj+1], qa[1][ks], bhh[2], bhh[3]);
            }
        }

        // ---- mask invalid keys ----
        const int colb = k0 + (lane & 3) * 2;
#pragma unroll
        for (int jn = 0; jn < 8; jn++) {
            int c0 = colb + jn * 8;
            if (c0 >= QLEN)     { s[jn][0] = -1e30f; s[jn][2] = -1e30f; }
            if (c0 + 1 >= QLEN) { s[jn][1] = -1e30f; s[jn][3] = -1e30f; }
        }

        // ---- online softmax (rows = quad groups: shfl over lanes 1,2) ----
        float mx0 = -1e30f, mx1 = -1e30f;
#pragma unroll
        for (int jn = 0; jn < 8; jn++) {
            mx0 = fmaxf(mx0, fmaxf(s[jn][0], s[jn][1]));
            mx1 = fmaxf(mx1, fmaxf(s[jn][2], s[jn][3]));
        }
        mx0 = fmaxf(mx0, __shfl_xor_sync(0xffffffffu, mx0, 1));
        mx0 = fmaxf(mx0, __shfl_xor_sync(0xffffffffu, mx0, 2));
        mx1 = fmaxf(mx1, __shfl_xor_sync(0xffffffffu, mx1, 1));
        mx1 = fmaxf(mx1, __shfl_xor_sync(0xffffffffu, mx1, 2));
        float mn0 = fmaxf(m0, mx0), mn1 = fmaxf(m1, mx1);
        float corr0 = __expf(m0 - mn0), corr1 = __expf(m1 - mn1);
        m0 = mn0; m1 = mn1;
        float rs0 = 0.f, rs1 = 0.f;
#pragma unroll
        for (int jn = 0; jn < 8; jn++) {
            s[jn][0] = __expf(s[jn][0] - mn0);
            s[jn][1] = __expf(s[jn][1] - mn0);
            s[jn][2] = __expf(s[jn][2] - mn1);
            s[jn][3] = __expf(s[jn][3] - mn1);
            rs0 += s[jn][0] + s[jn][1];
            rs1 += s[jn][2] + s[jn][3];
        }
        rs0 += __shfl_xor_sync(0xffffffffu, rs0, 1);
        rs0 += __shfl_xor_sync(0xffffffffu, rs0, 2);
        rs1 += __shfl_xor_sync(0xffffffffu, rs1, 1);
        rs1 += __shfl_xor_sync(0xffffffffu, rs1, 2);
        l0s = l0s * corr0 + rs0;
        l1s = l1s * corr1 + rs1;
#pragma unroll
        for (int jn = 0; jn < 4; jn++) {
            o[jn][0] *= corr0; o[jn][1] *= corr0;
            o[jn][2] *= corr1; o[jn][3] *= corr1;
        }

        // ---- O += P @ V : pack P frags from registers, bf16x3 ----
#pragma unroll
        for (int ks = 0; ks < 4; ks++) {
            uint32_t pah[4], pal[4];
            {
                const float* t0 = s[2*ks];
                const float* t1 = s[2*ks+1];
                uint16_t h0,h1,l0,l1;
                cvt_split(t0[0],h0,l0); cvt_split(t0[1],h1,l1);
                pah[0] = (uint32_t)h0 | ((uint32_t)h1<<16);
                pal[0] = (uint32_t)l0 | ((uint32_t)l1<<16);
                cvt_split(t0[2],h0,l0); cvt_split(t0[3],h1,l1);
                pah[1] = (uint32_t)h0 | ((uint32_t)h1<<16);
                pal[1] = (uint32_t)l0 | ((uint32_t)l1<<16);
                cvt_split(t1[0],h0,l0); cvt_split(t1[1],h1,l1);
                pah[2] = (uint32_t)h0 | ((uint32_t)h1<<16);
                pal[2] = (uint32_t)l0 | ((uint32_t)l1<<16);
                cvt_split(t1[2],h0,l0); cvt_split(t1[3],h1,l1);
                pah[3] = (uint32_t)h0 | ((uint32_t)h1<<16);
                pal[3] = (uint32_t)l0 | ((uint32_t)l1<<16);
            }
#pragma unroll
            for (int jj = 0; jj < 2; jj++) {
                uint32_t off = sw128((uint32_t)((jj*16 + (lane & 7)
                               + ((lane >> 4) << 3)) * 128
                               + ((lane >> 3) & 1) * 16 + ks * 32));
                uint32_t vhh[4], vll[4];
                ldmx4(vhh, uVh + off);
                ldmx4(vll, uVl + off);
                mma16816(o[2*jj],   pah, vhh[0], vhh[1]);
                mma16816(o[2*jj],   pah, vll[0], vll[1]);
                mma16816(o[2*jj],   pal, vhh[0], vhh[1]);
                mma16816(o[2*jj+1], pah, vhh[2], vhh[3]);
                mma16816(o[2*jj+1], pah, vll[2], vll[3]);
                mma16816(o[2*jj+1], pal, vhh[2], vhh[3]);
            }
        }
    }

    // ---- finalize ----
    {
        int r0 = q0 + w * 16 + (lane >> 2);
        float i0 = 1.f / l0s, i1 = 1.f / l1s;
#pragma unroll
        for (int jn = 0; jn < 4; jn++) {
            int c = h * 32 + jn * 8 + (lane & 3) * 2;
            if (r0 < QLEN)
                *(float2*)(O + (size_t)(b * QLEN + r0) * 256 + c) =
                    make_float2(o[jn][0] * i0, o[jn][1] * i0);
            if (r0 + 8 < QLEN)
                *(float2*)(O + (size_t)(b * QLEN + r0 + 8) * 256 + c) =
                    make_float2(o[jn][2] * i1, o[jn][3] * i1);
        }
    }
}

// ---------------------------------------------------------------------------
// out = LayerNorm(a + b) over D=256. One block (256 thr) per row.
// ---------------------------------------------------------------------------
__global__ __launch_bounds__(256) void add_ln(
    const float* __restrict__ a, const float* __restrict__ b,
    const float* __restrict__ gam, const float* __restrict__ bet,
    float* __restrict__ out)
{
    __shared__ float red[8];
    __shared__ float s_mu, s_rstd;
    const int tid = threadIdx.x;
    const int lane = tid & 31, w = tid >> 5;
    size_t idx = (size_t)blockIdx.x * 256 + tid;
    float v = a[idx] + b[idx];

    float s = v;
#pragma unroll
    for (int o = 16; o; o >>= 1) s += __shfl_xor_sync(0xffffffffu, s, o);
    if (lane == 0) red[w] = s;
    __syncthreads();
    if (tid == 0) {
        float t = 0.f;
        for (int i = 0; i < 8; i++) t += red[i];
        s_mu = t * (1.f / 256.f);
    }
    __syncthreads();
    float d = v - s_mu;
    float sq = d * d;
    __syncthreads();
#pragma unroll
    for (int o = 16; o; o >>= 1) sq += __shfl_xor_sync(0xffffffffu, sq, o);
    if (lane == 0) red[w] = sq;
    __syncthreads();
    if (tid == 0) {
        float t = 0.f;
        for (int i = 0; i < 8; i++) t += red[i];
        s_rstd = rsqrtf(t * (1.f / 256.f) + 1e-5f);
    }
    __syncthreads();
    out[idx] = d * s_rstd * gam[tid] + bet[tid];
}

// ---------------------------------------------------------------------------
// Fused deformable attention sampling. One block per (b,q).
// ---------------------------------------------------------------------------
__global__ __launch_bounds__(256) void deform_attn(
    const float* __restrict__ t, const float* __restrict__ val,
    const float* __restrict__ offs_w, const float* __restrict__ offs_b,
    const float* __restrict__ attw_w, const float* __restrict__ attw_b,
    const float* __restrict__ ref_w, const float* __restrict__ ref_b,
    const int* __restrict__ pH, const int* __restrict__ pW,
    float* __restrict__ out)
{
    __shared__ float trow[256];
    __shared__ float sref[2];
    __shared__ float soffs[64];
    __shared__ float sattw[32];
    const int bq = blockIdx.x;
    const int b = bq / QLEN;
    const int tid = threadIdx.x;
    const int warp = tid >> 5, lane = tid & 31;

    trow[tid] = t[(size_t)bq * 256 + tid];
    __syncthreads();

    for (int o = warp; o < 98; o += 8) {
        const float* wr;
        float bia;
        if (o < 2)       { wr = ref_w  + o * 256;        bia = ref_b[o]; }
        else if (o < 66) { wr = offs_w + (o - 2) * 256;  bia = offs_b[o - 2]; }
        else             { wr = attw_w + (o - 66) * 256; bia = attw_b[o - 66]; }
        float p = 0.f;
#pragma unroll
        for (int i = 0; i < 8; i++)
            p += trow[lane + i * 32] * wr[lane + i * 32];
#pragma unroll
        for (int oo = 16; oo; oo >>= 1) p += __shfl_xor_sync(0xffffffffu, p, oo);
        if (lane == 0) {
            float r = p + bia;
            if (o < 2)       sref[o] = 1.f / (1.f + __expf(-r));
            else if (o < 66) soffs[o - 2] = r;
            else             sattw[o - 66] = r;
        }
    }
    __syncthreads();

    if (tid < 8) {
        float m = -3.4e38f;
#pragma unroll
        for (int p = 0; p < 4; p++) m = fmaxf(m, sattw[tid * 4 + p]);
        float e[4], s = 0.f;
#pragma unroll
        for (int p = 0; p < 4; p++) { e[p] = __expf(sattw[tid * 4 + p] - m); s += e[p]; }
        float inv = 1.f / s;
#pragma unroll
        for (int p = 0; p < 4; p++) sattw[tid * 4 + p] = e[p] * inv;
    }
    __syncthreads();

    const int H = *pH, W = *pW;
    const float fH = (float)H, fW = (float)W;
    const int h = tid >> 5, d = tid & 31;
    const float refx = sref[0], refy = sref[1];
    const float* vbase = val + (size_t)b * H * W * 256 + h * 32 + d;
    float acc = 0.f;
#pragma unroll
    for (int p = 0; p < NPTS; p++) {
        float locx = refx + soffs[h * 8 + 2 * p]     / fW;
        float locy = refy + soffs[h * 8 + 2 * p + 1] / fH;
        float xx = locx * fW - 0.5f;
        float yy = locy * fH - 0.5f;
        float x0f = floorf(xx), y0f = floorf(yy);
        int x0 = (int)x0f, y0 = (int)y0f;
        float lx = xx - x0f, ly = yy - y0f;
        float w00 = (1.f - lx) * (1.f - ly);
        float w10 = lx * (1.f - ly);
        float w01 = (1.f - lx) * ly;
        float w11 = lx * ly;
        float s = 0.f;
        bool vx0 = (x0 >= 0) & (x0 < W);
        bool vx1 = (x0 + 1 >= 0) & (x0 + 1 < W);
        bool vy0 = (y0 >= 0) & (y0 < H);
        bool vy1 = (y0 + 1 >= 0) & (y0 + 1 < H);
        if (vx0 & vy0) s += w00 * vbase[((size_t)y0 * W + x0) * 256];
        if (vx1 & vy0) s += w10 * vbase[((size_t)y0 * W + x0 + 1) * 256];
        if (vx0 & vy1) s += w01 * vbase[((size_t)(y0 + 1) * W + x0) * 256];
        if (vx1 & vy1) s += w11 * vbase[((size_t)(y0 + 1) * W + x0 + 1) * 256];
        acc += sattw[h * 4 + p] * s;
    }
    out[(size_t)bq * 256 + tid] = acc;
}

// ---------------------------------------------------------------------------
extern "C" void kernel_launch(void* const* d_in, const int* in_sizes, int n_in,
                              void* d_out, int out_size)
{
    const float* tgt  = (const float*)d_in[0];
    const float* mem  = (const float*)d_in[1];
    const int*   pH   = (const int*)d_in[2];
    const int*   pW   = (const int*)d_in[3];
    const float* inw  = (const float*)d_in[4];
    const float* inb  = (const float*)d_in[5];
    const float* outw = (const float*)d_in[6];
    const float* outb = (const float*)d_in[7];
    const float* n1s  = (const float*)d_in[8];
    const float* n1b  = (const float*)d_in[9];
    const float* n2s  = (const float*)d_in[10];
    const float* n2b  = (const float*)d_in[11];
    const float* n3s  = (const float*)d_in[12];
    const float* n3b  = (const float*)d_in[13];
    const float* vpw  = (const float*)d_in[14];
    const float* vpb  = (const float*)d_in[15];
    const float* ofw  = (const float*)d_in[16];
    const float* ofb  = (const float*)d_in[17];
    const float* aww  = (const float*)d_in[18];
    const float* awb  = (const float*)d_in[19];
    const float* rfw  = (const float*)d_in[20];
    const float* rfb  = (const float*)d_in[21];
    const float* cow  = (const float*)d_in[22];
    const float* cob  = (const float*)d_in[23];
    const float* f1w  = (const float*)d_in[24];
    const float* f1b  = (const float*)d_in[25];
    const float* f2w  = (const float*)d_in[26];
    const float* f2b  = (const float*)d_in[27];
    float* outp = (float*)d_out;

    const int M  = in_sizes[0] / DM;          // B*Q = 7200
    const int Mm = in_sizes[1] / DM;          // B*HW = 80000
    const int B  = M / QLEN;                  // 8
    const int BHgrid = B * NH;                // 64

    float *qkv, *attn, *t1, *val, *dsm, *proj, *t2, *ffn;
    __nv_bfloat16 *ah, *al, *wh, *wl;
    cudaGetSymbolAddress((void**)&qkv,  g_qkv);
    cudaGetSymbolAddress((void**)&attn, g_attn);
    cudaGetSymbolAddress((void**)&t1,   g_t1);
    cudaGetSymbolAddress((void**)&val,  g_val);
    cudaGetSymbolAddress((void**)&dsm,  g_dsm);
    cudaGetSymbolAddress((void**)&proj, g_proj);
    cudaGetSymbolAddress((void**)&t2,   g_t2);
    cudaGetSymbolAddress((void**)&ffn,  g_ffn);
    cudaGetSymbolAddress((void**)&ah,   g_ah);
    cudaGetSymbolAddress((void**)&al,   g_al);
    cudaGetSymbolAddress((void**)&wh,   g_wh);
    cudaGetSymbolAddress((void**)&wl,   g_wl);

    cudaFuncSetAttribute(hgemm, cudaFuncAttributeMaxDynamicSharedMemorySize, HG_SMEM);

    const int mb  = (M + 127) / 128;          // 57
    const int mmb = (Mm + 127) / 128;         // 625

    auto splitN = [](const float* x, __nv_bfloat16* h, __nv_bfloat16* l, int n) {
        int n4 = n / 4;
        split_bf16<<<(n4 + 255) / 256, 256>>>(x, h, l, n4);
    };

    // ---- memory value projection ----
    splitN(mem, ah, al, Mm * 256);
    splitN(vpw, wh, wl, 256 * 256);
    hgemm<<<dim3(2, mmb), 256, HG_SMEM>>>(ah, al, wh, wl, vpb, val, Mm, 256, 256, 0);

    // ---- self-attention ----
    splitN(tgt, ah, al, M * 256);
    splitN(inw, wh, wl, 768 * 256);
    hgemm<<<dim3(6, mb), 256, HG_SMEM>>>(ah, al, wh, wl, inb, qkv, M, 768, 256, 0);
    flash_mma<<<dim3((QLEN + 63) / 64, BHgrid), 128>>>(qkv, attn);
    splitN(attn, ah, al, M * 256);
    splitN(outw, wh, wl, 256 * 256);
    hgemm<<<dim3(2, mb), 256, HG_SMEM>>>(ah, al, wh, wl, outb, proj, M, 256, 256, 0);
    add_ln<<<M, 256>>>(proj, tgt, n1s, n1b, t1);

    // ---- deformable cross-attention ----
    deform_attn<<<M, 256>>>(t1, val, ofw, ofb, aww, awb, rfw, rfb, pH, pW, dsm);
    splitN(dsm, ah, al, M * 256);
    splitN(cow, wh, wl, 256 * 256);
    hgemm<<<dim3(2, mb), 256, HG_SMEM>>>(ah, al, wh, wl, cob, proj, M, 256, 256, 0);
    add_ln<<<M, 256>>>(proj, t1, n2s, n2b, t2);

    // ---- FFN ----
    splitN(t2, ah, al, M * 256);
    splitN(f1w, wh, wl, FFD * 256);
    hgemm<<<dim3(8, mb), 256, HG_SMEM>>>(ah, al, wh, wl, f1b, ffn, M, FFD, 256, 1);
    splitN(ffn, ah, al, M * FFD);
    splitN(f2w, wh, wl, 256 * FFD);
    hgemm<<<dim3(2, mb), 256, HG_SMEM>>>(ah, al, wh, wl, f2b, proj, M, 256, FFD, 0);
    add_ln<<<M, 256>>>(proj, t2, n3s, n3b, outp);
}

// round 9
// speedup vs baseline: 2.5985x; 1.1701x over previous
#include <cuda_runtime.h>
#include <cuda_bf16.h>
#include <math.h>
#include <stdint.h>

#define QLEN 900
#define DM   256
#define NH   8
#define HD   32
#define NPTS 4
#define FFD  1024

// ---------------- scratch (__device__ globals; allocation-free) ----------------
__device__ float g_qkv[5529600];      // [B*Q, 768]
__device__ float g_t1[1843200];
__device__ float g_val[20480000];     // [B*HW, 256]
__device__ float g_proj[1843200];
__device__ float g_t2[1843200];
// bf16 hi/lo split buffers
__device__ __nv_bfloat16 g_ah[20480000];
__device__ __nv_bfloat16 g_al[20480000];
__device__ __nv_bfloat16 g_wh[262144];
__device__ __nv_bfloat16 g_wl[262144];
__device__ __nv_bfloat16 g_fh[7372800];   // ffn intermediate hi
__device__ __nv_bfloat16 g_fl[7372800];   // ffn intermediate lo

// ============================================================================
// helpers
// ============================================================================
__device__ __forceinline__ uint32_t smem_u32(const void* p) {
    uint32_t a;
    asm("{ .reg .u64 t; cvta.to.shared.u64 t, %1; cvt.u32.u64 %0, t; }"
        : "=r"(a) : "l"(p));
    return a;
}
__device__ __forceinline__ uint32_t sw128(uint32_t off) {
    return off ^ ((off >> 3) & 0x70);
}
__device__ __forceinline__ uint32_t sw64(uint32_t off) {
    return off ^ ((off >> 3) & 0x30);
}
__device__ __forceinline__ void cvt_split(float f, uint16_t& h, uint16_t& l) {
    __nv_bfloat16 hb = __float2bfloat16_rn(f);
    float r = f - __bfloat162float(hb);
    __nv_bfloat16 lb = __float2bfloat16_rn(r);
    h = *reinterpret_cast<uint16_t*>(&hb);
    l = *reinterpret_cast<uint16_t*>(&lb);
}
__device__ __forceinline__ void ldmx4(uint32_t* r, uint32_t addr) {
    asm volatile("ldmatrix.sync.aligned.m8n8.x4.shared.b16 {%0,%1,%2,%3}, [%4];"
        : "=r"(r[0]), "=r"(r[1]), "=r"(r[2]), "=r"(r[3]) : "r"(addr));
}
__device__ __forceinline__ void mma16816(float* d, const uint32_t* a,
                                         uint32_t b0, uint32_t b1) {
    asm volatile(
        "mma.sync.aligned.m16n8k16.row.col.f32.bf16.bf16.f32 "
        "{%0,%1,%2,%3}, {%4,%5,%6,%7}, {%8,%9}, {%0,%1,%2,%3};"
        : "+f"(d[0]), "+f"(d[1]), "+f"(d[2]), "+f"(d[3])
        : "r"(a[0]), "r"(a[1]), "r"(a[2]), "r"(a[3]), "r"(b0), "r"(b1));
}
__device__ __forceinline__ void cp_async16(uint32_t dst, const void* src, uint32_t sz) {
    asm volatile("cp.async.cg.shared.global [%0], [%1], 16, %2;"
        :: "r"(dst), "l"(src), "r"(sz));
}
#define CP_COMMIT() asm volatile("cp.async.commit_group;" ::: "memory")
#define CP_WAIT(n)  asm volatile("cp.async.wait_group %0;" :: "n"(n) : "memory")

// ============================================================================
// split_bf16: fp32 -> (hi, lo) bf16; 4 float4 per thread for MLP.
// ============================================================================
__global__ __launch_bounds__(256) void split_bf16(
    const float* __restrict__ x, __nv_bfloat16* __restrict__ hi,
    __nv_bfloat16* __restrict__ lo, int n4)
{
    int i0 = blockIdx.x * 1024 + threadIdx.x;
#pragma unroll
    for (int it = 0; it < 4; it++) {
        int i = i0 + it * 256;
        if (i >= n4) return;
        float4 v = ((const float4*)x)[i];
        uint16_t h0,h1,h2,h3,l0,l1,l2,l3;
        cvt_split(v.x,h0,l0); cvt_split(v.y,h1,l1);
        cvt_split(v.z,h2,l2); cvt_split(v.w,h3,l3);
        ((uint2*)hi)[i] = make_uint2((uint32_t)h0 | ((uint32_t)h1 << 16),
                                     (uint32_t)h2 | ((uint32_t)h3 << 16));
        ((uint2*)lo)[i] = make_uint2((uint32_t)l0 | ((uint32_t)l1 << 16),
                                     (uint32_t)l2 | ((uint32_t)l3 << 16));
    }
}

// ============================================================================
// hgemm: C = act(A @ W^T + bias), bf16x3, cp.async 2-stage pipeline.
// 128x128 tile, BK=64, 8 warps. mode bit0=relu, bit1=split-output (Ch/Cl).
// ============================================================================
#define HG_SMEM (2 * 65536)

__global__ __launch_bounds__(256) void hgemm(
    const __nv_bfloat16* __restrict__ Ah, const __nv_bfloat16* __restrict__ Al,
    const __nv_bfloat16* __restrict__ Wh, const __nv_bfloat16* __restrict__ Wl,
    const float* __restrict__ bias, float* __restrict__ C,
    __nv_bfloat16* __restrict__ Ch, __nv_bfloat16* __restrict__ Cl,
    int M, int N, int K, int mode)
{
    extern __shared__ char sm[];
    const uint32_t sb = smem_u32(sm);
    const int tid = threadIdx.x;
    const int wid = tid >> 5, lane = tid & 31;
    const int row0 = blockIdx.y * 128, col0 = blockIdx.x * 128;
    const int wm = (wid & 1) * 64;
    const int wn = (wid >> 1) * 32;

    float acc[4][4][4];
#pragma unroll
    for (int mt = 0; mt < 4; mt++)
#pragma unroll
        for (int nt = 0; nt < 4; nt++)
#pragma unroll
            for (int j = 0; j < 4; j++) acc[mt][nt][j] = 0.f;

    const uint32_t a_row = wm + (lane & 15);
    const uint32_t a_cb  = (lane >> 4) * 16;
    const uint32_t b_row = wn + (lane & 7) + ((lane >> 4) << 3);
    const uint32_t b_cb  = ((lane >> 3) & 1) * 16;
    const int nc = K >> 6;

    // per-thread load coordinates (4 iterations x 16B x 4 regions)
    const int lr  = tid >> 3;            // rows lr, lr+32, lr+64, lr+96
    const int lc8 = (tid & 7) * 8;

    // prologue: chunk 0 -> stage 0
#pragma unroll 1
    for (int c = 0; c <= 0; c++) {
#pragma unroll
        for (int it = 0; it < 4; it++) {
            int r = lr + it * 32;
            uint32_t so = sw128((uint32_t)(r * 128 + lc8 * 2));
            int ra = row0 + r < M ? row0 + r : M - 1;
            uint32_t asz = (row0 + r < M) ? 16u : 0u;
            cp_async16(sb + so,         Ah + (size_t)ra * K + lc8, asz);
            cp_async16(sb + 16384 + so, Al + (size_t)ra * K + lc8, asz);
            cp_async16(sb + 32768 + so, Wh + (size_t)(col0 + r) * K + lc8, 16u);
            cp_async16(sb + 49152 + so, Wl + (size_t)(col0 + r) * K + lc8, 16u);
        }
        CP_COMMIT();
    }

    for (int c = 0; c < nc; c++) {
        const uint32_t stb = sb + (uint32_t)(c & 1) * 65536;
        if (c + 1 < nc) {
            const uint32_t nstb = sb + (uint32_t)((c + 1) & 1) * 65536;
            const int k0 = (c + 1) << 6;
#pragma unroll
            for (int it = 0; it < 4; it++) {
                int r = lr + it * 32;
                uint32_t so = sw128((uint32_t)(r * 128 + lc8 * 2));
                int ra = row0 + r < M ? row0 + r : M - 1;
                uint32_t asz = (row0 + r < M) ? 16u : 0u;
                cp_async16(nstb + so,         Ah + (size_t)ra * K + k0 + lc8, asz);
                cp_async16(nstb + 16384 + so, Al + (size_t)ra * K + k0 + lc8, asz);
                cp_async16(nstb + 32768 + so, Wh + (size_t)(col0 + r) * K + k0 + lc8, 16u);
                cp_async16(nstb + 49152 + so, Wl + (size_t)(col0 + r) * K + k0 + lc8, 16u);
            }
            CP_COMMIT();
            CP_WAIT(1);
        } else {
            CP_WAIT(0);
        }
        __syncthreads();

#pragma unroll
        for (int ks = 0; ks < 64; ks += 16) {
            uint32_t ah[4][4], alr[4][4], bh[2][4], bl[2][4];
#pragma unroll
            for (int mt = 0; mt < 4; mt++) {
                uint32_t off = sw128((a_row + mt * 16) * 128 + ks * 2 + a_cb);
                ldmx4(ah[mt],  stb + off);
                ldmx4(alr[mt], stb + 16384 + off);
            }
#pragma unroll
            for (int bt = 0; bt < 2; bt++) {
                uint32_t off = sw128((b_row + bt * 16) * 128 + ks * 2 + b_cb);
                ldmx4(bh[bt], stb + 32768 + off);
                ldmx4(bl[bt], stb + 49152 + off);
            }
#pragma unroll
            for (int mt = 0; mt < 4; mt++) {
#pragma unroll
                for (int nt = 0; nt < 4; nt++) {
                    int bt = nt >> 1, bi = (nt & 1) * 2;
                    mma16816(acc[mt][nt], ah[mt],  bh[bt][bi], bh[bt][bi+1]);
                    mma16816(acc[mt][nt], ah[mt],  bl[bt][bi], bl[bt][bi+1]);
                    mma16816(acc[mt][nt], alr[mt], bh[bt][bi], bh[bt][bi+1]);
                }
            }
        }
        __syncthreads();
    }

    const bool relu = mode & 1;
    const bool split = mode & 2;
#pragma unroll
    for (int mt = 0; mt < 4; mt++) {
        int r0e = row0 + wm + mt * 16 + (lane >> 2);
#pragma unroll
        for (int nt = 0; nt < 4; nt++) {
            int c = col0 + wn + nt * 8 + (lane & 3) * 2;
            float b0 = bias[c], b1 = bias[c + 1];
            float2 v0 = make_float2(acc[mt][nt][0] + b0, acc[mt][nt][1] + b1);
            float2 v1 = make_float2(acc[mt][nt][2] + b0, acc[mt][nt][3] + b1);
            if (relu) {
                v0.x = fmaxf(v0.x, 0.f); v0.y = fmaxf(v0.y, 0.f);
                v1.x = fmaxf(v1.x, 0.f); v1.y = fmaxf(v1.y, 0.f);
            }
            if (!split) {
                if (r0e < M)     *(float2*)(C + (size_t)r0e * N + c) = v0;
                if (r0e + 8 < M) *(float2*)(C + (size_t)(r0e + 8) * N + c) = v1;
            } else {
                uint16_t h0,h1,l0,l1;
                if (r0e < M) {
                    cvt_split(v0.x, h0, l0); cvt_split(v0.y, h1, l1);
                    *(uint32_t*)(Ch + (size_t)r0e * N + c) =
                        (uint32_t)h0 | ((uint32_t)h1 << 16);
                    *(uint32_t*)(Cl + (size_t)r0e * N + c) =
                        (uint32_t)l0 | ((uint32_t)l1 << 16);
                }
                if (r0e + 8 < M) {
                    cvt_split(v1.x, h0, l0); cvt_split(v1.y, h1, l1);
                    *(uint32_t*)(Ch + (size_t)(r0e + 8) * N + c) =
                        (uint32_t)h0 | ((uint32_t)h1 << 16);
                    *(uint32_t*)(Cl + (size_t)(r0e + 8) * N + c) =
                        (uint32_t)l0 | ((uint32_t)l1 << 16);
                }
            }
        }
    }
}

// ============================================================================
// flash_mma: fused flash self-attention via mma.sync bf16x3.
// Output written as split bf16 hi/lo (feeds out-proj GEMM directly).
// ============================================================================
__global__ __launch_bounds__(128) void flash_mma(
    const float* __restrict__ qkv,
    __nv_bfloat16* __restrict__ Oh, __nv_bfloat16* __restrict__ Ol)
{
    __shared__ __align__(16) char sQh[4096], sQl[4096];
    __shared__ __align__(16) char sKh[4096], sKl[4096];
    __shared__ __align__(16) char sVh[4096], sVl[4096];

    const int bh = blockIdx.y;
    const int b = bh >> 3, h = bh & 7;
    const int q0 = blockIdx.x * 64;
    const int tid = threadIdx.x;
    const int w = tid >> 5, lane = tid & 31;
    const float scale = 0.17677669529663687f;
    const float* base = qkv + (size_t)b * QLEN * 768 + h * 32;

    const uint32_t uQh = smem_u32(sQh), uQl = smem_u32(sQl);
    const uint32_t uKh = smem_u32(sKh), uKl = smem_u32(sKl);
    const uint32_t uVh = smem_u32(sVh), uVl = smem_u32(sVl);

    {
        int r = tid >> 1, c0 = (tid & 1) * 16;
        bool v = (q0 + r) < QLEN;
        const float* p = base + (size_t)(q0 + r) * 768 + c0;
#pragma unroll
        for (int i = 0; i < 4; i++) {
            float4 x = v ? *(const float4*)(p + i * 4) : make_float4(0,0,0,0);
            x.x *= scale; x.y *= scale; x.z *= scale; x.w *= scale;
            uint16_t h0,h1,h2,h3,l0,l1,l2,l3;
            cvt_split(x.x,h0,l0); cvt_split(x.y,h1,l1);
            cvt_split(x.z,h2,l2); cvt_split(x.w,h3,l3);
            uint32_t off = sw64((uint32_t)(r * 64 + c0 * 2 + i * 8));
            *(uint2*)(sQh + off) = make_uint2((uint32_t)h0 | ((uint32_t)h1<<16),
                                              (uint32_t)h2 | ((uint32_t)h3<<16));
            *(uint2*)(sQl + off) = make_uint2((uint32_t)l0 | ((uint32_t)l1<<16),
                                              (uint32_t)l2 | ((uint32_t)l3<<16));
        }
    }
    __syncthreads();

    uint32_t qa[2][2][4];
#pragma unroll
    for (int ks = 0; ks < 2; ks++) {
        uint32_t off = sw64((uint32_t)((w*16 + (lane & 15)) * 64
                            + ks * 32 + (lane >> 4) * 16));
        ldmx4(qa[0][ks], uQh + off);
        ldmx4(qa[1][ks], uQl + off);
    }

    float m0 = -1e30f, m1 = -1e30f, l0s = 0.f, l1s = 0.f;
    float o[4][4];
#pragma unroll
    for (int i = 0; i < 4; i++)
#pragma unroll
        for (int j = 0; j < 4; j++) o[i][j] = 0.f;

    for (int kt = 0; kt < 15; kt++) {
        const int k0 = kt * 64;
        __syncthreads();
        {
            int r = tid >> 1, c0 = (tid & 1) * 16;
            bool v = (k0 + r) < QLEN;
            const float* p = base + 256 + (size_t)(k0 + r) * 768 + c0;
#pragma unroll
            for (int i = 0; i < 4; i++) {
                float4 x = v ? *(const float4*)(p + i * 4) : make_float4(0,0,0,0);
                uint16_t h0,h1,h2,h3,l0,l1,l2,l3;
                cvt_split(x.x,h0,l0); cvt_split(x.y,h1,l1);
                cvt_split(x.z,h2,l2); cvt_split(x.w,h3,l3);
                uint32_t off = sw64((uint32_t)(r * 64 + c0 * 2 + i * 8));
                *(uint2*)(sKh + off) = make_uint2((uint32_t)h0 | ((uint32_t)h1<<16),
                                                  (uint32_t)h2 | ((uint32_t)h3<<16));
                *(uint2*)(sKl + off) = make_uint2((uint32_t)l0 | ((uint32_t)l1<<16),
                                                  (uint32_t)l2 | ((uint32_t)l3<<16));
            }
        }
        {
            int col = tid >> 1, d0 = (tid & 1) * 16;
            bool v = (k0 + col) < QLEN;
            const float* p = base + 512 + (size_t)(k0 + col) * 768 + d0;
#pragma unroll
            for (int i = 0; i < 4; i++) {
                float4 x = v ? *(const float4*)(p + i * 4) : make_float4(0,0,0,0);
                float xv[4] = {x.x, x.y, x.z, x.w};
#pragma unroll
                for (int e = 0; e < 4; e++) {
                    int d = d0 + i * 4 + e;
                    uint16_t hb, lb;
                    cvt_split(xv[e], hb, lb);
                    uint32_t off = sw128((uint32_t)(d * 128 + col * 2));
                    *(uint16_t*)(sVh + off) = hb;
                    *(uint16_t*)(sVl + off) = lb;
                }
            }
        }
        __syncthreads();

        float s[8][4];
#pragma unroll
        for (int i = 0; i < 8; i++)
#pragma unroll
            for (int j = 0; j < 4; j++) s[i][j] = 0.f;
#pragma unroll
        for (int ks = 0; ks < 2; ks++) {
#pragma unroll
            for (int jj = 0; jj < 4; jj++) {
                uint32_t off = sw64((uint32_t)((jj*16 + (lane & 7)
                               + ((lane >> 4) << 3)) * 64
                               + ((lane >> 3) & 1) * 16 + ks * 32));
                uint32_t bhh[4], bll[4];
                ldmx4(bhh, uKh + off);
                ldmx4(bll, uKl + off);
                mma16816(s[2*jj],   qa[0][ks], bhh[0], bhh[1]);
                mma16816(s[2*jj],   qa[0][ks], bll[0], bll[1]);
                mma16816(s[2*jj],   qa[1][ks], bhh[0], bhh[1]);
                mma16816(s[2*jj+1], qa[0][ks], bhh[2], bhh[3]);
                mma16816(s[2*jj+1], qa[0][ks], bll[2], bll[3]);
                mma16816(s[2*jj+1], qa[1][ks], bhh[2], bhh[3]);
            }
        }

        const int colb = k0 + (lane & 3) * 2;
#pragma unroll
        for (int jn = 0; jn < 8; jn++) {
            int c0 = colb + jn * 8;
            if (c0 >= QLEN)     { s[jn][0] = -1e30f; s[jn][2] = -1e30f; }
            if (c0 + 1 >= QLEN) { s[jn][1] = -1e30f; s[jn][3] = -1e30f; }
        }

        float mx0 = -1e30f, mx1 = -1e30f;
#pragma unroll
        for (int jn = 0; jn < 8; jn++) {
            mx0 = fmaxf(mx0, fmaxf(s[jn][0], s[jn][1]));
            mx1 = fmaxf(mx1, fmaxf(s[jn][2], s[jn][3]));
        }
        mx0 = fmaxf(mx0, __shfl_xor_sync(0xffffffffu, mx0, 1));
        mx0 = fmaxf(mx0, __shfl_xor_sync(0xffffffffu, mx0, 2));
        mx1 = fmaxf(mx1, __shfl_xor_sync(0xffffffffu, mx1, 1));
        mx1 = fmaxf(mx1, __shfl_xor_sync(0xffffffffu, mx1, 2));
        float mn0 = fmaxf(m0, mx0), mn1 = fmaxf(m1, mx1);
        float corr0 = __expf(m0 - mn0), corr1 = __expf(m1 - mn1);
        m0 = mn0; m1 = mn1;
        float rs0 = 0.f, rs1 = 0.f;
#pragma unroll
        for (int jn = 0; jn < 8; jn++) {
            s[jn][0] = __expf(s[jn][0] - mn0);
            s[jn][1] = __expf(s[jn][1] - mn0);
            s[jn][2] = __expf(s[jn][2] - mn1);
            s[jn][3] = __expf(s[jn][3] - mn1);
            rs0 += s[jn][0] + s[jn][1];
            rs1 += s[jn][2] + s[jn][3];
        }
        rs0 += __shfl_xor_sync(0xffffffffu, rs0, 1);
        rs0 += __shfl_xor_sync(0xffffffffu, rs0, 2);
        rs1 += __shfl_xor_sync(0xffffffffu, rs1, 1);
        rs1 += __shfl_xor_sync(0xffffffffu, rs1, 2);
        l0s = l0s * corr0 + rs0;
        l1s = l1s * corr1 + rs1;
#pragma unroll
        for (int jn = 0; jn < 4; jn++) {
            o[jn][0] *= corr0; o[jn][1] *= corr0;
            o[jn][2] *= corr1; o[jn][3] *= corr1;
        }

#pragma unroll
        for (int ks = 0; ks < 4; ks++) {
            uint32_t pah[4], pal[4];
            {
                const float* t0 = s[2*ks];
                const float* t1 = s[2*ks+1];
                uint16_t h0,h1,l0,l1;
                cvt_split(t0[0],h0,l0); cvt_split(t0[1],h1,l1);
                pah[0] = (uint32_t)h0 | ((uint32_t)h1<<16);
                pal[0] = (uint32_t)l0 | ((uint32_t)l1<<16);
                cvt_split(t0[2],h0,l0); cvt_split(t0[3],h1,l1);
                pah[1] = (uint32_t)h0 | ((uint32_t)h1<<16);
                pal[1] = (uint32_t)l0 | ((uint32_t)l1<<16);
                cvt_split(t1[0],h0,l0); cvt_split(t1[1],h1,l1);
                pah[2] = (uint32_t)h0 | ((uint32_t)h1<<16);
                pal[2] = (uint32_t)l0 | ((uint32_t)l1<<16);
                cvt_split(t1[2],h0,l0); cvt_split(t1[3],h1,l1);
                pah[3] = (uint32_t)h0 | ((uint32_t)h1<<16);
                pal[3] = (uint32_t)l0 | ((uint32_t)l1<<16);
            }
#pragma unroll
            for (int jj = 0; jj < 2; jj++) {
                uint32_t off = sw128((uint32_t)((jj*16 + (lane & 7)
                               + ((lane >> 4) << 3)) * 128
                               + ((lane >> 3) & 1) * 16 + ks * 32));
                uint32_t vhh[4], vll[4];
                ldmx4(vhh, uVh + off);
                ldmx4(vll, uVl + off);
                mma16816(o[2*jj],   pah, vhh[0], vhh[1]);
                mma16816(o[2*jj],   pah, vll[0], vll[1]);
                mma16816(o[2*jj],   pal, vhh[0], vhh[1]);
                mma16816(o[2*jj+1], pah, vhh[2], vhh[3]);
                mma16816(o[2*jj+1], pah, vll[2], vll[3]);
                mma16816(o[2*jj+1], pal, vhh[2], vhh[3]);
            }
        }
    }

    // ---- finalize: write split bf16 ----
    {
        int r0 = q0 + w * 16 + (lane >> 2);
        float i0 = 1.f / l0s, i1 = 1.f / l1s;
#pragma unroll
        for (int jn = 0; jn < 4; jn++) {
            int c = h * 32 + jn * 8 + (lane & 3) * 2;
            uint16_t h0,h1,l0,l1;
            if (r0 < QLEN) {
                cvt_split(o[jn][0] * i0, h0, l0);
                cvt_split(o[jn][1] * i0, h1, l1);
                size_t off = (size_t)(b * QLEN + r0) * 256 + c;
                *(uint32_t*)(Oh + off) = (uint32_t)h0 | ((uint32_t)h1 << 16);
                *(uint32_t*)(Ol + off) = (uint32_t)l0 | ((uint32_t)l1 << 16);
            }
            if (r0 + 8 < QLEN) {
                cvt_split(o[jn][2] * i1, h0, l0);
                cvt_split(o[jn][3] * i1, h1, l1);
                size_t off = (size_t)(b * QLEN + r0 + 8) * 256 + c;
                *(uint32_t*)(Oh + off) = (uint32_t)h0 | ((uint32_t)h1 << 16);
                *(uint32_t*)(Ol + off) = (uint32_t)l0 | ((uint32_t)l1 << 16);
            }
        }
    }
}

// ---------------------------------------------------------------------------
// out = LayerNorm(a + b); optionally also emits bf16 hi/lo split of out.
// ---------------------------------------------------------------------------
__global__ __launch_bounds__(256) void add_ln(
    const float* __restrict__ a, const float* __restrict__ b,
    const float* __restrict__ gam, const float* __restrict__ bet,
    float* __restrict__ out,
    __nv_bfloat16* __restrict__ oh, __nv_bfloat16* __restrict__ ol,
    int do_split)
{
    __shared__ float red[8];
    __shared__ float s_mu, s_rstd;
    const int tid = threadIdx.x;
    const int lane = tid & 31, w = tid >> 5;
    size_t idx = (size_t)blockIdx.x * 256 + tid;
    float v = a[idx] + b[idx];

    float s = v;
#pragma unroll
    for (int o = 16; o; o >>= 1) s += __shfl_xor_sync(0xffffffffu, s, o);
    if (lane == 0) red[w] = s;
    __syncthreads();
    if (tid == 0) {
        float t = 0.f;
        for (int i = 0; i < 8; i++) t += red[i];
        s_mu = t * (1.f / 256.f);
    }
    __syncthreads();
    float d = v - s_mu;
    float sq = d * d;
    __syncthreads();
#pragma unroll
    for (int o = 16; o; o >>= 1) sq += __shfl_xor_sync(0xffffffffu, sq, o);
    if (lane == 0) red[w] = sq;
    __syncthreads();
    if (tid == 0) {
        float t = 0.f;
        for (int i = 0; i < 8; i++) t += red[i];
        s_rstd = rsqrtf(t * (1.f / 256.f) + 1e-5f);
    }
    __syncthreads();
    float r = d * s_rstd * gam[tid] + bet[tid];
    out[idx] = r;
    if (do_split) {
        uint16_t hh, ll;
        cvt_split(r, hh, ll);
        *(uint16_t*)(oh + idx) = hh;
        *(uint16_t*)(ol + idx) = ll;
    }
}

// ---------------------------------------------------------------------------
// Fused deformable attention sampling; emits split bf16 output.
// ---------------------------------------------------------------------------
__global__ __launch_bounds__(256) void deform_attn(
    const float* __restrict__ t, const float* __restrict__ val,
    const float* __restrict__ offs_w, const float* __restrict__ offs_b,
    const float* __restrict__ attw_w, const float* __restrict__ attw_b,
    const float* __restrict__ ref_w, const float* __restrict__ ref_b,
    const int* __restrict__ pH, const int* __restrict__ pW,
    __nv_bfloat16* __restrict__ oh, __nv_bfloat16* __restrict__ ol)
{
    __shared__ float trow[256];
    __shared__ float sref[2];
    __shared__ float soffs[64];
    __shared__ float sattw[32];
    const int bq = blockIdx.x;
    const int b = bq / QLEN;
    const int tid = threadIdx.x;
    const int warp = tid >> 5, lane = tid & 31;

    trow[tid] = t[(size_t)bq * 256 + tid];
    __syncthreads();

    for (int o = warp; o < 98; o += 8) {
        const float* wr;
        float bia;
        if (o < 2)       { wr = ref_w  + o * 256;        bia = ref_b[o]; }
        else if (o < 66) { wr = offs_w + (o - 2) * 256;  bia = offs_b[o - 2]; }
        else             { wr = attw_w + (o - 66) * 256; bia = attw_b[o - 66]; }
        float p = 0.f;
#pragma unroll
        for (int i = 0; i < 8; i++)
            p += trow[lane + i * 32] * wr[lane + i * 32];
#pragma unroll
        for (int oo = 16; oo; oo >>= 1) p += __shfl_xor_sync(0xffffffffu, p, oo);
        if (lane == 0) {
            float r = p + bia;
            if (o < 2)       sref[o] = 1.f / (1.f + __expf(-r));
            else if (o < 66) soffs[o - 2] = r;
            else             sattw[o - 66] = r;
        }
    }
    __syncthreads();

    if (tid < 8) {
        float m = -3.4e38f;
#pragma unroll
        for (int p = 0; p < 4; p++) m = fmaxf(m, sattw[tid * 4 + p]);
        float e[4], s = 0.f;
#pragma unroll
        for (int p = 0; p < 4; p++) { e[p] = __expf(sattw[tid * 4 + p] - m); s += e[p]; }
        float inv = 1.f / s;
#pragma unroll
        for (int p = 0; p < 4; p++) sattw[tid * 4 + p] = e[p] * inv;
    }
    __syncthreads();

    const int H = *pH, W = *pW;
    const float fH = (float)H, fW = (float)W;
    const int h = tid >> 5, d = tid & 31;
    const float refx = sref[0], refy = sref[1];
    const float* vbase = val + (size_t)b * H * W * 256 + h * 32 + d;
    float acc = 0.f;
#pragma unroll
    for (int p = 0; p < NPTS; p++) {
        float locx = refx + soffs[h * 8 + 2 * p]     / fW;
        float locy = refy + soffs[h * 8 + 2 * p + 1] / fH;
        float xx = locx * fW - 0.5f;
        float yy = locy * fH - 0.5f;
        float x0f = floorf(xx), y0f = floorf(yy);
        int x0 = (int)x0f, y0 = (int)y0f;
        float lx = xx - x0f, ly = yy - y0f;
        float w00 = (1.f - lx) * (1.f - ly);
        float w10 = lx * (1.f - ly);
        float w01 = (1.f - lx) * ly;
        float w11 = lx * ly;
        float s = 0.f;
        bool vx0 = (x0 >= 0) & (x0 < W);
        bool vx1 = (x0 + 1 >= 0) & (x0 + 1 < W);
        bool vy0 = (y0 >= 0) & (y0 < H);
        bool vy1 = (y0 + 1 >= 0) & (y0 + 1 < H);
        if (vx0 & vy0) s += w00 * vbase[((size_t)y0 * W + x0) * 256];
        if (vx1 & vy0) s += w10 * vbase[((size_t)y0 * W + x0 + 1) * 256];
        if (vx0 & vy1) s += w01 * vbase[((size_t)(y0 + 1) * W + x0) * 256];
        if (vx1 & vy1) s += w11 * vbase[((size_t)(y0 + 1) * W + x0 + 1) * 256];
        acc += sattw[h * 4 + p] * s;
    }
    uint16_t hh, ll;
    cvt_split(acc, hh, ll);
    *(uint16_t*)(oh + (size_t)bq * 256 + tid) = hh;
    *(uint16_t*)(ol + (size_t)bq * 256 + tid) = ll;
}

// ---------------------------------------------------------------------------
extern "C" void kernel_launch(void* const* d_in, const int* in_sizes, int n_in,
                              void* d_out, int out_size)
{
    const float* tgt  = (const float*)d_in[0];
    const float* mem  = (const float*)d_in[1];
    const int*   pH   = (const int*)d_in[2];
    const int*   pW   = (const int*)d_in[3];
    const float* inw  = (const float*)d_in[4];
    const float* inb  = (const float*)d_in[5];
    const float* outw = (const float*)d_in[6];
    const float* outb = (const float*)d_in[7];
    const float* n1s  = (const float*)d_in[8];
    const float* n1b  = (const float*)d_in[9];
    const float* n2s  = (const float*)d_in[10];
    const float* n2b  = (const float*)d_in[11];
    const float* n3s  = (const float*)d_in[12];
    const float* n3b  = (const float*)d_in[13];
    const float* vpw  = (const float*)d_in[14];
    const float* vpb  = (const float*)d_in[15];
    const float* ofw  = (const float*)d_in[16];
    const float* ofb  = (const float*)d_in[17];
    const float* aww  = (const float*)d_in[18];
    const float* awb  = (const float*)d_in[19];
    const float* rfw  = (const float*)d_in[20];
    const float* rfb  = (const float*)d_in[21];
    const float* cow  = (const float*)d_in[22];
    const float* cob  = (const float*)d_in[23];
    const float* f1w  = (const float*)d_in[24];
    const float* f1b  = (const float*)d_in[25];
    const float* f2w  = (const float*)d_in[26];
    const float* f2b  = (const float*)d_in[27];
    float* outp = (float*)d_out;

    const int M  = in_sizes[0] / DM;          // 7200
    const int Mm = in_sizes[1] / DM;          // 80000
    const int B  = M / QLEN;                  // 8
    const int BHgrid = B * NH;                // 64

    float *qkv, *t1, *val, *proj, *t2;
    __nv_bfloat16 *ah, *al, *wh, *wl, *fh, *fl;
    cudaGetSymbolAddress((void**)&qkv,  g_qkv);
    cudaGetSymbolAddress((void**)&t1,   g_t1);
    cudaGetSymbolAddress((void**)&val,  g_val);
    cudaGetSymbolAddress((void**)&proj, g_proj);
    cudaGetSymbolAddress((void**)&t2,   g_t2);
    cudaGetSymbolAddress((void**)&ah,   g_ah);
    cudaGetSymbolAddress((void**)&al,   g_al);
    cudaGetSymbolAddress((void**)&wh,   g_wh);
    cudaGetSymbolAddress((void**)&wl,   g_wl);
    cudaGetSymbolAddress((void**)&fh,   g_fh);
    cudaGetSymbolAddress((void**)&fl,   g_fl);

    cudaFuncSetAttribute(hgemm, cudaFuncAttributeMaxDynamicSharedMemorySize, HG_SMEM);

    const int mb  = (M + 127) / 128;          // 57
    const int mmb = (Mm + 127) / 128;         // 625

    auto splitN = [](const float* x, __nv_bfloat16* h, __nv_bfloat16* l, int n) {
        int n4 = n / 4;
        split_bf16<<<(n4 + 1023) / 1024, 256>>>(x, h, l, n4);
    };

    // ---- memory value projection ----
    splitN(mem, ah, al, Mm * 256);
    splitN(vpw, wh, wl, 256 * 256);
    hgemm<<<dim3(2, mmb), 256, HG_SMEM>>>(ah, al, wh, wl, vpb, val, 0, 0,
                                          Mm, 256, 256, 0);

    // ---- self-attention ----
    splitN(tgt, ah, al, M * 256);
    splitN(inw, wh, wl, 768 * 256);
    hgemm<<<dim3(6, mb), 256, HG_SMEM>>>(ah, al, wh, wl, inb, qkv, 0, 0,
                                         M, 768, 256, 0);
    flash_mma<<<dim3((QLEN + 63) / 64, BHgrid), 128>>>(qkv, ah, al);
    splitN(outw, wh, wl, 256 * 256);
    hgemm<<<dim3(2, mb), 256, HG_SMEM>>>(ah, al, wh, wl, outb, proj, 0, 0,
                                         M, 256, 256, 0);
    add_ln<<<M, 256>>>(proj, tgt, n1s, n1b, t1, 0, 0, 0);

    // ---- deformable cross-attention ----
    deform_attn<<<M, 256>>>(t1, val, ofw, ofb, aww, awb, rfw, rfb, pH, pW, ah, al);
    splitN(cow, wh, wl, 256 * 256);
    hgemm<<<dim3(2, mb), 256, HG_SMEM>>>(ah, al, wh, wl, cob, proj, 0, 0,
                                         M, 256, 256, 0);
    add_ln<<<M, 256>>>(proj, t1, n2s, n2b, t2, ah, al, 1);

    // ---- FFN ----
    splitN(f1w, wh, wl, FFD * 256);
    hgemm<<<dim3(8, mb), 256, HG_SMEM>>>(ah, al, wh, wl, f1b, 0, fh, fl,
                                         M, FFD, 256, 3);   // relu + split out
    splitN(f2w, wh, wl, 256 * FFD);
    hgemm<<<dim3(2, mb), 256, HG_SMEM>>>(fh, fl, wh, wl, f2b, proj, 0, 0,
                                         M, 256, FFD, 0);
    add_ln<<<M, 256>>>(proj, t2, n3s, n3b, outp, 0, 0, 0);
}

// round 10
// speedup vs baseline: 3.0044x; 1.1562x over previous
#include <cuda_runtime.h>
#include <cuda_bf16.h>
#include <math.h>
#include <stdint.h>

#define QLEN 900
#define DM   256
#define NH   8
#define HD   32
#define NPTS 4
#define FFD  1024

// ---------------- scratch (__device__ globals; allocation-free) ----------------
__device__ float g_t1[1843200];
__device__ float g_val[20480000];     // [B*HW, 256]
__device__ float g_proj[1843200];
__device__ float g_t2[1843200];
__device__ float g_dproj[921600];     // [B*Q, 128] deform projections
__device__ float g_dbias[128];
// bf16 hi/lo split buffers
__device__ __nv_bfloat16 g_ah[20480000];
__device__ __nv_bfloat16 g_al[20480000];
__device__ __nv_bfloat16 g_wh[917504];   // all weights concatenated
__device__ __nv_bfloat16 g_wl[917504];
__device__ __nv_bfloat16 g_ch[32768];    // deform proj weights 128x256
__device__ __nv_bfloat16 g_cl[32768];
__device__ __nv_bfloat16 g_fh[7372800];  // qkv / ffn intermediate hi
__device__ __nv_bfloat16 g_fl[7372800];  // qkv / ffn intermediate lo

// ============================================================================
// helpers
// ============================================================================
__device__ __forceinline__ uint32_t smem_u32(const void* p) {
    uint32_t a;
    asm("{ .reg .u64 t; cvta.to.shared.u64 t, %1; cvt.u32.u64 %0, t; }"
        : "=r"(a) : "l"(p));
    return a;
}
__device__ __forceinline__ uint32_t sw128(uint32_t off) {
    return off ^ ((off >> 3) & 0x70);
}
__device__ __forceinline__ uint32_t sw64(uint32_t off) {
    return off ^ ((off >> 3) & 0x30);
}
__device__ __forceinline__ void cvt_split(float f, uint16_t& h, uint16_t& l) {
    __nv_bfloat16 hb = __float2bfloat16_rn(f);
    float r = f - __bfloat162float(hb);
    __nv_bfloat16 lb = __float2bfloat16_rn(r);
    h = *reinterpret_cast<uint16_t*>(&hb);
    l = *reinterpret_cast<uint16_t*>(&lb);
}
__device__ __forceinline__ void ldmx4(uint32_t* r, uint32_t addr) {
    asm volatile("ldmatrix.sync.aligned.m8n8.x4.shared.b16 {%0,%1,%2,%3}, [%4];"
        : "=r"(r[0]), "=r"(r[1]), "=r"(r[2]), "=r"(r[3]) : "r"(addr));
}
__device__ __forceinline__ void ldmx4t(uint32_t* r, uint32_t addr) {
    asm volatile("ldmatrix.sync.aligned.m8n8.x4.trans.shared.b16 {%0,%1,%2,%3}, [%4];"
        : "=r"(r[0]), "=r"(r[1]), "=r"(r[2]), "=r"(r[3]) : "r"(addr));
}
__device__ __forceinline__ void mma16816(float* d, const uint32_t* a,
                                         uint32_t b0, uint32_t b1) {
    asm volatile(
        "mma.sync.aligned.m16n8k16.row.col.f32.bf16.bf16.f32 "
        "{%0,%1,%2,%3}, {%4,%5,%6,%7}, {%8,%9}, {%0,%1,%2,%3};"
        : "+f"(d[0]), "+f"(d[1]), "+f"(d[2]), "+f"(d[3])
        : "r"(a[0]), "r"(a[1]), "r"(a[2]), "r"(a[3]), "r"(b0), "r"(b1));
}
__device__ __forceinline__ void cp_async16(uint32_t dst, const void* src, uint32_t sz) {
    asm volatile("cp.async.cg.shared.global [%0], [%1], 16, %2;"
        :: "r"(dst), "l"(src), "r"(sz));
}
#define CP_COMMIT() asm volatile("cp.async.commit_group;" ::: "memory")
#define CP_WAIT0()  asm volatile("cp.async.wait_group 0;" ::: "memory")
#define CP_WAIT1()  asm volatile("cp.async.wait_group 1;" ::: "memory")

// ============================================================================
// split_bf16: fp32 -> (hi, lo) bf16; 4 float4 per thread.
// ============================================================================
__global__ __launch_bounds__(256) void split_bf16(
    const float* __restrict__ x, __nv_bfloat16* __restrict__ hi,
    __nv_bfloat16* __restrict__ lo, int n4)
{
    int i0 = blockIdx.x * 1024 + threadIdx.x;
#pragma unroll
    for (int it = 0; it < 4; it++) {
        int i = i0 + it * 256;
        if (i >= n4) return;
        float4 v = ((const float4*)x)[i];
        uint16_t h0,h1,h2,h3,l0,l1,l2,l3;
        cvt_split(v.x,h0,l0); cvt_split(v.y,h1,l1);
        cvt_split(v.z,h2,l2); cvt_split(v.w,h3,l3);
        ((uint2*)hi)[i] = make_uint2((uint32_t)h0 | ((uint32_t)h1 << 16),
                                     (uint32_t)h2 | ((uint32_t)h3 << 16));
        ((uint2*)lo)[i] = make_uint2((uint32_t)l0 | ((uint32_t)l1 << 16),
                                     (uint32_t)l2 | ((uint32_t)l3 << 16));
    }
}

// ============================================================================
// split_weights: all 6 weight matrices -> one concatenated hi/lo buffer.
// float4 units: vpw@0(16384) inw@16384(49152) outw@65536(16384) cow@81920(16384)
//               f1w@98304(65536) f2w@163840(65536)   total 229376
// ============================================================================
__global__ __launch_bounds__(256) void split_weights(
    const float* __restrict__ vpw, const float* __restrict__ inw,
    const float* __restrict__ outw, const float* __restrict__ cow,
    const float* __restrict__ f1w, const float* __restrict__ f2w,
    __nv_bfloat16* __restrict__ wh, __nv_bfloat16* __restrict__ wl)
{
    int i0 = blockIdx.x * 1024 + threadIdx.x;
#pragma unroll
    for (int it = 0; it < 4; it++) {
        int i = i0 + it * 256;
        if (i >= 229376) return;
        const float* src; int li;
        if (i < 16384)       { src = vpw;  li = i; }
        else if (i < 65536)  { src = inw;  li = i - 16384; }
        else if (i < 81920)  { src = outw; li = i - 65536; }
        else if (i < 98304)  { src = cow;  li = i - 81920; }
        else if (i < 163840) { src = f1w;  li = i - 98304; }
        else                 { src = f2w;  li = i - 163840; }
        float4 v = ((const float4*)src)[li];
        uint16_t h0,h1,h2,h3,l0,l1,l2,l3;
        cvt_split(v.x,h0,l0); cvt_split(v.y,h1,l1);
        cvt_split(v.z,h2,l2); cvt_split(v.w,h3,l3);
        ((uint2*)wh)[i] = make_uint2((uint32_t)h0 | ((uint32_t)h1 << 16),
                                     (uint32_t)h2 | ((uint32_t)h3 << 16));
        ((uint2*)wl)[i] = make_uint2((uint32_t)l0 | ((uint32_t)l1 << 16),
                                     (uint32_t)l2 | ((uint32_t)l3 << 16));
    }
}

// ============================================================================
// build_dproj_w: concat [ref(2) | offs(64) | attw(32) | pad(30)] x 256 weights
// into split bf16 + fp32 bias vector.
// ============================================================================
__global__ __launch_bounds__(256) void build_dproj_w(
    const float* __restrict__ rfw, const float* __restrict__ rfb,
    const float* __restrict__ ofw, const float* __restrict__ ofb,
    const float* __restrict__ aww, const float* __restrict__ awb,
    __nv_bfloat16* __restrict__ ch, __nv_bfloat16* __restrict__ cl,
    float* __restrict__ dbias)
{
    int row = blockIdx.x, tid = threadIdx.x;
    float v = 0.f;
    if (row < 2)       v = rfw[row * 256 + tid];
    else if (row < 66) v = ofw[(row - 2) * 256 + tid];
    else if (row < 98) v = aww[(row - 66) * 256 + tid];
    uint16_t hh, ll;
    cvt_split(v, hh, ll);
    *(uint16_t*)(ch + row * 256 + tid) = hh;
    *(uint16_t*)(cl + row * 256 + tid) = ll;
    if (tid == 0)
        dbias[row] = row < 2 ? rfb[row] : row < 66 ? ofb[row - 2]
                   : row < 98 ? awb[row - 66] : 0.f;
}

// ============================================================================
// hgemm: C = act(A @ W^T + bias), bf16x3, cp.async 2-stage pipeline.
// 128x128 tile, BK=64, 8 warps. mode bit0=relu, bit1=split-output (Ch/Cl).
// ============================================================================
#define HG_SMEM (2 * 65536)

__global__ __launch_bounds__(256) void hgemm(
    const __nv_bfloat16* __restrict__ Ah, const __nv_bfloat16* __restrict__ Al,
    const __nv_bfloat16* __restrict__ Wh, const __nv_bfloat16* __restrict__ Wl,
    const float* __restrict__ bias, float* __restrict__ C,
    __nv_bfloat16* __restrict__ Ch, __nv_bfloat16* __restrict__ Cl,
    int M, int N, int K, int mode)
{
    extern __shared__ char sm[];
    const uint32_t sb = smem_u32(sm);
    const int tid = threadIdx.x;
    const int wid = tid >> 5, lane = tid & 31;
    const int row0 = blockIdx.y * 128, col0 = blockIdx.x * 128;
    const int wm = (wid & 1) * 64;
    const int wn = (wid >> 1) * 32;

    float acc[4][4][4];
#pragma unroll
    for (int mt = 0; mt < 4; mt++)
#pragma unroll
        for (int nt = 0; nt < 4; nt++)
#pragma unroll
            for (int j = 0; j < 4; j++) acc[mt][nt][j] = 0.f;

    const uint32_t a_row = wm + (lane & 15);
    const uint32_t a_cb  = (lane >> 4) * 16;
    const uint32_t b_row = wn + (lane & 7) + ((lane >> 4) << 3);
    const uint32_t b_cb  = ((lane >> 3) & 1) * 16;
    const int nc = K >> 6;

    const int lr  = tid >> 3;
    const int lc8 = (tid & 7) * 8;

    {
#pragma unroll
        for (int it = 0; it < 4; it++) {
            int r = lr + it * 32;
            uint32_t so = sw128((uint32_t)(r * 128 + lc8 * 2));
            int ra = row0 + r < M ? row0 + r : M - 1;
            uint32_t asz = (row0 + r < M) ? 16u : 0u;
            cp_async16(sb + so,         Ah + (size_t)ra * K + lc8, asz);
            cp_async16(sb + 16384 + so, Al + (size_t)ra * K + lc8, asz);
            cp_async16(sb + 32768 + so, Wh + (size_t)(col0 + r) * K + lc8, 16u);
            cp_async16(sb + 49152 + so, Wl + (size_t)(col0 + r) * K + lc8, 16u);
        }
        CP_COMMIT();
    }

    for (int c = 0; c < nc; c++) {
        const uint32_t stb = sb + (uint32_t)(c & 1) * 65536;
        if (c + 1 < nc) {
            const uint32_t nstb = sb + (uint32_t)((c + 1) & 1) * 65536;
            const int k0 = (c + 1) << 6;
#pragma unroll
            for (int it = 0; it < 4; it++) {
                int r = lr + it * 32;
                uint32_t so = sw128((uint32_t)(r * 128 + lc8 * 2));
                int ra = row0 + r < M ? row0 + r : M - 1;
                uint32_t asz = (row0 + r < M) ? 16u : 0u;
                cp_async16(nstb + so,         Ah + (size_t)ra * K + k0 + lc8, asz);
                cp_async16(nstb + 16384 + so, Al + (size_t)ra * K + k0 + lc8, asz);
                cp_async16(nstb + 32768 + so, Wh + (size_t)(col0 + r) * K + k0 + lc8, 16u);
                cp_async16(nstb + 49152 + so, Wl + (size_t)(col0 + r) * K + k0 + lc8, 16u);
            }
            CP_COMMIT();
            CP_WAIT1();
        } else {
            CP_WAIT0();
        }
        __syncthreads();

#pragma unroll
        for (int ks = 0; ks < 64; ks += 16) {
            uint32_t ah[4][4], alr[4][4], bh[2][4], bl[2][4];
#pragma unroll
            for (int mt = 0; mt < 4; mt++) {
                uint32_t off = sw128((a_row + mt * 16) * 128 + ks * 2 + a_cb);
                ldmx4(ah[mt],  stb + off);
                ldmx4(alr[mt], stb + 16384 + off);
            }
#pragma unroll
            for (int bt = 0; bt < 2; bt++) {
                uint32_t off = sw128((b_row + bt * 16) * 128 + ks * 2 + b_cb);
                ldmx4(bh[bt], stb + 32768 + off);
                ldmx4(bl[bt], stb + 49152 + off);
            }
#pragma unroll
            for (int mt = 0; mt < 4; mt++) {
#pragma unroll
                for (int nt = 0; nt < 4; nt++) {
                    int bt = nt >> 1, bi = (nt & 1) * 2;
                    mma16816(acc[mt][nt], ah[mt],  bh[bt][bi], bh[bt][bi+1]);
                    mma16816(acc[mt][nt], ah[mt],  bl[bt][bi], bl[bt][bi+1]);
                    mma16816(acc[mt][nt], alr[mt], bh[bt][bi], bh[bt][bi+1]);
                }
            }
        }
        __syncthreads();
    }

    const bool relu = mode & 1;
    const bool split = mode & 2;
#pragma unroll
    for (int mt = 0; mt < 4; mt++) {
        int r0e = row0 + wm + mt * 16 + (lane >> 2);
#pragma unroll
        for (int nt = 0; nt < 4; nt++) {
            int c = col0 + wn + nt * 8 + (lane & 3) * 2;
            float b0 = bias[c], b1 = bias[c + 1];
            float2 v0 = make_float2(acc[mt][nt][0] + b0, acc[mt][nt][1] + b1);
            float2 v1 = make_float2(acc[mt][nt][2] + b0, acc[mt][nt][3] + b1);
            if (relu) {
                v0.x = fmaxf(v0.x, 0.f); v0.y = fmaxf(v0.y, 0.f);
                v1.x = fmaxf(v1.x, 0.f); v1.y = fmaxf(v1.y, 0.f);
            }
            if (!split) {
                if (r0e < M)     *(float2*)(C + (size_t)r0e * N + c) = v0;
                if (r0e + 8 < M) *(float2*)(C + (size_t)(r0e + 8) * N + c) = v1;
            } else {
                uint16_t h0,h1,l0,l1;
                if (r0e < M) {
                    cvt_split(v0.x, h0, l0); cvt_split(v0.y, h1, l1);
                    *(uint32_t*)(Ch + (size_t)r0e * N + c) =
                        (uint32_t)h0 | ((uint32_t)h1 << 16);
                    *(uint32_t*)(Cl + (size_t)r0e * N + c) =
                        (uint32_t)l0 | ((uint32_t)l1 << 16);
                }
                if (r0e + 8 < M) {
                    cvt_split(v1.x, h0, l0); cvt_split(v1.y, h1, l1);
                    *(uint32_t*)(Ch + (size_t)(r0e + 8) * N + c) =
                        (uint32_t)h0 | ((uint32_t)h1 << 16);
                    *(uint32_t*)(Cl + (size_t)(r0e + 8) * N + c) =
                        (uint32_t)l0 | ((uint32_t)l1 << 16);
                }
            }
        }
    }
}

// ============================================================================
// flash_mma: fused flash self-attention, bf16x3, split-bf16 QKV inputs.
// cp.async 2-stage KV pipeline; V B-frags via ldmatrix.trans (no transpose).
// ============================================================================
__global__ __launch_bounds__(128) void flash_mma(
    const __nv_bfloat16* __restrict__ QKVh, const __nv_bfloat16* __restrict__ QKVl,
    __nv_bfloat16* __restrict__ Oh, __nv_bfloat16* __restrict__ Ol)
{
    __shared__ __align__(16) char sQ[2][4096];       // [hi/lo] 64 rows x 64B
    __shared__ __align__(16) char sKV[2][4][4096];   // [stage][Kh,Kl,Vh,Vl]

    const int bh = blockIdx.y;
    const int b = bh >> 3, h = bh & 7;
    const int q0 = blockIdx.x * 64;
    const int tid = threadIdx.x;
    const int w = tid >> 5, lane = tid & 31;
    const float scale = 0.17677669529663687f;

    const size_t rowbase = (size_t)b * QLEN * 768 + h * 32;
    const __nv_bfloat16* gqh = QKVh + rowbase;
    const __nv_bfloat16* gql = QKVl + rowbase;

    const uint32_t uQ0 = smem_u32(sQ[0]), uQ1 = smem_u32(sQ[1]);
    const uint32_t uKV = smem_u32(sKV[0][0]);

    // per-thread cp.async slots: row = tid>>1, 32B half = (tid&1)
    const int lrow = tid >> 1;
    const int lel  = (tid & 1) * 16;                 // element offset
    const uint32_t so0 = sw64((uint32_t)(lrow * 64 + lel * 2));
    const uint32_t so1 = sw64((uint32_t)(lrow * 64 + lel * 2 + 16));

    // ---- issue Q + KV(0) ----
    {
        uint32_t qsz = (q0 + lrow < QLEN) ? 16u : 0u;
        const __nv_bfloat16* sh = gqh + (size_t)(q0 + lrow) * 768 + lel;
        const __nv_bfloat16* sl = gql + (size_t)(q0 + lrow) * 768 + lel;
        cp_async16(uQ0 + so0, sh, qsz);     cp_async16(uQ0 + so1, sh + 8, qsz);
        cp_async16(uQ1 + so0, sl, qsz);     cp_async16(uQ1 + so1, sl + 8, qsz);
        uint32_t ksz = (lrow < QLEN) ? 16u : 0u;   // k0 = 0
        const __nv_bfloat16* kh = gqh + 256 + (size_t)lrow * 768 + lel;
        const __nv_bfloat16* kl = gql + 256 + (size_t)lrow * 768 + lel;
        const __nv_bfloat16* vh = gqh + 512 + (size_t)lrow * 768 + lel;
        const __nv_bfloat16* vl = gql + 512 + (size_t)lrow * 768 + lel;
        cp_async16(uKV + so0, kh, ksz);             cp_async16(uKV + so1, kh + 8, ksz);
        cp_async16(uKV + 4096 + so0, kl, ksz);      cp_async16(uKV + 4096 + so1, kl + 8, ksz);
        cp_async16(uKV + 8192 + so0, vh, ksz);      cp_async16(uKV + 8192 + so1, vh + 8, ksz);
        cp_async16(uKV + 12288 + so0, vl, ksz);     cp_async16(uKV + 12288 + so1, vl + 8, ksz);
        CP_COMMIT();
    }
    CP_WAIT0();
    __syncthreads();

    // ---- Q A-fragments (fixed) ----
    uint32_t qa[2][2][4];
#pragma unroll
    for (int ks = 0; ks < 2; ks++) {
        uint32_t off = sw64((uint32_t)((w*16 + (lane & 15)) * 64
                            + ks * 32 + (lane >> 4) * 16));
        ldmx4(qa[0][ks], uQ0 + off);
        ldmx4(qa[1][ks], uQ1 + off);
    }

    float m0 = -1e30f, m1 = -1e30f, l0s = 0.f, l1s = 0.f;
    float o[4][4];
#pragma unroll
    for (int i = 0; i < 4; i++)
#pragma unroll
        for (int j = 0; j < 4; j++) o[i][j] = 0.f;

    for (int kt = 0; kt < 15; kt++) {
        // ---- prefetch KV(kt+1) ----
        if (kt < 14) {
            const int k0n = (kt + 1) * 64;
            const uint32_t nb = uKV + (uint32_t)((kt + 1) & 1) * 16384;
            uint32_t ksz = (k0n + lrow < QLEN) ? 16u : 0u;
            const __nv_bfloat16* kh = gqh + 256 + (size_t)(k0n + lrow) * 768 + lel;
            const __nv_bfloat16* kl = gql + 256 + (size_t)(k0n + lrow) * 768 + lel;
            const __nv_bfloat16* vh = gqh + 512 + (size_t)(k0n + lrow) * 768 + lel;
            const __nv_bfloat16* vl = gql + 512 + (size_t)(k0n + lrow) * 768 + lel;
            cp_async16(nb + so0, kh, ksz);            cp_async16(nb + so1, kh + 8, ksz);
            cp_async16(nb + 4096 + so0, kl, ksz);     cp_async16(nb + 4096 + so1, kl + 8, ksz);
            cp_async16(nb + 8192 + so0, vh, ksz);     cp_async16(nb + 8192 + so1, vh + 8, ksz);
            cp_async16(nb + 12288 + so0, vl, ksz);    cp_async16(nb + 12288 + so1, vl + 8, ksz);
            CP_COMMIT();
        }

        const uint32_t stb = uKV + (uint32_t)(kt & 1) * 16384;
        const int k0 = kt * 64;

        // ---- S = Q K^T (bf16x3) ----
        float s[8][4];
#pragma unroll
        for (int i = 0; i < 8; i++)
#pragma unroll
            for (int j = 0; j < 4; j++) s[i][j] = 0.f;
#pragma unroll
        for (int ks = 0; ks < 2; ks++) {
#pragma unroll
            for (int jj = 0; jj < 4; jj++) {
                uint32_t off = sw64((uint32_t)((jj*16 + (lane & 7)
                               + ((lane >> 4) << 3)) * 64
                               + ((lane >> 3) & 1) * 16 + ks * 32));
                uint32_t bhh[4], bll[4];
                ldmx4(bhh, stb + off);
                ldmx4(bll, stb + 4096 + off);
                mma16816(s[2*jj],   qa[0][ks], bhh[0], bhh[1]);
                mma16816(s[2*jj],   qa[0][ks], bll[0], bll[1]);
                mma16816(s[2*jj],   qa[1][ks], bhh[0], bhh[1]);
                mma16816(s[2*jj+1], qa[0][ks], bhh[2], bhh[3]);
                mma16816(s[2*jj+1], qa[0][ks], bll[2], bll[3]);
                mma16816(s[2*jj+1], qa[1][ks], bhh[2], bhh[3]);
            }
        }
        // scale + mask
#pragma unroll
        for (int jn = 0; jn < 8; jn++) {
#pragma unroll
            for (int j = 0; j < 4; j++) s[jn][j] *= scale;
        }
        const int colb = k0 + (lane & 3) * 2;
#pragma unroll
        for (int jn = 0; jn < 8; jn++) {
            int c0 = colb + jn * 8;
            if (c0 >= QLEN)     { s[jn][0] = -1e30f; s[jn][2] = -1e30f; }
            if (c0 + 1 >= QLEN) { s[jn][1] = -1e30f; s[jn][3] = -1e30f; }
        }

        // ---- online softmax ----
        float mx0 = -1e30f, mx1 = -1e30f;
#pragma unroll
        for (int jn = 0; jn < 8; jn++) {
            mx0 = fmaxf(mx0, fmaxf(s[jn][0], s[jn][1]));
            mx1 = fmaxf(mx1, fmaxf(s[jn][2], s[jn][3]));
        }
        mx0 = fmaxf(mx0, __shfl_xor_sync(0xffffffffu, mx0, 1));
        mx0 = fmaxf(mx0, __shfl_xor_sync(0xffffffffu, mx0, 2));
        mx1 = fmaxf(mx1, __shfl_xor_sync(0xffffffffu, mx1, 1));
        mx1 = fmaxf(mx1, __shfl_xor_sync(0xffffffffu, mx1, 2));
        float mn0 = fmaxf(m0, mx0), mn1 = fmaxf(m1, mx1);
        float corr0 = __expf(m0 - mn0), corr1 = __expf(m1 - mn1);
        m0 = mn0; m1 = mn1;
        float rs0 = 0.f, rs1 = 0.f;
#pragma unroll
        for (int jn = 0; jn < 8; jn++) {
            s[jn][0] = __expf(s[jn][0] - mn0);
            s[jn][1] = __expf(s[jn][1] - mn0);
            s[jn][2] = __expf(s[jn][2] - mn1);
            s[jn][3] = __expf(s[jn][3] - mn1);
            rs0 += s[jn][0] + s[jn][1];
            rs1 += s[jn][2] + s[jn][3];
        }
        rs0 += __shfl_xor_sync(0xffffffffu, rs0, 1);
        rs0 += __shfl_xor_sync(0xffffffffu, rs0, 2);
        rs1 += __shfl_xor_sync(0xffffffffu, rs1, 1);
        rs1 += __shfl_xor_sync(0xffffffffu, rs1, 2);
        l0s = l0s * corr0 + rs0;
        l1s = l1s * corr1 + rs1;
#pragma unroll
        for (int jn = 0; jn < 4; jn++) {
            o[jn][0] *= corr0; o[jn][1] *= corr0;
            o[jn][2] *= corr1; o[jn][3] *= corr1;
        }

        // ---- O += P @ V : P from registers, V via ldmatrix.trans ----
#pragma unroll
        for (int ks = 0; ks < 4; ks++) {
            uint32_t pah[4], pal[4];
            {
                const float* t0 = s[2*ks];
                const float* t1 = s[2*ks+1];
                uint16_t h0,h1,l0,l1;
                cvt_split(t0[0],h0,l0); cvt_split(t0[1],h1,l1);
                pah[0] = (uint32_t)h0 | ((uint32_t)h1<<16);
                pal[0] = (uint32_t)l0 | ((uint32_t)l1<<16);
                cvt_split(t0[2],h0,l0); cvt_split(t0[3],h1,l1);
                pah[1] = (uint32_t)h0 | ((uint32_t)h1<<16);
                pal[1] = (uint32_t)l0 | ((uint32_t)l1<<16);
                cvt_split(t1[0],h0,l0); cvt_split(t1[1],h1,l1);
                pah[2] = (uint32_t)h0 | ((uint32_t)h1<<16);
                pal[2] = (uint32_t)l0 | ((uint32_t)l1<<16);
                cvt_split(t1[2],h0,l0); cvt_split(t1[3],h1,l1);
                pah[3] = (uint32_t)h0 | ((uint32_t)h1<<16);
                pal[3] = (uint32_t)l0 | ((uint32_t)l1<<16);
            }
            // V rows = kpos, cols = d; trans load gives B-frags
            uint32_t vrow = (uint32_t)(ks * 16 + (lane & 7) + ((lane >> 3) & 1) * 8);
#pragma unroll
            for (int jj = 0; jj < 2; jj++) {
                uint32_t off = sw64(vrow * 64 + jj * 32 + (lane >> 4) * 16);
                uint32_t vhh[4], vll[4];
                ldmx4t(vhh, stb + 8192 + off);
                ldmx4t(vll, stb + 12288 + off);
                mma16816(o[2*jj],   pah, vhh[0], vhh[1]);
                mma16816(o[2*jj],   pah, vll[0], vll[1]);
                mma16816(o[2*jj],   pal, vhh[0], vhh[1]);
                mma16816(o[2*jj+1], pah, vhh[2], vhh[3]);
                mma16816(o[2*jj+1], pah, vll[2], vll[3]);
                mma16816(o[2*jj+1], pal, vhh[2], vhh[3]);
            }
        }

        if (kt < 14) CP_WAIT0();
        __syncthreads();
    }

    // ---- finalize: write split bf16 ----
    {
        int r0 = q0 + w * 16 + (lane >> 2);
        float i0 = 1.f / l0s, i1 = 1.f / l1s;
#pragma unroll
        for (int jn = 0; jn < 4; jn++) {
            int c = h * 32 + jn * 8 + (lane & 3) * 2;
            uint16_t h0,h1,l0,l1;
            if (r0 < QLEN) {
                cvt_split(o[jn][0] * i0, h0, l0);
                cvt_split(o[jn][1] * i0, h1, l1);
                size_t off = (size_t)(b * QLEN + r0) * 256 + c;
                *(uint32_t*)(Oh + off) = (uint32_t)h0 | ((uint32_t)h1 << 16);
                *(uint32_t*)(Ol + off) = (uint32_t)l0 | ((uint32_t)l1 << 16);
            }
            if (r0 + 8 < QLEN) {
                cvt_split(o[jn][2] * i1, h0, l0);
                cvt_split(o[jn][3] * i1, h1, l1);
                size_t off = (size_t)(b * QLEN + r0 + 8) * 256 + c;
                *(uint32_t*)(Oh + off) = (uint32_t)h0 | ((uint32_t)h1 << 16);
                *(uint32_t*)(Ol + off) = (uint32_t)l0 | ((uint32_t)l1 << 16);
            }
        }
    }
}

// ---------------------------------------------------------------------------
// out = LayerNorm(a + b); optionally also emits bf16 hi/lo split of out.
// ---------------------------------------------------------------------------
__global__ __launch_bounds__(256) void add_ln(
    const float* __restrict__ a, const float* __restrict__ b,
    const float* __restrict__ gam, const float* __restrict__ bet,
    float* __restrict__ out,
    __nv_bfloat16* __restrict__ oh, __nv_bfloat16* __restrict__ ol,
    int do_split)
{
    __shared__ float red[8];
    __shared__ float s_mu, s_rstd;
    const int tid = threadIdx.x;
    const int lane = tid & 31, w = tid >> 5;
    size_t idx = (size_t)blockIdx.x * 256 + tid;
    float v = a[idx] + b[idx];

    float s = v;
#pragma unroll
    for (int o = 16; o; o >>= 1) s += __shfl_xor_sync(0xffffffffu, s, o);
    if (lane == 0) red[w] = s;
    __syncthreads();
    if (tid == 0) {
        float t = 0.f;
        for (int i = 0; i < 8; i++) t += red[i];
        s_mu = t * (1.f / 256.f);
    }
    __syncthreads();
    float d = v - s_mu;
    float sq = d * d;
    __syncthreads();
#pragma unroll
    for (int o = 16; o; o >>= 1) sq += __shfl_xor_sync(0xffffffffu, sq, o);
    if (lane == 0) red[w] = sq;
    __syncthreads();
    if (tid == 0) {
        float t = 0.f;
        for (int i = 0; i < 8; i++) t += red[i];
        s_rstd = rsqrtf(t * (1.f / 256.f) + 1e-5f);
    }
    __syncthreads();
    float r = d * s_rstd * gam[tid] + bet[tid];
    out[idx] = r;
    if (do_split) {
        uint16_t hh, ll;
        cvt_split(r, hh, ll);
        *(uint16_t*)(oh + idx) = hh;
        *(uint16_t*)(ol + idx) = ll;
    }
}

// ---------------------------------------------------------------------------
// deform_attn v2: projections precomputed by GEMM; sigmoid/softmax + gather.
// ---------------------------------------------------------------------------
__global__ __launch_bounds__(256) void deform_attn(
    const float* __restrict__ dproj, const float* __restrict__ val,
    const int* __restrict__ pH, const int* __restrict__ pW,
    __nv_bfloat16* __restrict__ oh, __nv_bfloat16* __restrict__ ol)
{
    __shared__ float sref[2];
    __shared__ float soffs[64];
    __shared__ float sattw[32];
    const int bq = blockIdx.x;
    const int b = bq / QLEN;
    const int tid = threadIdx.x;

    if (tid < 98) {
        float v = dproj[(size_t)bq * 128 + tid];
        if (tid < 2)       sref[tid] = 1.f / (1.f + __expf(-v));
        else if (tid < 66) soffs[tid - 2] = v;
        else               sattw[tid - 66] = v;
    }
    __syncthreads();

    if (tid < 8) {
        float m = -3.4e38f;
#pragma unroll
        for (int p = 0; p < 4; p++) m = fmaxf(m, sattw[tid * 4 + p]);
        float e[4], s = 0.f;
#pragma unroll
        for (int p = 0; p < 4; p++) { e[p] = __expf(sattw[tid * 4 + p] - m); s += e[p]; }
        float inv = 1.f / s;
#pragma unroll
        for (int p = 0; p < 4; p++) sattw[tid * 4 + p] = e[p] * inv;
    }
    __syncthreads();

    const int H = *pH, W = *pW;
    const float fH = (float)H, fW = (float)W;
    const int h = tid >> 5, d = tid & 31;
    const float refx = sref[0], refy = sref[1];
    const float* vbase = val + (size_t)b * H * W * 256 + h * 32 + d;
    float acc = 0.f;
#pragma unroll
    for (int p = 0; p < NPTS; p++) {
        float locx = refx + soffs[h * 8 + 2 * p]     / fW;
        float locy = refy + soffs[h * 8 + 2 * p + 1] / fH;
        float xx = locx * fW - 0.5f;
        float yy = locy * fH - 0.5f;
        float x0f = floorf(xx), y0f = floorf(yy);
        int x0 = (int)x0f, y0 = (int)y0f;
        float lx = xx - x0f, ly = yy - y0f;
        float w00 = (1.f - lx) * (1.f - ly);
        float w10 = lx * (1.f - ly);
        float w01 = (1.f - lx) * ly;
        float w11 = lx * ly;
        float s = 0.f;
        bool vx0 = (x0 >= 0) & (x0 < W);
        bool vx1 = (x0 + 1 >= 0) & (x0 + 1 < W);
        bool vy0 = (y0 >= 0) & (y0 < H);
        bool vy1 = (y0 + 1 >= 0) & (y0 + 1 < H);
        if (vx0 & vy0) s += w00 * vbase[((size_t)y0 * W + x0) * 256];
        if (vx1 & vy0) s += w10 * vbase[((size_t)y0 * W + x0 + 1) * 256];
        if (vx0 & vy1) s += w01 * vbase[((size_t)(y0 + 1) * W + x0) * 256];
        if (vx1 & vy1) s += w11 * vbase[((size_t)(y0 + 1) * W + x0 + 1) * 256];
        acc += sattw[h * 4 + p] * s;
    }
    uint16_t hh, ll;
    cvt_split(acc, hh, ll);
    *(uint16_t*)(oh + (size_t)bq * 256 + tid) = hh;
    *(uint16_t*)(ol + (size_t)bq * 256 + tid) = ll;
}

// ---------------------------------------------------------------------------
extern "C" void kernel_launch(void* const* d_in, const int* in_sizes, int n_in,
                              void* d_out, int out_size)
{
    const float* tgt  = (const float*)d_in[0];
    const float* mem  = (const float*)d_in[1];
    const int*   pH   = (const int*)d_in[2];
    const int*   pW   = (const int*)d_in[3];
    const float* inw  = (const float*)d_in[4];
    const float* inb  = (const float*)d_in[5];
    const float* outw = (const float*)d_in[6];
    const float* outb = (const float*)d_in[7];
    const float* n1s  = (const float*)d_in[8];
    const float* n1b  = (const float*)d_in[9];
    const float* n2s  = (const float*)d_in[10];
    const float* n2b  = (const float*)d_in[11];
    const float* n3s  = (const float*)d_in[12];
    const float* n3b  = (const float*)d_in[13];
    const float* vpw  = (const float*)d_in[14];
    const float* vpb  = (const float*)d_in[15];
    const float* ofw  = (const float*)d_in[16];
    const float* ofb  = (const float*)d_in[17];
    const float* aww  = (const float*)d_in[18];
    const float* awb  = (const float*)d_in[19];
    const float* rfw  = (const float*)d_in[20];
    const float* rfb  = (const float*)d_in[21];
    const float* cow  = (const float*)d_in[22];
    const float* cob  = (const float*)d_in[23];
    const float* f1w  = (const float*)d_in[24];
    const float* f1b  = (const float*)d_in[25];
    const float* f2w  = (const float*)d_in[26];
    const float* f2b  = (const float*)d_in[27];
    float* outp = (float*)d_out;

    const int M  = in_sizes[0] / DM;          // 7200
    const int Mm = in_sizes[1] / DM;          // 80000
    const int B  = M / QLEN;                  // 8
    const int BHgrid = B * NH;                // 64

    float *t1, *val, *proj, *t2, *dproj, *dbias;
    __nv_bfloat16 *ah, *al, *wh, *wl, *ch, *cl, *fh, *fl;
    cudaGetSymbolAddress((void**)&t1,    g_t1);
    cudaGetSymbolAddress((void**)&val,   g_val);
    cudaGetSymbolAddress((void**)&proj,  g_proj);
    cudaGetSymbolAddress((void**)&t2,    g_t2);
    cudaGetSymbolAddress((void**)&dproj, g_dproj);
    cudaGetSymbolAddress((void**)&dbias, g_dbias);
    cudaGetSymbolAddress((void**)&ah,    g_ah);
    cudaGetSymbolAddress((void**)&al,    g_al);
    cudaGetSymbolAddress((void**)&wh,    g_wh);
    cudaGetSymbolAddress((void**)&wl,    g_wl);
    cudaGetSymbolAddress((void**)&ch,    g_ch);
    cudaGetSymbolAddress((void**)&cl,    g_cl);
    cudaGetSymbolAddress((void**)&fh,    g_fh);
    cudaGetSymbolAddress((void**)&fl,    g_fl);

    cudaFuncSetAttribute(hgemm, cudaFuncAttributeMaxDynamicSharedMemorySize, HG_SMEM);

    const int mb  = (M + 127) / 128;          // 57
    const int mmb = (Mm + 127) / 128;         // 625

    // weight offsets (elements) in concatenated buffer
    const int O_VPW = 0, O_INW = 65536, O_OUTW = 262144, O_COW = 327680,
              O_F1W = 393216, O_F2W = 655360;

    // ---- one-time prep ----
    split_weights<<<224, 256>>>(vpw, inw, outw, cow, f1w, f2w, wh, wl);
    build_dproj_w<<<128, 256>>>(rfw, rfb, ofw, ofb, aww, awb, ch, cl, dbias);

    // ---- memory value projection ----
    split_bf16<<<(Mm * 64 + 1023) / 1024, 256>>>(mem, ah, al, Mm * 64);
    hgemm<<<dim3(2, mmb), 256, HG_SMEM>>>(ah, al, wh + O_VPW, wl + O_VPW,
                                          vpb, val, 0, 0, Mm, 256, 256, 0);

    // ---- self-attention ----
    split_bf16<<<(M * 64 + 1023) / 1024, 256>>>(tgt, ah, al, M * 64);
    hgemm<<<dim3(6, mb), 256, HG_SMEM>>>(ah, al, wh + O_INW, wl + O_INW,
                                         inb, 0, fh, fl, M, 768, 256, 2);
    flash_mma<<<dim3(15, BHgrid), 128>>>(fh, fl, ah, al);
    hgemm<<<dim3(2, mb), 256, HG_SMEM>>>(ah, al, wh + O_OUTW, wl + O_OUTW,
                                         outb, proj, 0, 0, M, 256, 256, 0);
    add_ln<<<M, 256>>>(proj, tgt, n1s, n1b, t1, ah, al, 1);

    // ---- deformable cross-attention ----
    hgemm<<<dim3(1, mb), 256, HG_SMEM>>>(ah, al, ch, cl, dbias, dproj, 0, 0,
                                         M, 128, 256, 0);
    deform_attn<<<M, 256>>>(dproj, val, pH, pW, ah, al);
    hgemm<<<dim3(2, mb), 256, HG_SMEM>>>(ah, al, wh + O_COW, wl + O_COW,
                                         cob, proj, 0, 0, M, 256, 256, 0);
    add_ln<<<M, 256>>>(proj, t1, n2s, n2b, t2, ah, al, 1);

    // ---- FFN ----
    hgemm<<<dim3(8, mb), 256, HG_SMEM>>>(ah, al, wh + O_F1W, wl + O_F1W,
                                         f1b, 0, fh, fl, M, FFD, 256, 3);
    hgemm<<<dim3(2, mb), 256, HG_SMEM>>>(fh, fl, wh + O_F2W, wl + O_F2W,
                                         f2b, proj, 0, 0, M, 256, FFD, 0);
    add_ln<<<M, 256>>>(proj, t2, n3s, n3b, outp, 0, 0, 0);
}

// round 11
// speedup vs baseline: 3.0160x; 1.0038x over previous
#include <cuda_runtime.h>
#include <cuda_bf16.h>
#include <math.h>
#include <stdint.h>

#define QLEN 900
#define DM   256
#define NH   8
#define HD   32
#define NPTS 4
#define FFD  1024

// ---------------- scratch (__device__ globals; allocation-free) ----------------
__device__ float g_t1[1843200];
__device__ float g_val[20480000];     // [B*HW, 256]
__device__ float g_proj[1843200];
__device__ float g_t2[1843200];
__device__ float g_dproj[921600];     // [B*Q, 128] deform projections
__device__ float g_dbias[128];
// bf16 hi/lo split buffers
__device__ __nv_bfloat16 g_ah[20480000];
__device__ __nv_bfloat16 g_al[20480000];
__device__ __nv_bfloat16 g_wh[917504];   // all weights concatenated
__device__ __nv_bfloat16 g_wl[917504];
__device__ __nv_bfloat16 g_ch[32768];    // deform proj weights 128x256
__device__ __nv_bfloat16 g_cl[32768];
__device__ __nv_bfloat16 g_fh[7372800];  // qkv / ffn intermediate hi
__device__ __nv_bfloat16 g_fl[7372800];  // qkv / ffn intermediate lo

// ============================================================================
// helpers
// ============================================================================
__device__ __forceinline__ uint32_t smem_u32(const void* p) {
    uint32_t a;
    asm("{ .reg .u64 t; cvta.to.shared.u64 t, %1; cvt.u32.u64 %0, t; }"
        : "=r"(a) : "l"(p));
    return a;
}
__device__ __forceinline__ uint32_t sw128(uint32_t off) {
    return off ^ ((off >> 3) & 0x70);
}
__device__ __forceinline__ uint32_t sw64(uint32_t off) {
    return off ^ ((off >> 3) & 0x30);
}
__device__ __forceinline__ void cvt_split(float f, uint16_t& h, uint16_t& l) {
    __nv_bfloat16 hb = __float2bfloat16_rn(f);
    float r = f - __bfloat162float(hb);
    __nv_bfloat16 lb = __float2bfloat16_rn(r);
    h = *reinterpret_cast<uint16_t*>(&hb);
    l = *reinterpret_cast<uint16_t*>(&lb);
}
__device__ __forceinline__ void ldmx4(uint32_t* r, uint32_t addr) {
    asm volatile("ldmatrix.sync.aligned.m8n8.x4.shared.b16 {%0,%1,%2,%3}, [%4];"
        : "=r"(r[0]), "=r"(r[1]), "=r"(r[2]), "=r"(r[3]) : "r"(addr));
}
__device__ __forceinline__ void ldmx4t(uint32_t* r, uint32_t addr) {
    asm volatile("ldmatrix.sync.aligned.m8n8.x4.trans.shared.b16 {%0,%1,%2,%3}, [%4];"
        : "=r"(r[0]), "=r"(r[1]), "=r"(r[2]), "=r"(r[3]) : "r"(addr));
}
__device__ __forceinline__ void mma16816(float* d, const uint32_t* a,
                                         uint32_t b0, uint32_t b1) {
    asm volatile(
        "mma.sync.aligned.m16n8k16.row.col.f32.bf16.bf16.f32 "
        "{%0,%1,%2,%3}, {%4,%5,%6,%7}, {%8,%9}, {%0,%1,%2,%3};"
        : "+f"(d[0]), "+f"(d[1]), "+f"(d[2]), "+f"(d[3])
        : "r"(a[0]), "r"(a[1]), "r"(a[2]), "r"(a[3]), "r"(b0), "r"(b1));
}
__device__ __forceinline__ void cp_async16(uint32_t dst, const void* src, uint32_t sz) {
    asm volatile("cp.async.cg.shared.global [%0], [%1], 16, %2;"
        :: "r"(dst), "l"(src), "r"(sz));
}
#define CP_COMMIT() asm volatile("cp.async.commit_group;" ::: "memory")
#define CP_WAIT0()  asm volatile("cp.async.wait_group 0;" ::: "memory")
#define CP_WAIT1()  asm volatile("cp.async.wait_group 1;" ::: "memory")

// ============================================================================
// split_bf16: fp32 -> (hi, lo) bf16; 4 float4 per thread.
// ============================================================================
__global__ __launch_bounds__(256) void split_bf16(
    const float* __restrict__ x, __nv_bfloat16* __restrict__ hi,
    __nv_bfloat16* __restrict__ lo, int n4)
{
    int i0 = blockIdx.x * 1024 + threadIdx.x;
#pragma unroll
    for (int it = 0; it < 4; it++) {
        int i = i0 + it * 256;
        if (i >= n4) return;
        float4 v = ((const float4*)x)[i];
        uint16_t h0,h1,h2,h3,l0,l1,l2,l3;
        cvt_split(v.x,h0,l0); cvt_split(v.y,h1,l1);
        cvt_split(v.z,h2,l2); cvt_split(v.w,h3,l3);
        ((uint2*)hi)[i] = make_uint2((uint32_t)h0 | ((uint32_t)h1 << 16),
                                     (uint32_t)h2 | ((uint32_t)h3 << 16));
        ((uint2*)lo)[i] = make_uint2((uint32_t)l0 | ((uint32_t)l1 << 16),
                                     (uint32_t)l2 | ((uint32_t)l3 << 16));
    }
}

// ============================================================================
// split_weights: all 6 weight matrices -> one concatenated hi/lo buffer.
// ============================================================================
__global__ __launch_bounds__(256) void split_weights(
    const float* __restrict__ vpw, const float* __restrict__ inw,
    const float* __restrict__ outw, const float* __restrict__ cow,
    const float* __restrict__ f1w, const float* __restrict__ f2w,
    __nv_bfloat16* __restrict__ wh, __nv_bfloat16* __restrict__ wl)
{
    int i0 = blockIdx.x * 1024 + threadIdx.x;
#pragma unroll
    for (int it = 0; it < 4; it++) {
        int i = i0 + it * 256;
        if (i >= 229376) return;
        const float* src; int li;
        if (i < 16384)       { src = vpw;  li = i; }
        else if (i < 65536)  { src = inw;  li = i - 16384; }
        else if (i < 81920)  { src = outw; li = i - 65536; }
        else if (i < 98304)  { src = cow;  li = i - 81920; }
        else if (i < 163840) { src = f1w;  li = i - 98304; }
        else                 { src = f2w;  li = i - 163840; }
        float4 v = ((const float4*)src)[li];
        uint16_t h0,h1,h2,h3,l0,l1,l2,l3;
        cvt_split(v.x,h0,l0); cvt_split(v.y,h1,l1);
        cvt_split(v.z,h2,l2); cvt_split(v.w,h3,l3);
        ((uint2*)wh)[i] = make_uint2((uint32_t)h0 | ((uint32_t)h1 << 16),
                                     (uint32_t)h2 | ((uint32_t)h3 << 16));
        ((uint2*)wl)[i] = make_uint2((uint32_t)l0 | ((uint32_t)l1 << 16),
                                     (uint32_t)l2 | ((uint32_t)l3 << 16));
    }
}

// ============================================================================
// build_dproj_w: concat [ref(2) | offs(64) | attw(32) | pad(30)] x 256 weights
// ============================================================================
__global__ __launch_bounds__(256) void build_dproj_w(
    const float* __restrict__ rfw, const float* __restrict__ rfb,
    const float* __restrict__ ofw, const float* __restrict__ ofb,
    const float* __restrict__ aww, const float* __restrict__ awb,
    __nv_bfloat16* __restrict__ ch, __nv_bfloat16* __restrict__ cl,
    float* __restrict__ dbias)
{
    int row = blockIdx.x, tid = threadIdx.x;
    float v = 0.f;
    if (row < 2)       v = rfw[row * 256 + tid];
    else if (row < 66) v = ofw[(row - 2) * 256 + tid];
    else if (row < 98) v = aww[(row - 66) * 256 + tid];
    uint16_t hh, ll;
    cvt_split(v, hh, ll);
    *(uint16_t*)(ch + row * 256 + tid) = hh;
    *(uint16_t*)(cl + row * 256 + tid) = ll;
    if (tid == 0)
        dbias[row] = row < 2 ? rfb[row] : row < 66 ? ofb[row - 2]
                   : row < 98 ? awb[row - 66] : 0.f;
}

// ============================================================================
// hgemm: C = act(A @ W^T + bias), bf16x3, cp.async 2-stage pipeline.
// Term-major MMA scheduling (hh, hl, lh passes) for HMMA dependency hiding.
// ============================================================================
#define HG_SMEM (2 * 65536)

__global__ __launch_bounds__(256) void hgemm(
    const __nv_bfloat16* __restrict__ Ah, const __nv_bfloat16* __restrict__ Al,
    const __nv_bfloat16* __restrict__ Wh, const __nv_bfloat16* __restrict__ Wl,
    const float* __restrict__ bias, float* __restrict__ C,
    __nv_bfloat16* __restrict__ Ch, __nv_bfloat16* __restrict__ Cl,
    int M, int N, int K, int mode)
{
    extern __shared__ char sm[];
    const uint32_t sb = smem_u32(sm);
    const int tid = threadIdx.x;
    const int wid = tid >> 5, lane = tid & 31;
    const int row0 = blockIdx.y * 128, col0 = blockIdx.x * 128;
    const int wm = (wid & 1) * 64;
    const int wn = (wid >> 1) * 32;

    float acc[4][4][4];
#pragma unroll
    for (int mt = 0; mt < 4; mt++)
#pragma unroll
        for (int nt = 0; nt < 4; nt++)
#pragma unroll
            for (int j = 0; j < 4; j++) acc[mt][nt][j] = 0.f;

    const uint32_t a_row = wm + (lane & 15);
    const uint32_t a_cb  = (lane >> 4) * 16;
    const uint32_t b_row = wn + (lane & 7) + ((lane >> 4) << 3);
    const uint32_t b_cb  = ((lane >> 3) & 1) * 16;
    const int nc = K >> 6;

    const int lr  = tid >> 3;
    const int lc8 = (tid & 7) * 8;

    {
#pragma unroll
        for (int it = 0; it < 4; it++) {
            int r = lr + it * 32;
            uint32_t so = sw128((uint32_t)(r * 128 + lc8 * 2));
            int ra = row0 + r < M ? row0 + r : M - 1;
            uint32_t asz = (row0 + r < M) ? 16u : 0u;
            cp_async16(sb + so,         Ah + (size_t)ra * K + lc8, asz);
            cp_async16(sb + 16384 + so, Al + (size_t)ra * K + lc8, asz);
            cp_async16(sb + 32768 + so, Wh + (size_t)(col0 + r) * K + lc8, 16u);
            cp_async16(sb + 49152 + so, Wl + (size_t)(col0 + r) * K + lc8, 16u);
        }
        CP_COMMIT();
    }

    for (int c = 0; c < nc; c++) {
        const uint32_t stb = sb + (uint32_t)(c & 1) * 65536;
        if (c + 1 < nc) {
            const uint32_t nstb = sb + (uint32_t)((c + 1) & 1) * 65536;
            const int k0 = (c + 1) << 6;
#pragma unroll
            for (int it = 0; it < 4; it++) {
                int r = lr + it * 32;
                uint32_t so = sw128((uint32_t)(r * 128 + lc8 * 2));
                int ra = row0 + r < M ? row0 + r : M - 1;
                uint32_t asz = (row0 + r < M) ? 16u : 0u;
                cp_async16(nstb + so,         Ah + (size_t)ra * K + k0 + lc8, asz);
                cp_async16(nstb + 16384 + so, Al + (size_t)ra * K + k0 + lc8, asz);
                cp_async16(nstb + 32768 + so, Wh + (size_t)(col0 + r) * K + k0 + lc8, 16u);
                cp_async16(nstb + 49152 + so, Wl + (size_t)(col0 + r) * K + k0 + lc8, 16u);
            }
            CP_COMMIT();
            CP_WAIT1();
        } else {
            CP_WAIT0();
        }
        __syncthreads();

#pragma unroll
        for (int ks = 0; ks < 64; ks += 16) {
            uint32_t ah[4][4], alr[4][4], bh[2][4], bl[2][4];
#pragma unroll
            for (int mt = 0; mt < 4; mt++) {
                uint32_t off = sw128((a_row + mt * 16) * 128 + ks * 2 + a_cb);
                ldmx4(ah[mt],  stb + off);
                ldmx4(alr[mt], stb + 16384 + off);
            }
#pragma unroll
            for (int bt = 0; bt < 2; bt++) {
                uint32_t off = sw128((b_row + bt * 16) * 128 + ks * 2 + b_cb);
                ldmx4(bh[bt], stb + 32768 + off);
                ldmx4(bl[bt], stb + 49152 + off);
            }
            // term-major passes: per-accumulator order hh -> hl -> lh
            // (identical numerics, 16-MMA dependency distance)
#pragma unroll
            for (int mt = 0; mt < 4; mt++)
#pragma unroll
                for (int nt = 0; nt < 4; nt++) {
                    int bt = nt >> 1, bi = (nt & 1) * 2;
                    mma16816(acc[mt][nt], ah[mt], bh[bt][bi], bh[bt][bi+1]);
                }
#pragma unroll
            for (int mt = 0; mt < 4; mt++)
#pragma unroll
                for (int nt = 0; nt < 4; nt++) {
                    int bt = nt >> 1, bi = (nt & 1) * 2;
                    mma16816(acc[mt][nt], ah[mt], bl[bt][bi], bl[bt][bi+1]);
                }
#pragma unroll
            for (int mt = 0; mt < 4; mt++)
#pragma unroll
                for (int nt = 0; nt < 4; nt++) {
                    int bt = nt >> 1, bi = (nt & 1) * 2;
                    mma16816(acc[mt][nt], alr[mt], bh[bt][bi], bh[bt][bi+1]);
                }
        }
        __syncthreads();
    }

    const bool relu = mode & 1;
    const bool split = mode & 2;
#pragma unroll
    for (int mt = 0; mt < 4; mt++) {
        int r0e = row0 + wm + mt * 16 + (lane >> 2);
#pragma unroll
        for (int nt = 0; nt < 4; nt++) {
            int c = col0 + wn + nt * 8 + (lane & 3) * 2;
            float b0 = bias[c], b1 = bias[c + 1];
            float2 v0 = make_float2(acc[mt][nt][0] + b0, acc[mt][nt][1] + b1);
            float2 v1 = make_float2(acc[mt][nt][2] + b0, acc[mt][nt][3] + b1);
            if (relu) {
                v0.x = fmaxf(v0.x, 0.f); v0.y = fmaxf(v0.y, 0.f);
                v1.x = fmaxf(v1.x, 0.f); v1.y = fmaxf(v1.y, 0.f);
            }
            if (!split) {
                if (r0e < M)     *(float2*)(C + (size_t)r0e * N + c) = v0;
                if (r0e + 8 < M) *(float2*)(C + (size_t)(r0e + 8) * N + c) = v1;
            } else {
                uint16_t h0,h1,l0,l1;
                if (r0e < M) {
                    cvt_split(v0.x, h0, l0); cvt_split(v0.y, h1, l1);
                    *(uint32_t*)(Ch + (size_t)r0e * N + c) =
                        (uint32_t)h0 | ((uint32_t)h1 << 16);
                    *(uint32_t*)(Cl + (size_t)r0e * N + c) =
                        (uint32_t)l0 | ((uint32_t)l1 << 16);
                }
                if (r0e + 8 < M) {
                    cvt_split(v1.x, h0, l0); cvt_split(v1.y, h1, l1);
                    *(uint32_t*)(Ch + (size_t)(r0e + 8) * N + c) =
                        (uint32_t)h0 | ((uint32_t)h1 << 16);
                    *(uint32_t*)(Cl + (size_t)(r0e + 8) * N + c) =
                        (uint32_t)l0 | ((uint32_t)l1 << 16);
                }
            }
        }
    }
}

// ============================================================================
// flash_mma: fused flash self-attention, bf16x3, split-bf16 QKV inputs.
// Term-major MMA scheduling in both S and PV loops.
// ============================================================================
__global__ __launch_bounds__(128) void flash_mma(
    const __nv_bfloat16* __restrict__ QKVh, const __nv_bfloat16* __restrict__ QKVl,
    __nv_bfloat16* __restrict__ Oh, __nv_bfloat16* __restrict__ Ol)
{
    __shared__ __align__(16) char sQ[2][4096];       // [hi/lo] 64 rows x 64B
    __shared__ __align__(16) char sKV[2][4][4096];   // [stage][Kh,Kl,Vh,Vl]

    const int bh = blockIdx.y;
    const int b = bh >> 3, h = bh & 7;
    const int q0 = blockIdx.x * 64;
    const int tid = threadIdx.x;
    const int w = tid >> 5, lane = tid & 31;
    const float scale = 0.17677669529663687f;

    const size_t rowbase = (size_t)b * QLEN * 768 + h * 32;
    const __nv_bfloat16* gqh = QKVh + rowbase;
    const __nv_bfloat16* gql = QKVl + rowbase;

    const uint32_t uQ0 = smem_u32(sQ[0]), uQ1 = smem_u32(sQ[1]);
    const uint32_t uKV = smem_u32(sKV[0][0]);

    const int lrow = tid >> 1;
    const int lel  = (tid & 1) * 16;
    const uint32_t so0 = sw64((uint32_t)(lrow * 64 + lel * 2));
    const uint32_t so1 = sw64((uint32_t)(lrow * 64 + lel * 2 + 16));

    {
        uint32_t qsz = (q0 + lrow < QLEN) ? 16u : 0u;
        const __nv_bfloat16* sh = gqh + (size_t)(q0 + lrow) * 768 + lel;
        const __nv_bfloat16* sl = gql + (size_t)(q0 + lrow) * 768 + lel;
        cp_async16(uQ0 + so0, sh, qsz);     cp_async16(uQ0 + so1, sh + 8, qsz);
        cp_async16(uQ1 + so0, sl, qsz);     cp_async16(uQ1 + so1, sl + 8, qsz);
        uint32_t ksz = (lrow < QLEN) ? 16u : 0u;
        const __nv_bfloat16* kh = gqh + 256 + (size_t)lrow * 768 + lel;
        const __nv_bfloat16* kl = gql + 256 + (size_t)lrow * 768 + lel;
        const __nv_bfloat16* vh = gqh + 512 + (size_t)lrow * 768 + lel;
        const __nv_bfloat16* vl = gql + 512 + (size_t)lrow * 768 + lel;
        cp_async16(uKV + so0, kh, ksz);             cp_async16(uKV + so1, kh + 8, ksz);
        cp_async16(uKV + 4096 + so0, kl, ksz);      cp_async16(uKV + 4096 + so1, kl + 8, ksz);
        cp_async16(uKV + 8192 + so0, vh, ksz);      cp_async16(uKV + 8192 + so1, vh + 8, ksz);
        cp_async16(uKV + 12288 + so0, vl, ksz);     cp_async16(uKV + 12288 + so1, vl + 8, ksz);
        CP_COMMIT();
    }
    CP_WAIT0();
    __syncthreads();

    uint32_t qa[2][2][4];
#pragma unroll
    for (int ks = 0; ks < 2; ks++) {
        uint32_t off = sw64((uint32_t)((w*16 + (lane & 15)) * 64
                            + ks * 32 + (lane >> 4) * 16));
        ldmx4(qa[0][ks], uQ0 + off);
        ldmx4(qa[1][ks], uQ1 + off);
    }

    float m0 = -1e30f, m1 = -1e30f, l0s = 0.f, l1s = 0.f;
    float o[4][4];
#pragma unroll
    for (int i = 0; i < 4; i++)
#pragma unroll
        for (int j = 0; j < 4; j++) o[i][j] = 0.f;

    for (int kt = 0; kt < 15; kt++) {
        if (kt < 14) {
            const int k0n = (kt + 1) * 64;
            const uint32_t nb = uKV + (uint32_t)((kt + 1) & 1) * 16384;
            uint32_t ksz = (k0n + lrow < QLEN) ? 16u : 0u;
            const __nv_bfloat16* kh = gqh + 256 + (size_t)(k0n + lrow) * 768 + lel;
            const __nv_bfloat16* kl = gql + 256 + (size_t)(k0n + lrow) * 768 + lel;
            const __nv_bfloat16* vh = gqh + 512 + (size_t)(k0n + lrow) * 768 + lel;
            const __nv_bfloat16* vl = gql + 512 + (size_t)(k0n + lrow) * 768 + lel;
            cp_async16(nb + so0, kh, ksz);            cp_async16(nb + so1, kh + 8, ksz);
            cp_async16(nb + 4096 + so0, kl, ksz);     cp_async16(nb + 4096 + so1, kl + 8, ksz);
            cp_async16(nb + 8192 + so0, vh, ksz);     cp_async16(nb + 8192 + so1, vh + 8, ksz);
            cp_async16(nb + 12288 + so0, vl, ksz);    cp_async16(nb + 12288 + so1, vl + 8, ksz);
            CP_COMMIT();
        }

        const uint32_t stb = uKV + (uint32_t)(kt & 1) * 16384;
        const int k0 = kt * 64;

        // ---- S = Q K^T, bf16x3, term-major ----
        float s[8][4];
#pragma unroll
        for (int i = 0; i < 8; i++)
#pragma unroll
            for (int j = 0; j < 4; j++) s[i][j] = 0.f;
#pragma unroll
        for (int ks = 0; ks < 2; ks++) {
            uint32_t bhh[4][4], bll[4][4];
#pragma unroll
            for (int jj = 0; jj < 4; jj++) {
                uint32_t off = sw64((uint32_t)((jj*16 + (lane & 7)
                               + ((lane >> 4) << 3)) * 64
                               + ((lane >> 3) & 1) * 16 + ks * 32));
                ldmx4(bhh[jj], stb + off);
                ldmx4(bll[jj], stb + 4096 + off);
            }
#pragma unroll
            for (int jj = 0; jj < 4; jj++) {
                mma16816(s[2*jj],   qa[0][ks], bhh[jj][0], bhh[jj][1]);
                mma16816(s[2*jj+1], qa[0][ks], bhh[jj][2], bhh[jj][3]);
            }
#pragma unroll
            for (int jj = 0; jj < 4; jj++) {
                mma16816(s[2*jj],   qa[0][ks], bll[jj][0], bll[jj][1]);
                mma16816(s[2*jj+1], qa[0][ks], bll[jj][2], bll[jj][3]);
            }
#pragma unroll
            for (int jj = 0; jj < 4; jj++) {
                mma16816(s[2*jj],   qa[1][ks], bhh[jj][0], bhh[jj][1]);
                mma16816(s[2*jj+1], qa[1][ks], bhh[jj][2], bhh[jj][3]);
            }
        }
        // scale + mask
#pragma unroll
        for (int jn = 0; jn < 8; jn++) {
#pragma unroll
            for (int j = 0; j < 4; j++) s[jn][j] *= scale;
        }
        const int colb = k0 + (lane & 3) * 2;
#pragma unroll
        for (int jn = 0; jn < 8; jn++) {
            int c0 = colb + jn * 8;
            if (c0 >= QLEN)     { s[jn][0] = -1e30f; s[jn][2] = -1e30f; }
            if (c0 + 1 >= QLEN) { s[jn][1] = -1e30f; s[jn][3] = -1e30f; }
        }

        // ---- online softmax ----
        float mx0 = -1e30f, mx1 = -1e30f;
#pragma unroll
        for (int jn = 0; jn < 8; jn++) {
            mx0 = fmaxf(mx0, fmaxf(s[jn][0], s[jn][1]));
            mx1 = fmaxf(mx1, fmaxf(s[jn][2], s[jn][3]));
        }
        mx0 = fmaxf(mx0, __shfl_xor_sync(0xffffffffu, mx0, 1));
        mx0 = fmaxf(mx0, __shfl_xor_sync(0xffffffffu, mx0, 2));
        mx1 = fmaxf(mx1, __shfl_xor_sync(0xffffffffu, mx1, 1));
        mx1 = fmaxf(mx1, __shfl_xor_sync(0xffffffffu, mx1, 2));
        float mn0 = fmaxf(m0, mx0), mn1 = fmaxf(m1, mx1);
        float corr0 = __expf(m0 - mn0), corr1 = __expf(m1 - mn1);
        m0 = mn0; m1 = mn1;
        float rs0 = 0.f, rs1 = 0.f;
#pragma unroll
        for (int jn = 0; jn < 8; jn++) {
            s[jn][0] = __expf(s[jn][0] - mn0);
            s[jn][1] = __expf(s[jn][1] - mn0);
            s[jn][2] = __expf(s[jn][2] - mn1);
            s[jn][3] = __expf(s[jn][3] - mn1);
            rs0 += s[jn][0] + s[jn][1];
            rs1 += s[jn][2] + s[jn][3];
        }
        rs0 += __shfl_xor_sync(0xffffffffu, rs0, 1);
        rs0 += __shfl_xor_sync(0xffffffffu, rs0, 2);
        rs1 += __shfl_xor_sync(0xffffffffu, rs1, 1);
        rs1 += __shfl_xor_sync(0xffffffffu, rs1, 2);
        l0s = l0s * corr0 + rs0;
        l1s = l1s * corr1 + rs1;
#pragma unroll
        for (int jn = 0; jn < 4; jn++) {
            o[jn][0] *= corr0; o[jn][1] *= corr0;
            o[jn][2] *= corr1; o[jn][3] *= corr1;
        }

        // ---- O += P @ V : term-major per k-step ----
#pragma unroll
        for (int ks = 0; ks < 4; ks++) {
            uint32_t pah[4], pal[4];
            {
                const float* t0 = s[2*ks];
                const float* t1 = s[2*ks+1];
                uint16_t h0,h1,l0,l1;
                cvt_split(t0[0],h0,l0); cvt_split(t0[1],h1,l1);
                pah[0] = (uint32_t)h0 | ((uint32_t)h1<<16);
                pal[0] = (uint32_t)l0 | ((uint32_t)l1<<16);
                cvt_split(t0[2],h0,l0); cvt_split(t0[3],h1,l1);
                pah[1] = (uint32_t)h0 | ((uint32_t)h1<<16);
                pal[1] = (uint32_t)l0 | ((uint32_t)l1<<16);
                cvt_split(t1[0],h0,l0); cvt_split(t1[1],h1,l1);
                pah[2] = (uint32_t)h0 | ((uint32_t)h1<<16);
                pal[2] = (uint32_t)l0 | ((uint32_t)l1<<16);
                cvt_split(t1[2],h0,l0); cvt_split(t1[3],h1,l1);
                pah[3] = (uint32_t)h0 | ((uint32_t)h1<<16);
                pal[3] = (uint32_t)l0 | ((uint32_t)l1<<16);
            }
            uint32_t vrow = (uint32_t)(ks * 16 + (lane & 7) + ((lane >> 3) & 1) * 8);
            uint32_t vhh[2][4], vll[2][4];
#pragma unroll
            for (int jj = 0; jj < 2; jj++) {
                uint32_t off = sw64(vrow * 64 + jj * 32 + (lane >> 4) * 16);
                ldmx4t(vhh[jj], stb + 8192 + off);
                ldmx4t(vll[jj], stb + 12288 + off);
            }
#pragma unroll
            for (int jj = 0; jj < 2; jj++) {
                mma16816(o[2*jj],   pah, vhh[jj][0], vhh[jj][1]);
                mma16816(o[2*jj+1], pah, vhh[jj][2], vhh[jj][3]);
            }
#pragma unroll
            for (int jj = 0; jj < 2; jj++) {
                mma16816(o[2*jj],   pah, vll[jj][0], vll[jj][1]);
                mma16816(o[2*jj+1], pah, vll[jj][2], vll[jj][3]);
            }
#pragma unroll
            for (int jj = 0; jj < 2; jj++) {
                mma16816(o[2*jj],   pal, vhh[jj][0], vhh[jj][1]);
                mma16816(o[2*jj+1], pal, vhh[jj][2], vhh[jj][3]);
            }
        }

        if (kt < 14) CP_WAIT0();
        __syncthreads();
    }

    // ---- finalize ----
    {
        int r0 = q0 + w * 16 + (lane >> 2);
        float i0 = 1.f / l0s, i1 = 1.f / l1s;
#pragma unroll
        for (int jn = 0; jn < 4; jn++) {
            int c = h * 32 + jn * 8 + (lane & 3) * 2;
            uint16_t h0,h1,l0,l1;
            if (r0 < QLEN) {
                cvt_split(o[jn][0] * i0, h0, l0);
                cvt_split(o[jn][1] * i0, h1, l1);
                size_t off = (size_t)(b * QLEN + r0) * 256 + c;
                *(uint32_t*)(Oh + off) = (uint32_t)h0 | ((uint32_t)h1 << 16);
                *(uint32_t*)(Ol + off) = (uint32_t)l0 | ((uint32_t)l1 << 16);
            }
            if (r0 + 8 < QLEN) {
                cvt_split(o[jn][2] * i1, h0, l0);
                cvt_split(o[jn][3] * i1, h1, l1);
                size_t off = (size_t)(b * QLEN + r0 + 8) * 256 + c;
                *(uint32_t*)(Oh + off) = (uint32_t)h0 | ((uint32_t)h1 << 16);
                *(uint32_t*)(Ol + off) = (uint32_t)l0 | ((uint32_t)l1 << 16);
            }
        }
    }
}

// ---------------------------------------------------------------------------
// out = LayerNorm(a + b); optionally also emits bf16 hi/lo split of out.
// ---------------------------------------------------------------------------
__global__ __launch_bounds__(256) void add_ln(
    const float* __restrict__ a, const float* __restrict__ b,
    const float* __restrict__ gam, const float* __restrict__ bet,
    float* __restrict__ out,
    __nv_bfloat16* __restrict__ oh, __nv_bfloat16* __restrict__ ol,
    int do_split)
{
    __shared__ float red[8];
    __shared__ float s_mu, s_rstd;
    const int tid = threadIdx.x;
    const int lane = tid & 31, w = tid >> 5;
    size_t idx = (size_t)blockIdx.x * 256 + tid;
    float v = a[idx] + b[idx];

    float s = v;
#pragma unroll
    for (int o = 16; o; o >>= 1) s += __shfl_xor_sync(0xffffffffu, s, o);
    if (lane == 0) red[w] = s;
    __syncthreads();
    if (tid == 0) {
        float t = 0.f;
        for (int i = 0; i < 8; i++) t += red[i];
        s_mu = t * (1.f / 256.f);
    }
    __syncthreads();
    float d = v - s_mu;
    float sq = d * d;
    __syncthreads();
#pragma unroll
    for (int o = 16; o; o >>= 1) sq += __shfl_xor_sync(0xffffffffu, sq, o);
    if (lane == 0) red[w] = sq;
    __syncthreads();
    if (tid == 0) {
        float t = 0.f;
        for (int i = 0; i < 8; i++) t += red[i];
        s_rstd = rsqrtf(t * (1.f / 256.f) + 1e-5f);
    }
    __syncthreads();
    float r = d * s_rstd * gam[tid] + bet[tid];
    out[idx] = r;
    if (do_split) {
        uint16_t hh, ll;
        cvt_split(r, hh, ll);
        *(uint16_t*)(oh + idx) = hh;
        *(uint16_t*)(ol + idx) = ll;
    }
}

// ---------------------------------------------------------------------------
// deform_attn: projections precomputed by GEMM; sigmoid/softmax + gather.
// ---------------------------------------------------------------------------
__global__ __launch_bounds__(256) void deform_attn(
    const float* __restrict__ dproj, const float* __restrict__ val,
    const int* __restrict__ pH, const int* __restrict__ pW,
    __nv_bfloat16* __restrict__ oh, __nv_bfloat16* __restrict__ ol)
{
    __shared__ float sref[2];
    __shared__ float soffs[64];
    __shared__ float sattw[32];
    const int bq = blockIdx.x;
    const int b = bq / QLEN;
    const int tid = threadIdx.x;

    if (tid < 98) {
        float v = dproj[(size_t)bq * 128 + tid];
        if (tid < 2)       sref[tid] = 1.f / (1.f + __expf(-v));
        else if (tid < 66) soffs[tid - 2] = v;
        else               sattw[tid - 66] = v;
    }
    __syncthreads();

    if (tid < 8) {
        float m = -3.4e38f;
#pragma unroll
        for (int p = 0; p < 4; p++) m = fmaxf(m, sattw[tid * 4 + p]);
        float e[4], s = 0.f;
#pragma unroll
        for (int p = 0; p < 4; p++) { e[p] = __expf(sattw[tid * 4 + p] - m); s += e[p]; }
        float inv = 1.f / s;
#pragma unroll
        for (int p = 0; p < 4; p++) sattw[tid * 4 + p] = e[p] * inv;
    }
    __syncthreads();

    const int H = *pH, W = *pW;
    const float fH = (float)H, fW = (float)W;
    const int h = tid >> 5, d = tid & 31;
    const float refx = sref[0], refy = sref[1];
    const float* vbase = val + (size_t)b * H * W * 256 + h * 32 + d;
    float acc = 0.f;
#pragma unroll
    for (int p = 0; p < NPTS; p++) {
        float locx = refx + soffs[h * 8 + 2 * p]     / fW;
        float locy = refy + soffs[h * 8 + 2 * p + 1] / fH;
        float xx = locx * fW - 0.5f;
        float yy = locy * fH - 0.5f;
        float x0f = floorf(xx), y0f = floorf(yy);
        int x0 = (int)x0f, y0 = (int)y0f;
        float lx = xx - x0f, ly = yy - y0f;
        float w00 = (1.f - lx) * (1.f - ly);
        float w10 = lx * (1.f - ly);
        float w01 = (1.f - lx) * ly;
        float w11 = lx * ly;
        float s = 0.f;
        bool vx0 = (x0 >= 0) & (x0 < W);
        bool vx1 = (x0 + 1 >= 0) & (x0 + 1 < W);
        bool vy0 = (y0 >= 0) & (y0 < H);
        bool vy1 = (y0 + 1 >= 0) & (y0 + 1 < H);
        if (vx0 & vy0) s += w00 * vbase[((size_t)y0 * W + x0) * 256];
        if (vx1 & vy0) s += w10 * vbase[((size_t)y0 * W + x0 + 1) * 256];
        if (vx0 & vy1) s += w01 * vbase[((size_t)(y0 + 1) * W + x0) * 256];
        if (vx1 & vy1) s += w11 * vbase[((size_t)(y0 + 1) * W + x0 + 1) * 256];
        acc += sattw[h * 4 + p] * s;
    }
    uint16_t hh, ll;
    cvt_split(acc, hh, ll);
    *(uint16_t*)(oh + (size_t)bq * 256 + tid) = hh;
    *(uint16_t*)(ol + (size_t)bq * 256 + tid) = ll;
}

// ---------------------------------------------------------------------------
extern "C" void kernel_launch(void* const* d_in, const int* in_sizes, int n_in,
                              void* d_out, int out_size)
{
    const float* tgt  = (const float*)d_in[0];
    const float* mem  = (const float*)d_in[1];
    const int*   pH   = (const int*)d_in[2];
    const int*   pW   = (const int*)d_in[3];
    const float* inw  = (const float*)d_in[4];
    const float* inb  = (const float*)d_in[5];
    const float* outw = (const float*)d_in[6];
    const float* outb = (const float*)d_in[7];
    const float* n1s  = (const float*)d_in[8];
    const float* n1b  = (const float*)d_in[9];
    const float* n2s  = (const float*)d_in[10];
    const float* n2b  = (const float*)d_in[11];
    const float* n3s  = (const float*)d_in[12];
    const float* n3b  = (const float*)d_in[13];
    const float* vpw  = (const float*)d_in[14];
    const float* vpb  = (const float*)d_in[15];
    const float* ofw  = (const float*)d_in[16];
    const float* ofb  = (const float*)d_in[17];
    const float* aww  = (const float*)d_in[18];
    const float* awb  = (const float*)d_in[19];
    const float* rfw  = (const float*)d_in[20];
    const float* rfb  = (const float*)d_in[21];
    const float* cow  = (const float*)d_in[22];
    const float* cob  = (const float*)d_in[23];
    const float* f1w  = (const float*)d_in[24];
    const float* f1b  = (const float*)d_in[25];
    const float* f2w  = (const float*)d_in[26];
    const float* f2b  = (const float*)d_in[27];
    float* outp = (float*)d_out;

    const int M  = in_sizes[0] / DM;          // 7200
    const int Mm = in_sizes[1] / DM;          // 80000
    const int B  = M / QLEN;                  // 8
    const int BHgrid = B * NH;                // 64

    float *t1, *val, *proj, *t2, *dproj, *dbias;
    __nv_bfloat16 *ah, *al, *wh, *wl, *ch, *cl, *fh, *fl;
    cudaGetSymbolAddress((void**)&t1,    g_t1);
    cudaGetSymbolAddress((void**)&val,   g_val);
    cudaGetSymbolAddress((void**)&proj,  g_proj);
    cudaGetSymbolAddress((void**)&t2,    g_t2);
    cudaGetSymbolAddress((void**)&dproj, g_dproj);
    cudaGetSymbolAddress((void**)&dbias, g_dbias);
    cudaGetSymbolAddress((void**)&ah,    g_ah);
    cudaGetSymbolAddress((void**)&al,    g_al);
    cudaGetSymbolAddress((void**)&wh,    g_wh);
    cudaGetSymbolAddress((void**)&wl,    g_wl);
    cudaGetSymbolAddress((void**)&ch,    g_ch);
    cudaGetSymbolAddress((void**)&cl,    g_cl);
    cudaGetSymbolAddress((void**)&fh,    g_fh);
    cudaGetSymbolAddress((void**)&fl,    g_fl);

    cudaFuncSetAttribute(hgemm, cudaFuncAttributeMaxDynamicSharedMemorySize, HG_SMEM);

    const int mb  = (M + 127) / 128;          // 57
    const int mmb = (Mm + 127) / 128;         // 625

    const int O_VPW = 0, O_INW = 65536, O_OUTW = 262144, O_COW = 327680,
              O_F1W = 393216, O_F2W = 655360;

    // ---- one-time prep ----
    split_weights<<<224, 256>>>(vpw, inw, outw, cow, f1w, f2w, wh, wl);
    build_dproj_w<<<128, 256>>>(rfw, rfb, ofw, ofb, aww, awb, ch, cl, dbias);

    // ---- memory value projection ----
    split_bf16<<<(Mm * 64 + 1023) / 1024, 256>>>(mem, ah, al, Mm * 64);
    hgemm<<<dim3(2, mmb), 256, HG_SMEM>>>(ah, al, wh + O_VPW, wl + O_VPW,
                                          vpb, val, 0, 0, Mm, 256, 256, 0);

    // ---- self-attention ----
    split_bf16<<<(M * 64 + 1023) / 1024, 256>>>(tgt, ah, al, M * 64);
    hgemm<<<dim3(6, mb), 256, HG_SMEM>>>(ah, al, wh + O_INW, wl + O_INW,
                                         inb, 0, fh, fl, M, 768, 256, 2);
    flash_mma<<<dim3(15, BHgrid), 128>>>(fh, fl, ah, al);
    hgemm<<<dim3(2, mb), 256, HG_SMEM>>>(ah, al, wh + O_OUTW, wl + O_OUTW,
                                         outb, proj, 0, 0, M, 256, 256, 0);
    add_ln<<<M, 256>>>(proj, tgt, n1s, n1b, t1, ah, al, 1);

    // ---- deformable cross-attention ----
    hgemm<<<dim3(1, mb), 256, HG_SMEM>>>(ah, al, ch, cl, dbias, dproj, 0, 0,
                                         M, 128, 256, 0);
    deform_attn<<<M, 256>>>(dproj, val, pH, pW, ah, al);
    hgemm<<<dim3(2, mb), 256, HG_SMEM>>>(ah, al, wh + O_COW, wl + O_COW,
                                         cob, proj, 0, 0, M, 256, 256, 0);
    add_ln<<<M, 256>>>(proj, t1, n2s, n2b, t2, ah, al, 1);

    // ---- FFN ----
    hgemm<<<dim3(8, mb), 256, HG_SMEM>>>(ah, al, wh + O_F1W, wl + O_F1W,
                                         f1b, 0, fh, fl, M, FFD, 256, 3);
    hgemm<<<dim3(2, mb), 256, HG_SMEM>>>(fh, fl, wh + O_F2W, wl + O_F2W,
                                         f2b, proj, 0, 0, M, 256, FFD, 0);
    add_ln<<<M, 256>>>(proj, t2, n3s, n3b, outp, 0, 0, 0);
}